// round 12
// baseline (speedup 1.0000x reference)
#include <cuda_runtime.h>
#include <cuda_bf16.h>
#include <cuda_pipeline.h>
#include <math.h>
#include <stdint.h>

#define BSZ 64
#define NPIX 196
#define ENCD 512
#define DD 512
#define VV 32000
#define TT 50
#define ML 51
#define NSPLIT 8
#define RBLK 64                  // recurrence blocks (barrier group)
#define PBLK 125                 // preds blocks (VV/256)
#define GRID (RBLK + PBLK)       // 189 <= 296 co-resident

// ---------------- scratch (static device globals; no runtime alloc) ----------
__device__ float d_enc_s[BSZ*NPIX*ENCD];
__device__ float d_ea[BSZ*NPIX*ENCD];
__device__ float d_mean[BSZ*ENCD];
__device__ float d_hbuf[2][BSZ*DD];
__device__ uint32_t d_hph[2][BSZ*DD/2];      // h bf16-hi pairs
__device__ uint32_t d_hpl[2][BSZ*DD/2];      // h bf16-lo pairs
__device__ float d_c[BSZ*DD];
__device__ uint32_t d_ctxp_h[BSZ*DD/2];      // ctx bf16 packed
__device__ uint32_t d_ctxp_l[BSZ*DD/2];
__device__ float d_da[BSZ*DD];
__device__ float d_gate[BSZ*ENCD];
__device__ float d_gates_p[NSPLIT*BSZ*4*DD];
__device__ uint32_t d_wfh16[(size_t)VV*256];   // W_fc bf16 hi
__device__ uint32_t d_wfl16[(size_t)VV*256];   // W_fc bf16 lo
__device__ uint32_t d_wihh_h[2048*768];        // [Wih|Whh] bf16 hi (k-pairs)
__device__ uint32_t d_wihh_l[2048*768];
__device__ uint32_t d_wdg_h[1024*256];         // [Wd;Wg] bf16 hi
__device__ uint32_t d_wdg_l[1024*256];
__device__ uint32_t d_embp_h[(size_t)ML*BSZ*256];  // sorted emb rows packed
__device__ uint32_t d_embp_l[(size_t)ML*BSZ*256];
__device__ unsigned int d_bar;                 // monotonic rec barrier
__device__ unsigned int d_hready;              // steps with h published
__device__ unsigned int d_pdone;               // preds blocks*steps done
__device__ int   d_order[BSZ];
__device__ int   d_declen[BSZ];
__device__ int   d_caps_s[BSZ*ML];
__device__ int   d_nact[TT];

// ---------------- helpers ----------------------------------------------------
__device__ __forceinline__ float warp_sum(float v) {
    #pragma unroll
    for (int o = 16; o > 0; o >>= 1) v += __shfl_down_sync(0xffffffffu, v, o);
    return v;
}
__device__ __forceinline__ float warp_max(float v) {
    #pragma unroll
    for (int o = 16; o > 0; o >>= 1) v = fmaxf(v, __shfl_down_sync(0xffffffffu, v, o));
    return v;
}
__device__ __forceinline__ float sigmoidf_(float x) { return 1.0f / (1.0f + __expf(-x)); }

__device__ __forceinline__ void bfsplit2(float a, float b, uint32_t& hi, uint32_t& lo) {
    __nv_bfloat162 h2 = __floats2bfloat162_rn(a, b);
    float ra = a - __bfloat162float(h2.x);
    float rb = b - __bfloat162float(h2.y);
    __nv_bfloat162 l2 = __floats2bfloat162_rn(ra, rb);
    hi = *(uint32_t*)&h2;
    lo = *(uint32_t*)&l2;
}

__device__ __forceinline__ void mma_bf16(float c[4], uint32_t a0, uint32_t a1,
                                         uint32_t a2, uint32_t a3,
                                         uint32_t b0, uint32_t b1) {
    asm volatile(
        "mma.sync.aligned.m16n8k16.row.col.f32.bf16.bf16.f32 "
        "{%0,%1,%2,%3}, {%4,%5,%6,%7}, {%8,%9}, {%0,%1,%2,%3};\n"
        : "+f"(c[0]), "+f"(c[1]), "+f"(c[2]), "+f"(c[3])
        : "r"(a0), "r"(a1), "r"(a2), "r"(a3), "r"(b0), "r"(b1));
}

// barrier among the first RBLK blocks only: atomic arrive, acquire-poll
__device__ __forceinline__ void rec_bar(int tid) {
    __threadfence();
    __syncthreads();
    if (tid == 0) {
        unsigned t0 = atomicAdd(&d_bar, 1u);
        unsigned target = t0 - (t0 % RBLK) + RBLK;
        unsigned v;
        do {
            asm volatile("ld.global.acquire.gpu.u32 %0, [%1];" : "=r"(v) : "l"(&d_bar));
        } while (v < target);
    }
    __syncthreads();
}

__device__ __forceinline__ unsigned ld_acq(const unsigned* p) {
    unsigned v;
    asm volatile("ld.global.acquire.gpu.u32 %0, [%1];" : "=r"(v) : "l"(p));
    return v;
}
__device__ __forceinline__ void st_rel(unsigned* p, unsigned v) {
    asm volatile("st.global.release.gpu.u32 [%0], %1;" :: "l"(p), "r"(v));
}

// ---------------- one-time converts -------------------------------------------
__global__ __launch_bounds__(256) void convert_wfc_kernel(const float4* __restrict__ W) {
    size_t gi = (size_t)blockIdx.x*256 + threadIdx.x;
    float4 v0 = W[gi*2];
    float4 v1 = W[gi*2+1];
    uint4 h, l;
    bfsplit2(v0.x, v0.y, h.x, l.x);
    bfsplit2(v0.z, v0.w, h.y, l.y);
    bfsplit2(v1.x, v1.y, h.z, l.z);
    bfsplit2(v1.z, v1.w, h.w, l.w);
    ((uint4*)d_wfh16)[gi] = h;
    ((uint4*)d_wfl16)[gi] = l;
}

__global__ __launch_bounds__(256) void convert_wihh_kernel(
        const float* __restrict__ Wih, const float* __restrict__ Whh) {
    int idx = blockIdx.x*256 + threadIdx.x;
    int n = idx / 768, p = idx % 768;
    int k = p * 2;
    float a, b;
    if (k < 1024) { a = Wih[(size_t)n*1024 + k]; b = Wih[(size_t)n*1024 + k + 1]; }
    else          { a = Whh[(size_t)n*512 + (k-1024)]; b = Whh[(size_t)n*512 + (k-1023)]; }
    uint32_t hi, lo; bfsplit2(a, b, hi, lo);
    d_wihh_h[idx] = hi; d_wihh_l[idx] = lo;
}

__global__ __launch_bounds__(256) void convert_wdg_kernel(
        const float* __restrict__ Wd, const float* __restrict__ Wg) {
    int idx = blockIdx.x*256 + threadIdx.x;
    int n = idx >> 8, p = idx & 255;
    int k = p * 2;
    const float* W = (n < 512) ? (Wd + (size_t)n*512) : (Wg + (size_t)(n-512)*512);
    uint32_t hi, lo; bfsplit2(W[k], W[k+1], hi, lo);
    d_wdg_h[idx] = hi; d_wdg_l[idx] = lo;
}

__global__ __launch_bounds__(256) void convert_emb_kernel(const float* __restrict__ emb) {
    int b = blockIdx.x, tt = blockIdx.y, tid = threadIdx.x;
    int tok = d_caps_s[b*ML + tt];
    const float* src = emb + (size_t)tok*512 + tid*2;
    uint32_t hi, lo; bfsplit2(src[0], src[1], hi, lo);
    size_t o = ((size_t)tt*BSZ + b)*256 + tid;
    d_embp_h[o] = hi; d_embp_l[o] = lo;
}

__global__ __launch_bounds__(256) void convert_h0_kernel() {
    int pid = blockIdx.x*256 + threadIdx.x;
    float a = d_hbuf[0][pid*2];
    float b = d_hbuf[0][pid*2+1];
    uint32_t hi, lo; bfsplit2(a, b, hi, lo);
    d_hph[0][pid] = hi; d_hpl[0][pid] = lo;
}

// ---------------- sort (stable, descending cap_len) + flag reset --------------
__global__ void sort_kernel(const int* __restrict__ cap_len,
                            const int* __restrict__ caps,
                            float* __restrict__ out_caps,
                            float* __restrict__ out_declen,
                            float* __restrict__ out_order) {
    int i = threadIdx.x;
    if (i == 0) { d_hready = 0u; d_pdone = 0u; }
    int cl = cap_len[i];
    int r = 0;
    for (int j = 0; j < BSZ; j++) {
        int cj = cap_len[j];
        if (cj > cl || (cj == cl && j < i)) r++;
    }
    d_order[r]  = i;
    d_declen[r] = cl - 1;
    __syncthreads();
    out_order[i]  = (float)d_order[i];
    out_declen[i] = (float)d_declen[i];
    int src = d_order[i];
    for (int tt = 0; tt < ML; tt++) {
        int tok = caps[src*ML + tt];
        d_caps_s[i*ML + tt] = tok;
        out_caps[i*ML + tt] = (float)tok;
    }
    if (i < TT) {
        int cnt = 0;
        for (int j = 0; j < BSZ; j++) if (d_declen[j] > i) cnt++;
        d_nact[i] = cnt;
    }
}

// ---------------- reorder encoder + per-batch pixel mean ----------------------
__global__ __launch_bounds__(256) void reorder_mean_kernel(const float* __restrict__ enc) {
    int b = blockIdx.x;
    int tid = threadIdx.x;
    int src = d_order[b];
    const float* Ein = enc + (size_t)src*NPIX*ENCD;
    float* Eo = d_enc_s + (size_t)b*NPIX*ENCD;
    float s0 = 0.f, s1 = 0.f;
    for (int p = 0; p < NPIX; p++) {
        float v0 = Ein[p*ENCD + tid];
        float v1 = Ein[p*ENCD + tid + 256];
        Eo[p*ENCD + tid]       = v0;
        Eo[p*ENCD + tid + 256] = v1;
        s0 += v0; s1 += v1;
    }
    d_mean[b*ENCD + tid]       = s0 * (1.0f/NPIX);
    d_mean[b*ENCD + tid + 256] = s1 * (1.0f/NPIX);
}

// ---------------- small GEMM for h0/c0: C = A @ W^T + bias -------------------
__global__ __launch_bounds__(256) void gemm64_kernel(int sel,
        const float* __restrict__ Wmat, const float* __restrict__ bias,
        int K, int N) {
    const float* Amat = d_mean;
    float*       Cmat = (sel == 1) ? d_hbuf[0] : d_c;
    __shared__ float sA[32][64];
    __shared__ float sW[32][64];
    int tid = threadIdx.x;
    int tx = tid & 15, ty = tid >> 4;
    int m0 = blockIdx.y * 64;
    int n0 = blockIdx.x * 64;
    float acc[4][4] = {};
    for (int k0 = 0; k0 < K; k0 += 32) {
        #pragma unroll
        for (int u = 0; u < 2; u++) {
            int f4i = tid + u*256;
            int m  = f4i >> 3;
            int kk = (f4i & 7) << 2;
            float4 a = *(const float4*)&Amat[(size_t)(m0+m)*K + k0 + kk];
            sA[kk][m] = a.x; sA[kk+1][m] = a.y; sA[kk+2][m] = a.z; sA[kk+3][m] = a.w;
            float4 w = *(const float4*)&Wmat[(size_t)(n0+m)*K + k0 + kk];
            sW[kk][m] = w.x; sW[kk+1][m] = w.y; sW[kk+2][m] = w.z; sW[kk+3][m] = w.w;
        }
        __syncthreads();
        #pragma unroll
        for (int k = 0; k < 32; k++) {
            float4 a = *(const float4*)&sA[k][ty*4];
            float4 w = *(const float4*)&sW[k][tx*4];
            float av[4] = {a.x, a.y, a.z, a.w};
            float wv[4] = {w.x, w.y, w.z, w.w};
            #pragma unroll
            for (int i = 0; i < 4; i++)
                #pragma unroll
                for (int j = 0; j < 4; j++)
                    acc[i][j] += av[i] * wv[j];
        }
        __syncthreads();
    }
    #pragma unroll
    for (int i = 0; i < 4; i++) {
        int m = m0 + ty*4 + i;
        #pragma unroll
        for (int j = 0; j < 4; j++) {
            int n = n0 + tx*4 + j;
            Cmat[(size_t)m*N + n] = acc[i][j] + bias[n];
        }
    }
}

// ---------------- ea = enc_s @ W_enc^T + b via bf16 3-term split mma ----------
__global__ void __launch_bounds__(256, 2) ea_mma_kernel(
        const float* __restrict__ Wenc, const float* __restrict__ bias) {
    extern __shared__ __align__(16) uint32_t sm[];
    uint32_t* Asm = sm;                  // [64][36]
    uint32_t* Wsm = sm + 64*36;          // [256][36]

    int m0 = blockIdx.y * 64;
    int n0 = blockIdx.x * 256;
    int tid = threadIdx.x;
    int lane = tid & 31, wp = tid >> 5;
    int g = lane >> 2, tig = lane & 3;

    float acc[4][4][4];
    #pragma unroll
    for (int a = 0; a < 4; a++)
        #pragma unroll
        for (int b2 = 0; b2 < 4; b2++)
            #pragma unroll
            for (int c2 = 0; c2 < 4; c2++) acc[a][b2][c2] = 0.f;

    for (int kt = 0; kt < 16; kt++) {
        {
            int row = tid >> 2, c = tid & 3;
            const float* src = d_enc_s + (size_t)(m0+row)*512 + kt*32 + c*8;
            float4 v0 = *(const float4*)src;
            float4 v1 = *(const float4*)(src + 4);
            uint4 h, l;
            bfsplit2(v0.x, v0.y, h.x, l.x);
            bfsplit2(v0.z, v0.w, h.y, l.y);
            bfsplit2(v1.x, v1.y, h.z, l.z);
            bfsplit2(v1.z, v1.w, h.w, l.w);
            *(uint4*)&Asm[row*36 + c*4]      = h;
            *(uint4*)&Asm[row*36 + 16 + c*4] = l;
        }
        #pragma unroll
        for (int u = 0; u < 4; u++) {
            int cid = tid + u*256;
            int row = cid >> 2, c = cid & 3;
            const float* src = Wenc + (size_t)(n0+row)*512 + kt*32 + c*8;
            float4 v0 = *(const float4*)src;
            float4 v1 = *(const float4*)(src + 4);
            uint4 h, l;
            bfsplit2(v0.x, v0.y, h.x, l.x);
            bfsplit2(v0.z, v0.w, h.y, l.y);
            bfsplit2(v1.x, v1.y, h.z, l.z);
            bfsplit2(v1.z, v1.w, h.w, l.w);
            *(uint4*)&Wsm[row*36 + c*4]      = h;
            *(uint4*)&Wsm[row*36 + 16 + c*4] = l;
        }
        __syncthreads();
        #pragma unroll
        for (int ks = 0; ks < 2; ks++) {
            int ko = ks*8 + tig;
            uint32_t ah[4][4], al[4][4];
            #pragma unroll
            for (int mf = 0; mf < 4; mf++) {
                int r0 = (mf*16 + g)*36, r1 = (mf*16 + g + 8)*36;
                ah[mf][0] = Asm[r0 + ko];      ah[mf][1] = Asm[r1 + ko];
                ah[mf][2] = Asm[r0 + ko + 4];  ah[mf][3] = Asm[r1 + ko + 4];
                al[mf][0] = Asm[r0 + 16 + ko];     al[mf][1] = Asm[r1 + 16 + ko];
                al[mf][2] = Asm[r0 + 16 + ko + 4]; al[mf][3] = Asm[r1 + 16 + ko + 4];
            }
            #pragma unroll
            for (int nf = 0; nf < 4; nf++) {
                int rw = (wp*32 + nf*8 + g)*36 + ko;
                uint32_t bh0 = Wsm[rw], bh1 = Wsm[rw + 4];
                uint32_t bl0 = Wsm[rw + 16], bl1 = Wsm[rw + 20];
                #pragma unroll
                for (int mf = 0; mf < 4; mf++) {
                    mma_bf16(acc[mf][nf], ah[mf][0], ah[mf][1], ah[mf][2], ah[mf][3], bh0, bh1);
                    mma_bf16(acc[mf][nf], al[mf][0], al[mf][1], al[mf][2], al[mf][3], bh0, bh1);
                    mma_bf16(acc[mf][nf], ah[mf][0], ah[mf][1], ah[mf][2], ah[mf][3], bl0, bl1);
                }
            }
        }
        __syncthreads();
    }

    #pragma unroll
    for (int nf = 0; nf < 4; nf++) {
        int n = n0 + wp*32 + nf*8 + 2*tig;
        float2 bb = *(const float2*)&bias[n];
        #pragma unroll
        for (int mf = 0; mf < 4; mf++) {
            int m1 = m0 + mf*16 + g;
            float2 o1; o1.x = acc[mf][nf][0] + bb.x; o1.y = acc[mf][nf][1] + bb.y;
            *(float2*)&d_ea[(size_t)m1*512 + n] = o1;
            int m2 = m1 + 8;
            float2 o2; o2.x = acc[mf][nf][2] + bb.x; o2.y = acc[mf][nf][3] + bb.y;
            *(float2*)&d_ea[(size_t)m2*512 + n] = o2;
        }
    }
}

// ---------------- standalone dagate (step-0 prologue, SIMT) -------------------
__global__ __launch_bounds__(256) void dagate_kernel(
        const float* __restrict__ Wd, const float* __restrict__ bd,
        const float* __restrict__ Wg, const float* __restrict__ bg) {
    __shared__ float sA[32][64];
    __shared__ float sW[32][64];
    const float* hsrc = d_hbuf[0];
    int tid = threadIdx.x;
    int tx = tid & 15, ty = tid >> 4;
    int n0 = blockIdx.x * 64;
    const float* Wmat = (n0 < 512) ? (Wd + (size_t)n0*512) : (Wg + (size_t)(n0-512)*512);
    float acc[4][4] = {};
    for (int k0 = 0; k0 < 512; k0 += 32) {
        #pragma unroll
        for (int u = 0; u < 2; u++) {
            int f4i = tid + u*256;
            int m  = f4i >> 3;
            int kk = (f4i & 7) << 2;
            float4 a = *(const float4*)&hsrc[(size_t)m*512 + k0 + kk];
            sA[kk][m] = a.x; sA[kk+1][m] = a.y; sA[kk+2][m] = a.z; sA[kk+3][m] = a.w;
            float4 w = *(const float4*)&Wmat[(size_t)m*512 + k0 + kk];
            sW[kk][m] = w.x; sW[kk+1][m] = w.y; sW[kk+2][m] = w.z; sW[kk+3][m] = w.w;
        }
        __syncthreads();
        #pragma unroll
        for (int k = 0; k < 32; k++) {
            float4 a = *(const float4*)&sA[k][ty*4];
            float4 w = *(const float4*)&sW[k][tx*4];
            float av[4] = {a.x, a.y, a.z, a.w};
            float wv[4] = {w.x, w.y, w.z, w.w};
            #pragma unroll
            for (int i = 0; i < 4; i++)
                #pragma unroll
                for (int j = 0; j < 4; j++)
                    acc[i][j] += av[i] * wv[j];
        }
        __syncthreads();
    }
    #pragma unroll
    for (int i = 0; i < 4; i++) {
        int m = ty*4 + i;
        #pragma unroll
        for (int j = 0; j < 4; j++) {
            int n = n0 + tx*4 + j;
            if (n < 512) d_da[m*512 + n] = acc[i][j] + bd[n];
            else         d_gate[m*512 + (n-512)] = sigmoidf_(acc[i][j] + bg[n-512]);
        }
    }
}

// ---------------- preds issue + body -------------------------------------------
__device__ __forceinline__ void preds_issue(uint32_t* Asm, uint32_t* Wsm,
        int stage, int kt, int n0, int tid, const uint4* hph, const uint4* hpl) {
    uint32_t* As = Asm + stage*(64*36);
    uint32_t* Ws = Wsm + stage*(256*36);
    #pragma unroll
    for (int u = 0; u < 2; u++) {
        int cid = tid + u*256;
        int row = cid >> 3, c = cid & 7;
        const uint4* src = ((c < 4) ? hph : hpl) + row*64 + kt*4 + (c & 3);
        uint32_t* dst = As + row*36 + ((c < 4) ? c*4 : 16 + (c - 4)*4);
        __pipeline_memcpy_async(dst, src, 16);
    }
    const uint4* wh = (const uint4*)d_wfh16;
    const uint4* wl = (const uint4*)d_wfl16;
    #pragma unroll
    for (int u = 0; u < 8; u++) {
        int cid = tid + u*256;
        int row = cid >> 3, c = cid & 7;
        const uint4* src = ((c < 4) ? wh : wl) + (size_t)(n0 + row)*64 + kt*4 + (c & 3);
        uint32_t* dst = Ws + row*36 + ((c < 4) ? c*4 : 16 + (c - 4)*4);
        __pipeline_memcpy_async(dst, src, 16);
    }
    __pipeline_commit();
}

__device__ void preds_body(int j, uint32_t* sm, int tid,
                           const float* __restrict__ bfc,
                           float* __restrict__ out_pred, int n0) {
    int nact = d_nact[j];
    int mfmax = (nact + 15) >> 4;
    int hb = (j + 1) & 1;
    uint32_t* Asm = sm;
    uint32_t* Wsm = sm + 2*64*36;

    int lane = tid & 31, wp = tid >> 5;
    int g = lane >> 2, tig = lane & 3;
    const uint4* hph = (const uint4*)d_hph[hb];
    const uint4* hpl = (const uint4*)d_hpl[hb];

    float acc[4][4][4];
    #pragma unroll
    for (int a = 0; a < 4; a++)
        #pragma unroll
        for (int b2 = 0; b2 < 4; b2++)
            #pragma unroll
            for (int c2 = 0; c2 < 4; c2++) acc[a][b2][c2] = 0.f;

    preds_issue(Asm, Wsm, 0, 0, n0, tid, hph, hpl);
    for (int kt = 0; kt < 16; kt++) {
        int stage = kt & 1;
        if (kt < 15) {
            preds_issue(Asm, Wsm, stage ^ 1, kt + 1, n0, tid, hph, hpl);
            __pipeline_wait_prior(1);
        } else {
            __pipeline_wait_prior(0);
        }
        __syncthreads();
        const uint32_t* Ahs = Asm + stage*(64*36);
        const uint32_t* Whs = Wsm + stage*(256*36);
        #pragma unroll
        for (int ks = 0; ks < 2; ks++) {
            int ko = ks*8 + tig;
            uint32_t ah[4][4], al[4][4];
            #pragma unroll
            for (int mf = 0; mf < 4; mf++) {
                if (mf >= mfmax) continue;
                int r0 = (mf*16 + g)*36, r1 = (mf*16 + g + 8)*36;
                ah[mf][0] = Ahs[r0 + ko];      ah[mf][1] = Ahs[r1 + ko];
                ah[mf][2] = Ahs[r0 + ko + 4];  ah[mf][3] = Ahs[r1 + ko + 4];
                al[mf][0] = Ahs[r0 + 16 + ko];     al[mf][1] = Ahs[r1 + 16 + ko];
                al[mf][2] = Ahs[r0 + 16 + ko + 4]; al[mf][3] = Ahs[r1 + 16 + ko + 4];
            }
            #pragma unroll
            for (int nf = 0; nf < 4; nf++) {
                int rw = (wp*32 + nf*8 + g)*36 + ko;
                uint32_t bh0 = Whs[rw], bh1 = Whs[rw + 4];
                uint32_t bl0 = Whs[rw + 16], bl1 = Whs[rw + 20];
                #pragma unroll
                for (int mf = 0; mf < 4; mf++) {
                    if (mf >= mfmax) continue;
                    mma_bf16(acc[mf][nf], ah[mf][0], ah[mf][1], ah[mf][2], ah[mf][3], bh0, bh1);
                    mma_bf16(acc[mf][nf], al[mf][0], al[mf][1], al[mf][2], al[mf][3], bh0, bh1);
                    mma_bf16(acc[mf][nf], ah[mf][0], ah[mf][1], ah[mf][2], ah[mf][3], bl0, bl1);
                }
            }
        }
        __syncthreads();
    }

    size_t tbase = (size_t)j * VV;
    #pragma unroll
    for (int nf = 0; nf < 4; nf++) {
        int n = n0 + wp*32 + nf*8 + 2*tig;
        float2 bb = *(const float2*)&bfc[n];
        #pragma unroll
        for (int mf = 0; mf < 4; mf++) {
            int m1 = mf*16 + g;
            float2 o1;
            o1.x = (m1 < nact) ? acc[mf][nf][0] + bb.x : 0.f;
            o1.y = (m1 < nact) ? acc[mf][nf][1] + bb.y : 0.f;
            *(float2*)&out_pred[(size_t)m1*((size_t)TT*VV) + tbase + n] = o1;
            int m2 = m1 + 8;
            float2 o2;
            o2.x = (m2 < nact) ? acc[mf][nf][2] + bb.x : 0.f;
            o2.y = (m2 < nact) ? acc[mf][nf][3] + bb.y : 0.f;
            *(float2*)&out_pred[(size_t)m2*((size_t)TT*VV) + tbase + n] = o2;
        }
    }
}

// ---------------- phase-B issue: A from packed (emb|ctx|h), W from wihh -------
__device__ __forceinline__ void lstm_issue(uint32_t* Asm, uint32_t* Wsm,
        int stage, int c0, int n0, int tid, int t, int hb) {
    uint32_t* As = Asm + stage*(64*36);
    uint32_t* Ws = Wsm + stage*(256*36);
    const uint4* ah4; const uint4* al4; int off4;
    if (c0 < 512) {
        ah4 = (const uint4*)d_embp_h + (size_t)t*BSZ*64;
        al4 = (const uint4*)d_embp_l + (size_t)t*BSZ*64;
        off4 = c0 >> 3;
    } else if (c0 < 1024) {
        ah4 = (const uint4*)d_ctxp_h;
        al4 = (const uint4*)d_ctxp_l;
        off4 = (c0 - 512) >> 3;
    } else {
        ah4 = (const uint4*)d_hph[hb];
        al4 = (const uint4*)d_hpl[hb];
        off4 = (c0 - 1024) >> 3;
    }
    #pragma unroll
    for (int u = 0; u < 2; u++) {
        int cid = tid + u*256;
        int row = cid >> 3, c = cid & 7;
        const uint4* src = ((c < 4) ? ah4 : al4) + (size_t)row*64 + off4 + (c & 3);
        uint32_t* dst = As + row*36 + ((c < 4) ? c*4 : 16 + (c - 4)*4);
        __pipeline_memcpy_async(dst, src, 16);
    }
    const uint4* wh = (const uint4*)d_wihh_h;
    const uint4* wl = (const uint4*)d_wihh_l;
    int woff4 = c0 >> 3;
    #pragma unroll
    for (int u = 0; u < 8; u++) {
        int cid = tid + u*256;
        int row = cid >> 3, c = cid & 7;
        const uint4* src = ((c < 4) ? wh : wl) + (size_t)(n0 + row)*192 + woff4 + (c & 3);
        uint32_t* dst = Ws + row*36 + ((c < 4) ? c*4 : 16 + (c - 4)*4);
        __pipeline_memcpy_async(dst, src, 16);
    }
    __pipeline_commit();
}

// ---------------- phase-D issue: A = h packed, W = wdg packed (N=64) ----------
__device__ __forceinline__ void dg_issue(uint32_t* Asm, uint32_t* Wsm,
        int stage, int kt, int n0, int tid, int hbw) {
    uint32_t* As = Asm + stage*(64*36);
    uint32_t* Ws = Wsm + stage*(64*36);
    const uint4* ah4 = (const uint4*)d_hph[hbw];
    const uint4* al4 = (const uint4*)d_hpl[hbw];
    #pragma unroll
    for (int u = 0; u < 2; u++) {
        int cid = tid + u*256;
        int row = cid >> 3, c = cid & 7;
        const uint4* src = ((c < 4) ? ah4 : al4) + (size_t)row*64 + kt*4 + (c & 3);
        uint32_t* dst = As + row*36 + ((c < 4) ? c*4 : 16 + (c - 4)*4);
        __pipeline_memcpy_async(dst, src, 16);
    }
    const uint4* wh = (const uint4*)d_wdg_h;
    const uint4* wl = (const uint4*)d_wdg_l;
    #pragma unroll
    for (int u = 0; u < 2; u++) {
        int cid = tid + u*256;
        int row = cid >> 3, c = cid & 7;
        const uint4* src = ((c < 4) ? wh : wl) + (size_t)(n0 + row)*64 + kt*4 + (c & 3);
        uint32_t* dst = Ws + row*36 + ((c < 4) ? c*4 : 16 + (c - 4)*4);
        __pipeline_memcpy_async(dst, src, 16);
    }
    __pipeline_commit();
}

// ============ PERSISTENT: all 50 steps; rec on blocks 0..63, preds on 64+ =====
__global__ void __launch_bounds__(256, 2) persistent_kernel(
        const float* __restrict__ wf, const float* __restrict__ bf_scalar,
        const float* __restrict__ bih, const float* __restrict__ bhh,
        const float* __restrict__ bd, const float* __restrict__ bg,
        const float* __restrict__ bfc,
        float* __restrict__ out_alphas, float* __restrict__ out_pred) {
    extern __shared__ __align__(16) uint32_t smem_u[];
    int bid = blockIdx.x;
    int tid = threadIdx.x;

    if (bid >= RBLK) {
        // ---------------- preds group: one n-tile, all steps -------------------
        int n0 = (bid - RBLK) * 256;
        for (int j = 0; j < TT; j++) {
            if (tid == 0) {
                while (ld_acq(&d_hready) < (unsigned)(j + 1)) { }
            }
            __syncthreads();
            preds_body(j, smem_u, tid, bfc, out_pred, n0);
            __syncthreads();               // all reads of hph done
            if (tid == 0) atomicAdd(&d_pdone, 1u);
        }
        return;
    }

    // ---------------- recurrence group -----------------------------------------
    for (int t = 0; t < TT; t++) {
        int hb  = t & 1;
        int hbw = (t + 1) & 1;

        // phase A: attention
        if (t < d_declen[bid]) {
            int b = bid;
            int lane = tid & 31, warp = tid >> 5;
            float4* s_da = (float4*)smem_u;
            float4* s_wf = s_da + 128;
            float*  sc   = (float*)(s_wf + 128);
            float*  red  = sc + 200;

            if (tid < 128) {
                s_da[tid] = ((const float4*)d_da)[b*128 + tid];
                s_wf[tid] = ((const float4*)wf)[tid];
            }
            __syncthreads();

            const float4* ea4 = ((const float4*)d_ea) + (size_t)b*NPIX*128;
            float bfull = bf_scalar[0];
            for (int p0 = warp*2; p0 < NPIX; p0 += 16) {
                int p1 = p0 + 1;
                float s0 = 0.f, s1 = 0.f;
                #pragma unroll
                for (int j = 0; j < 4; j++) {
                    int k4 = lane + j*32;
                    float4 e0 = ea4[p0*128 + k4];
                    float4 e1 = ea4[p1*128 + k4];
                    float4 da = s_da[k4];
                    float4 w  = s_wf[k4];
                    s0 += fmaxf(e0.x + da.x, 0.f) * w.x;
                    s0 += fmaxf(e0.y + da.y, 0.f) * w.y;
                    s0 += fmaxf(e0.z + da.z, 0.f) * w.z;
                    s0 += fmaxf(e0.w + da.w, 0.f) * w.w;
                    s1 += fmaxf(e1.x + da.x, 0.f) * w.x;
                    s1 += fmaxf(e1.y + da.y, 0.f) * w.y;
                    s1 += fmaxf(e1.z + da.z, 0.f) * w.z;
                    s1 += fmaxf(e1.w + da.w, 0.f) * w.w;
                }
                s0 = warp_sum(s0);
                s1 = warp_sum(s1);
                if (lane == 0) { sc[p0] = s0 + bfull; sc[p1] = s1 + bfull; }
            }
            __syncthreads();

            float v = (tid < NPIX) ? sc[tid] : -1e30f;
            float wm = warp_max(v);
            if (lane == 0) red[warp] = wm;
            __syncthreads();
            if (tid == 0) {
                float mm = red[0];
                #pragma unroll
                for (int i = 1; i < 8; i++) mm = fmaxf(mm, red[i]);
                red[16] = mm;
            }
            __syncthreads();
            float gmax = red[16];
            float e = (tid < NPIX) ? __expf(v - gmax) : 0.f;
            float ws = warp_sum(e);
            if (lane == 0) red[8 + warp] = ws;
            __syncthreads();
            if (tid == 0) {
                float ss = 0.f;
                #pragma unroll
                for (int i = 0; i < 8; i++) ss += red[8 + i];
                red[17] = ss;
            }
            __syncthreads();
            float alpha = e / red[17];
            __syncthreads();
            if (tid < NPIX) {
                sc[tid] = alpha;
                out_alphas[(size_t)b*TT*NPIX + (size_t)t*NPIX + tid] = alpha;
            }
            __syncthreads();

            const float2* encb2 = (const float2*)(d_enc_s + (size_t)b*NPIX*512);
            float sx[16], sy[16];
            #pragma unroll
            for (int u = 0; u < 16; u++) { sx[u] = 0.f; sy[u] = 0.f; }
            #pragma unroll 2
            for (int p0 = 0; p0 < 192; p0 += 16) {
                #pragma unroll
                for (int u = 0; u < 16; u++) {
                    float2 vv = encb2[(p0+u)*256 + tid];
                    float al = sc[p0+u];
                    sx[u] += al * vv.x;
                    sy[u] += al * vv.y;
                }
            }
            #pragma unroll
            for (int u = 0; u < 4; u++) {
                float2 vv = encb2[(192+u)*256 + tid];
                float al = sc[192+u];
                sx[u] += al * vv.x;
                sy[u] += al * vv.y;
            }
            float X = 0.f, Y = 0.f;
            #pragma unroll
            for (int u = 0; u < 16; u++) { X += sx[u]; Y += sy[u]; }
            float2 g2 = ((const float2*)d_gate)[b*256 + tid];
            float cx = X * g2.x, cy = Y * g2.y;
            uint32_t chi, clo; bfsplit2(cx, cy, chi, clo);
            d_ctxp_h[b*256 + tid] = chi;
            d_ctxp_l[b*256 + tid] = clo;
        }
        rec_bar(tid);

        // phase B: LSTM gate GEMM via mma (8 n-tiles x 8 k-splits)
        {
            uint32_t* Asm = smem_u;
            uint32_t* Wsm = smem_u + 2*64*36;
            int n0 = (bid & 7) * 256;
            int ksplit = bid >> 3;
            int kbase = ksplit * 192;
            int lane = tid & 31, wp = tid >> 5;
            int g = lane >> 2, tig = lane & 3;

            float acc[4][4][4];
            #pragma unroll
            for (int a = 0; a < 4; a++)
                #pragma unroll
                for (int b2 = 0; b2 < 4; b2++)
                    #pragma unroll
                    for (int c2 = 0; c2 < 4; c2++) acc[a][b2][c2] = 0.f;

            lstm_issue(Asm, Wsm, 0, kbase, n0, tid, t, hb);
            for (int kt = 0; kt < 6; kt++) {
                int stage = kt & 1;
                if (kt < 5) {
                    lstm_issue(Asm, Wsm, stage ^ 1, kbase + (kt+1)*32, n0, tid, t, hb);
                    __pipeline_wait_prior(1);
                } else {
                    __pipeline_wait_prior(0);
                }
                __syncthreads();
                const uint32_t* Ahs = Asm + stage*(64*36);
                const uint32_t* Whs = Wsm + stage*(256*36);
                #pragma unroll
                for (int ks = 0; ks < 2; ks++) {
                    int ko = ks*8 + tig;
                    uint32_t ah[4][4], al[4][4];
                    #pragma unroll
                    for (int mf = 0; mf < 4; mf++) {
                        int r0 = (mf*16 + g)*36, r1 = (mf*16 + g + 8)*36;
                        ah[mf][0] = Ahs[r0 + ko];      ah[mf][1] = Ahs[r1 + ko];
                        ah[mf][2] = Ahs[r0 + ko + 4];  ah[mf][3] = Ahs[r1 + ko + 4];
                        al[mf][0] = Ahs[r0 + 16 + ko];     al[mf][1] = Ahs[r1 + 16 + ko];
                        al[mf][2] = Ahs[r0 + 16 + ko + 4]; al[mf][3] = Ahs[r1 + 16 + ko + 4];
                    }
                    #pragma unroll
                    for (int nf = 0; nf < 4; nf++) {
                        int rw = (wp*32 + nf*8 + g)*36 + ko;
                        uint32_t bh0 = Whs[rw], bh1 = Whs[rw + 4];
                        uint32_t bl0 = Whs[rw + 16], bl1 = Whs[rw + 20];
                        #pragma unroll
                        for (int mf = 0; mf < 4; mf++) {
                            mma_bf16(acc[mf][nf], ah[mf][0], ah[mf][1], ah[mf][2], ah[mf][3], bh0, bh1);
                            mma_bf16(acc[mf][nf], al[mf][0], al[mf][1], al[mf][2], al[mf][3], bh0, bh1);
                            mma_bf16(acc[mf][nf], ah[mf][0], ah[mf][1], ah[mf][2], ah[mf][3], bl0, bl1);
                        }
                    }
                }
                __syncthreads();
            }

            float* gp = d_gates_p + (size_t)ksplit * (BSZ*2048);
            #pragma unroll
            for (int nf = 0; nf < 4; nf++) {
                int n = n0 + wp*32 + nf*8 + 2*tig;
                #pragma unroll
                for (int mf = 0; mf < 4; mf++) {
                    int m1 = mf*16 + g;
                    float2 o1; o1.x = acc[mf][nf][0]; o1.y = acc[mf][nf][1];
                    *(float2*)&gp[m1*2048 + n] = o1;
                    int m2 = m1 + 8;
                    float2 o2; o2.x = acc[mf][nf][2]; o2.y = acc[mf][nf][3];
                    *(float2*)&gp[m2*2048 + n] = o2;
                }
            }
        }
        rec_bar(tid);

        // phase C: LSTM apply + bf16 pack (blocks 0..15)
        if (bid < 16) {
            // WAR: preds(t-2) reads hph[hbw]; wait until it finished
            if (t >= 2 && tid == 0) {
                unsigned need = (unsigned)(t - 1) * PBLK;
                while (ld_acq(&d_pdone) < need) { }
            }
            __syncthreads();

            int gid = bid*256 + tid;
            int idx0 = gid*8;
            int b = idx0 >> 9;
            int f0 = (idx0 & 511) >> 2;
            float acc[4][8];
            #pragma unroll
            for (int q = 0; q < 4; q++)
                #pragma unroll
                for (int e = 0; e < 8; e++) acc[q][e] = 0.f;
            #pragma unroll
            for (int s = 0; s < NSPLIT; s++) {
                const float4* g4 = (const float4*)(d_gates_p + (size_t)s*(BSZ*2048) + b*2048);
                #pragma unroll
                for (int q = 0; q < 4; q++) {
                    float4 v0 = g4[q*128 + f0];
                    float4 v1 = g4[q*128 + f0 + 1];
                    acc[q][0] += v0.x; acc[q][1] += v0.y; acc[q][2] += v0.z; acc[q][3] += v0.w;
                    acc[q][4] += v1.x; acc[q][5] += v1.y; acc[q][6] += v1.z; acc[q][7] += v1.w;
                }
            }
            const float4* bi4 = (const float4*)bih;
            const float4* bh4 = (const float4*)bhh;
            #pragma unroll
            for (int q = 0; q < 4; q++) {
                float4 u0 = bi4[q*128 + f0], u1 = bi4[q*128 + f0 + 1];
                float4 w0 = bh4[q*128 + f0], w1 = bh4[q*128 + f0 + 1];
                acc[q][0] += u0.x + w0.x; acc[q][1] += u0.y + w0.y;
                acc[q][2] += u0.z + w0.z; acc[q][3] += u0.w + w0.w;
                acc[q][4] += u1.x + w1.x; acc[q][5] += u1.y + w1.y;
                acc[q][6] += u1.z + w1.z; acc[q][7] += u1.w + w1.w;
            }
            float hv[8];
            #pragma unroll
            for (int e = 0; e < 8; e++) {
                float ig = sigmoidf_(acc[0][e]);
                float fg = sigmoidf_(acc[1][e]);
                float g2 = tanhf(acc[2][e]);
                float og = sigmoidf_(acc[3][e]);
                float c  = fg * d_c[idx0 + e] + ig * g2;
                float h  = og * tanhf(c);
                d_c[idx0 + e] = c;
                hv[e] = h;
            }
            uint4 ph, pl;
            bfsplit2(hv[0], hv[1], ph.x, pl.x);
            bfsplit2(hv[2], hv[3], ph.y, pl.y);
            bfsplit2(hv[4], hv[5], ph.z, pl.z);
            bfsplit2(hv[6], hv[7], ph.w, pl.w);
            ((uint4*)d_hph[hbw])[gid] = ph;
            ((uint4*)d_hpl[hbw])[gid] = pl;
        }
        rec_bar(tid);

        // publish h(t) for preds group (after barrier => all C writes fenced)
        if (bid == 0 && tid == 0) st_rel(&d_hready, (unsigned)(t + 1));

        // phase D: dagate via mma (blocks 0..15, N=64)
        if (bid < 16) {
            uint32_t* Asm = smem_u;
            uint32_t* Wsm = smem_u + 2*64*36;
            int n0 = bid * 64;
            int lane = tid & 31, wp = tid >> 5;
            int g = lane >> 2, tig = lane & 3;

            float acc[4][4];
            #pragma unroll
            for (int a = 0; a < 4; a++)
                #pragma unroll
                for (int c2 = 0; c2 < 4; c2++) acc[a][c2] = 0.f;

            dg_issue(Asm, Wsm, 0, 0, n0, tid, hbw);
            for (int kt = 0; kt < 16; kt++) {
                int stage = kt & 1;
                if (kt < 15) {
                    dg_issue(Asm, Wsm, stage ^ 1, kt + 1, n0, tid, hbw);
                    __pipeline_wait_prior(1);
                } else {
                    __pipeline_wait_prior(0);
                }
                __syncthreads();
                const uint32_t* Ahs = Asm + stage*(64*36);
                const uint32_t* Whs = Wsm + stage*(64*36);
                #pragma unroll
                for (int ks = 0; ks < 2; ks++) {
                    int ko = ks*8 + tig;
                    int rw = (wp*8 + g)*36 + ko;
                    uint32_t bh0 = Whs[rw], bh1 = Whs[rw + 4];
                    uint32_t bl0 = Whs[rw + 16], bl1 = Whs[rw + 20];
                    #pragma unroll
                    for (int mf = 0; mf < 4; mf++) {
                        int r0 = (mf*16 + g)*36, r1 = (mf*16 + g + 8)*36;
                        uint32_t a0 = Ahs[r0 + ko],      a1 = Ahs[r1 + ko];
                        uint32_t a2 = Ahs[r0 + ko + 4],  a3 = Ahs[r1 + ko + 4];
                        uint32_t l0 = Ahs[r0 + 16 + ko],     l1 = Ahs[r1 + 16 + ko];
                        uint32_t l2 = Ahs[r0 + 16 + ko + 4], l3 = Ahs[r1 + 16 + ko + 4];
                        mma_bf16(acc[mf], a0, a1, a2, a3, bh0, bh1);
                        mma_bf16(acc[mf], l0, l1, l2, l3, bh0, bh1);
                        mma_bf16(acc[mf], a0, a1, a2, a3, bl0, bl1);
                    }
                }
                __syncthreads();
            }

            int n = n0 + wp*8 + 2*tig;
            #pragma unroll
            for (int mf = 0; mf < 4; mf++) {
                int m1 = mf*16 + g;
                int m2 = m1 + 8;
                if (n < 512) {
                    float2 bb = *(const float2*)&bd[n];
                    float2 o1; o1.x = acc[mf][0] + bb.x; o1.y = acc[mf][1] + bb.y;
                    *(float2*)&d_da[m1*512 + n] = o1;
                    float2 o2; o2.x = acc[mf][2] + bb.x; o2.y = acc[mf][3] + bb.y;
                    *(float2*)&d_da[m2*512 + n] = o2;
                } else {
                    int ng = n - 512;
                    float2 bb = *(const float2*)&bg[ng];
                    float2 o1; o1.x = sigmoidf_(acc[mf][0] + bb.x); o1.y = sigmoidf_(acc[mf][1] + bb.y);
                    *(float2*)&d_gate[m1*512 + ng] = o1;
                    float2 o2; o2.x = sigmoidf_(acc[mf][2] + bb.x); o2.y = sigmoidf_(acc[mf][3] + bb.y);
                    *(float2*)&d_gate[m2*512 + ng] = o2;
                }
            }
        }
        rec_bar(tid);   // D(t) -> A(t+1)
    }
}

// ---------------- launch ------------------------------------------------------
extern "C" void kernel_launch(void* const* d_in, const int* in_sizes, int n_in,
                              void* d_out, int out_size) {
    const float* encoder_out = (const float*)d_in[0];
    const int*   caps        = (const int*)  d_in[1];
    const int*   cap_len     = (const int*)  d_in[2];
    const float* W_enc_attn  = (const float*)d_in[3];
    const float* b_enc_attn  = (const float*)d_in[4];
    const float* W_dec_attn  = (const float*)d_in[5];
    const float* b_dec_attn  = (const float*)d_in[6];
    const float* w_full_attn = (const float*)d_in[7];
    const float* b_full_attn = (const float*)d_in[8];
    const float* emb_table   = (const float*)d_in[9];
    const float* W_ih        = (const float*)d_in[10];
    const float* W_hh        = (const float*)d_in[11];
    const float* b_ih        = (const float*)d_in[12];
    const float* b_hh        = (const float*)d_in[13];
    const float* W_init_h    = (const float*)d_in[14];
    const float* b_init_h    = (const float*)d_in[15];
    const float* W_init_c    = (const float*)d_in[16];
    const float* b_init_c    = (const float*)d_in[17];
    const float* W_f_beta    = (const float*)d_in[18];
    const float* b_f_beta    = (const float*)d_in[19];
    const float* W_fc        = (const float*)d_in[20];
    const float* b_fc        = (const float*)d_in[21];

    float* out = (float*)d_out;
    const size_t OFF_PRED   = 0;
    const size_t OFF_CAPS   = OFF_PRED + (size_t)BSZ*TT*VV;
    const size_t OFF_DECLEN = OFF_CAPS + (size_t)BSZ*ML;
    const size_t OFF_ALPHA  = OFF_DECLEN + BSZ;
    const size_t OFF_ORDER  = OFF_ALPHA + (size_t)BSZ*TT*NPIX;
    float* out_pred   = out + OFF_PRED;
    float* out_caps   = out + OFF_CAPS;
    float* out_declen = out + OFF_DECLEN;
    float* out_alphas = out + OFF_ALPHA;
    float* out_order  = out + OFF_ORDER;

    static cudaStream_t s2 = nullptr;
    static cudaEvent_t evRoot, evCvt;
    static bool inited = false;
    const int FUSED_SMEM = (2*64*36 + 2*256*36) * 4;   // 92160 B
    const int EA_SMEM = (64*36 + 256*36) * 4;          // 46080 B
    if (!inited) {
        cudaStreamCreateWithFlags(&s2, cudaStreamNonBlocking);
        cudaEventCreateWithFlags(&evRoot, cudaEventDisableTiming);
        cudaEventCreateWithFlags(&evCvt, cudaEventDisableTiming);
        cudaFuncSetAttribute(persistent_kernel, cudaFuncAttributeMaxDynamicSharedMemorySize,
                             FUSED_SMEM);
        cudaFuncSetAttribute(ea_mma_kernel, cudaFuncAttributeMaxDynamicSharedMemorySize,
                             EA_SMEM);
        inited = true;
    }

    size_t tail = (size_t)out_size - OFF_CAPS;
    cudaMemsetAsync(out + OFF_CAPS, 0, tail * sizeof(float));

    // weight converts on s2, overlapped with main prologue on stream 0
    cudaEventRecord(evRoot, 0);
    cudaStreamWaitEvent(s2, evRoot, 0);
    convert_wfc_kernel<<<(VV*64)/256, 256, 0, s2>>>((const float4*)W_fc);
    convert_wihh_kernel<<<(2048*768)/256, 256, 0, s2>>>(W_ih, W_hh);
    convert_wdg_kernel<<<(1024*256)/256, 256, 0, s2>>>(W_dec_attn, W_f_beta);
    cudaEventRecord(evCvt, s2);

    sort_kernel<<<1, 64>>>(cap_len, caps, out_caps, out_declen, out_order);
    convert_emb_kernel<<<dim3(BSZ, ML), 256>>>(emb_table);
    reorder_mean_kernel<<<BSZ, 256>>>(encoder_out);
    ea_mma_kernel<<<dim3(2, 196), 256, EA_SMEM>>>(W_enc_attn, b_enc_attn);
    gemm64_kernel<<<dim3(8, 1), 256>>>(1, W_init_h, b_init_h, 512, 512);
    gemm64_kernel<<<dim3(8, 1), 256>>>(2, W_init_c, b_init_c, 512, 512);
    convert_h0_kernel<<<64, 256>>>();
    dagate_kernel<<<16, 256>>>(W_dec_attn, b_dec_attn, W_f_beta, b_f_beta);

    cudaStreamWaitEvent((cudaStream_t)0, evCvt, 0);
    persistent_kernel<<<GRID, 256, FUSED_SMEM>>>(w_full_attn, b_full_attn,
                                                 b_ih, b_hh, b_dec_attn, b_f_beta,
                                                 b_fc, out_alphas, out_pred);
}

// round 13
// speedup vs baseline: 1.4794x; 1.4794x over previous
#include <cuda_runtime.h>
#include <cuda_bf16.h>
#include <cuda_pipeline.h>
#include <math.h>
#include <stdint.h>

#define BSZ 64
#define NPIX 196
#define ENCD 512
#define DD 512
#define VV 32000
#define TT 50
#define ML 51
#define NSPLIT 8
#define RBLK 64                  // recurrence blocks (barrier group)
#define PBLK 125                 // preds blocks (VV/256)
#define GRID (RBLK + PBLK)       // 189

// ---------------- scratch (static device globals; no runtime alloc) ----------
__device__ float d_enc_s[BSZ*NPIX*ENCD];
__device__ float d_ea[BSZ*NPIX*ENCD];
__device__ float d_mean[BSZ*ENCD];
__device__ float d_hbuf[2][BSZ*DD];
__device__ uint32_t d_hph[2][BSZ*DD/2];      // h bf16-hi pairs
__device__ uint32_t d_hpl[2][BSZ*DD/2];      // h bf16-lo pairs
__device__ float d_c[BSZ*DD];
__device__ uint32_t d_ctxp_h[BSZ*DD/2];      // ctx bf16 packed
__device__ uint32_t d_ctxp_l[BSZ*DD/2];
__device__ float d_da[BSZ*DD];
__device__ float d_gate[BSZ*ENCD];
__device__ float d_gates_p[NSPLIT*BSZ*4*DD];
__device__ uint32_t d_wfh16[(size_t)VV*256];   // W_fc bf16 hi
__device__ uint32_t d_wfl16[(size_t)VV*256];   // W_fc bf16 lo
__device__ uint32_t d_wihh_h[2048*768];        // [Wih|Whh] bf16 hi (k-pairs)
__device__ uint32_t d_wihh_l[2048*768];
__device__ uint32_t d_wdg_h[1024*256];         // [Wd;Wg] bf16 hi
__device__ uint32_t d_wdg_l[1024*256];
__device__ uint32_t d_embp_h[(size_t)ML*BSZ*256];  // sorted emb rows packed
__device__ uint32_t d_embp_l[(size_t)ML*BSZ*256];
__device__ unsigned int d_bar;
__device__ int   d_order[BSZ];
__device__ int   d_declen[BSZ];
__device__ int   d_caps_s[BSZ*ML];
__device__ int   d_nact[TT];

// ---------------- helpers ----------------------------------------------------
__device__ __forceinline__ float warp_sum(float v) {
    #pragma unroll
    for (int o = 16; o > 0; o >>= 1) v += __shfl_down_sync(0xffffffffu, v, o);
    return v;
}
__device__ __forceinline__ float warp_max(float v) {
    #pragma unroll
    for (int o = 16; o > 0; o >>= 1) v = fmaxf(v, __shfl_down_sync(0xffffffffu, v, o));
    return v;
}
__device__ __forceinline__ float sigmoidf_(float x) { return 1.0f / (1.0f + __expf(-x)); }

__device__ __forceinline__ void bfsplit2(float a, float b, uint32_t& hi, uint32_t& lo) {
    __nv_bfloat162 h2 = __floats2bfloat162_rn(a, b);
    float ra = a - __bfloat162float(h2.x);
    float rb = b - __bfloat162float(h2.y);
    __nv_bfloat162 l2 = __floats2bfloat162_rn(ra, rb);
    hi = *(uint32_t*)&h2;
    lo = *(uint32_t*)&l2;
}

__device__ __forceinline__ void mma_bf16(float c[4], uint32_t a0, uint32_t a1,
                                         uint32_t a2, uint32_t a3,
                                         uint32_t b0, uint32_t b1) {
    asm volatile(
        "mma.sync.aligned.m16n8k16.row.col.f32.bf16.bf16.f32 "
        "{%0,%1,%2,%3}, {%4,%5,%6,%7}, {%8,%9}, {%0,%1,%2,%3};\n"
        : "+f"(c[0]), "+f"(c[1]), "+f"(c[2]), "+f"(c[3])
        : "r"(a0), "r"(a1), "r"(a2), "r"(a3), "r"(b0), "r"(b1));
}

// barrier among the first RBLK blocks only: atomic arrive, acquire-poll
__device__ __forceinline__ void rec_bar(int tid) {
    __threadfence();
    __syncthreads();
    if (tid == 0) {
        unsigned t0 = atomicAdd(&d_bar, 1u);
        unsigned target = t0 - (t0 % RBLK) + RBLK;
        unsigned v;
        do {
            asm volatile("ld.global.acquire.gpu.u32 %0, [%1];" : "=r"(v) : "l"(&d_bar));
        } while (v < target);
    }
    __syncthreads();
}

// ---------------- one-time converts -------------------------------------------
__global__ __launch_bounds__(256) void convert_wfc_kernel(const float4* __restrict__ W) {
    size_t gi = (size_t)blockIdx.x*256 + threadIdx.x;
    float4 v0 = W[gi*2];
    float4 v1 = W[gi*2+1];
    uint4 h, l;
    bfsplit2(v0.x, v0.y, h.x, l.x);
    bfsplit2(v0.z, v0.w, h.y, l.y);
    bfsplit2(v1.x, v1.y, h.z, l.z);
    bfsplit2(v1.z, v1.w, h.w, l.w);
    ((uint4*)d_wfh16)[gi] = h;
    ((uint4*)d_wfl16)[gi] = l;
}

__global__ __launch_bounds__(256) void convert_wihh_kernel(
        const float* __restrict__ Wih, const float* __restrict__ Whh) {
    int idx = blockIdx.x*256 + threadIdx.x;
    int n = idx / 768, p = idx % 768;
    int k = p * 2;
    float a, b;
    if (k < 1024) { a = Wih[(size_t)n*1024 + k]; b = Wih[(size_t)n*1024 + k + 1]; }
    else          { a = Whh[(size_t)n*512 + (k-1024)]; b = Whh[(size_t)n*512 + (k-1023)]; }
    uint32_t hi, lo; bfsplit2(a, b, hi, lo);
    d_wihh_h[idx] = hi; d_wihh_l[idx] = lo;
}

__global__ __launch_bounds__(256) void convert_wdg_kernel(
        const float* __restrict__ Wd, const float* __restrict__ Wg) {
    int idx = blockIdx.x*256 + threadIdx.x;
    int n = idx >> 8, p = idx & 255;
    int k = p * 2;
    const float* W = (n < 512) ? (Wd + (size_t)n*512) : (Wg + (size_t)(n-512)*512);
    uint32_t hi, lo; bfsplit2(W[k], W[k+1], hi, lo);
    d_wdg_h[idx] = hi; d_wdg_l[idx] = lo;
}

__global__ __launch_bounds__(256) void convert_emb_kernel(const float* __restrict__ emb) {
    int b = blockIdx.x, tt = blockIdx.y, tid = threadIdx.x;
    int tok = d_caps_s[b*ML + tt];
    const float* src = emb + (size_t)tok*512 + tid*2;
    uint32_t hi, lo; bfsplit2(src[0], src[1], hi, lo);
    size_t o = ((size_t)tt*BSZ + b)*256 + tid;
    d_embp_h[o] = hi; d_embp_l[o] = lo;
}

__global__ __launch_bounds__(256) void convert_h0_kernel() {
    int pid = blockIdx.x*256 + threadIdx.x;
    float a = d_hbuf[0][pid*2];
    float b = d_hbuf[0][pid*2+1];
    uint32_t hi, lo; bfsplit2(a, b, hi, lo);
    d_hph[0][pid] = hi; d_hpl[0][pid] = lo;
}

// ---------------- sort (stable, descending cap_len) ---------------------------
__global__ void sort_kernel(const int* __restrict__ cap_len,
                            const int* __restrict__ caps,
                            float* __restrict__ out_caps,
                            float* __restrict__ out_declen,
                            float* __restrict__ out_order) {
    int i = threadIdx.x;
    int cl = cap_len[i];
    int r = 0;
    for (int j = 0; j < BSZ; j++) {
        int cj = cap_len[j];
        if (cj > cl || (cj == cl && j < i)) r++;
    }
    d_order[r]  = i;
    d_declen[r] = cl - 1;
    __syncthreads();
    out_order[i]  = (float)d_order[i];
    out_declen[i] = (float)d_declen[i];
    int src = d_order[i];
    for (int tt = 0; tt < ML; tt++) {
        int tok = caps[src*ML + tt];
        d_caps_s[i*ML + tt] = tok;
        out_caps[i*ML + tt] = (float)tok;
    }
    if (i < TT) {
        int cnt = 0;
        for (int j = 0; j < BSZ; j++) if (d_declen[j] > i) cnt++;
        d_nact[i] = cnt;
    }
}

// ---------------- reorder encoder + per-batch pixel mean ----------------------
__global__ __launch_bounds__(256) void reorder_mean_kernel(const float* __restrict__ enc) {
    int b = blockIdx.x;
    int tid = threadIdx.x;
    int src = d_order[b];
    const float* Ein = enc + (size_t)src*NPIX*ENCD;
    float* Eo = d_enc_s + (size_t)b*NPIX*ENCD;
    float s0 = 0.f, s1 = 0.f;
    for (int p = 0; p < NPIX; p++) {
        float v0 = Ein[p*ENCD + tid];
        float v1 = Ein[p*ENCD + tid + 256];
        Eo[p*ENCD + tid]       = v0;
        Eo[p*ENCD + tid + 256] = v1;
        s0 += v0; s1 += v1;
    }
    d_mean[b*ENCD + tid]       = s0 * (1.0f/NPIX);
    d_mean[b*ENCD + tid + 256] = s1 * (1.0f/NPIX);
}

// ---------------- small GEMM for h0/c0: C = A @ W^T + bias -------------------
__global__ __launch_bounds__(256) void gemm64_kernel(int sel,
        const float* __restrict__ Wmat, const float* __restrict__ bias,
        int K, int N) {
    const float* Amat = d_mean;
    float*       Cmat = (sel == 1) ? d_hbuf[0] : d_c;
    __shared__ float sA[32][64];
    __shared__ float sW[32][64];
    int tid = threadIdx.x;
    int tx = tid & 15, ty = tid >> 4;
    int m0 = blockIdx.y * 64;
    int n0 = blockIdx.x * 64;
    float acc[4][4] = {};
    for (int k0 = 0; k0 < K; k0 += 32) {
        #pragma unroll
        for (int u = 0; u < 2; u++) {
            int f4i = tid + u*256;
            int m  = f4i >> 3;
            int kk = (f4i & 7) << 2;
            float4 a = *(const float4*)&Amat[(size_t)(m0+m)*K + k0 + kk];
            sA[kk][m] = a.x; sA[kk+1][m] = a.y; sA[kk+2][m] = a.z; sA[kk+3][m] = a.w;
            float4 w = *(const float4*)&Wmat[(size_t)(n0+m)*K + k0 + kk];
            sW[kk][m] = w.x; sW[kk+1][m] = w.y; sW[kk+2][m] = w.z; sW[kk+3][m] = w.w;
        }
        __syncthreads();
        #pragma unroll
        for (int k = 0; k < 32; k++) {
            float4 a = *(const float4*)&sA[k][ty*4];
            float4 w = *(const float4*)&sW[k][tx*4];
            float av[4] = {a.x, a.y, a.z, a.w};
            float wv[4] = {w.x, w.y, w.z, w.w};
            #pragma unroll
            for (int i = 0; i < 4; i++)
                #pragma unroll
                for (int j = 0; j < 4; j++)
                    acc[i][j] += av[i] * wv[j];
        }
        __syncthreads();
    }
    #pragma unroll
    for (int i = 0; i < 4; i++) {
        int m = m0 + ty*4 + i;
        #pragma unroll
        for (int j = 0; j < 4; j++) {
            int n = n0 + tx*4 + j;
            Cmat[(size_t)m*N + n] = acc[i][j] + bias[n];
        }
    }
}

// ---------------- ea = enc_s @ W_enc^T + b via bf16 3-term split mma ----------
__global__ void __launch_bounds__(256, 2) ea_mma_kernel(
        const float* __restrict__ Wenc, const float* __restrict__ bias) {
    extern __shared__ __align__(16) uint32_t sm[];
    uint32_t* Asm = sm;                  // [64][36]
    uint32_t* Wsm = sm + 64*36;          // [256][36]

    int m0 = blockIdx.y * 64;
    int n0 = blockIdx.x * 256;
    int tid = threadIdx.x;
    int lane = tid & 31, wp = tid >> 5;
    int g = lane >> 2, tig = lane & 3;

    float acc[4][4][4];
    #pragma unroll
    for (int a = 0; a < 4; a++)
        #pragma unroll
        for (int b2 = 0; b2 < 4; b2++)
            #pragma unroll
            for (int c2 = 0; c2 < 4; c2++) acc[a][b2][c2] = 0.f;

    for (int kt = 0; kt < 16; kt++) {
        {
            int row = tid >> 2, c = tid & 3;
            const float* src = d_enc_s + (size_t)(m0+row)*512 + kt*32 + c*8;
            float4 v0 = *(const float4*)src;
            float4 v1 = *(const float4*)(src + 4);
            uint4 h, l;
            bfsplit2(v0.x, v0.y, h.x, l.x);
            bfsplit2(v0.z, v0.w, h.y, l.y);
            bfsplit2(v1.x, v1.y, h.z, l.z);
            bfsplit2(v1.z, v1.w, h.w, l.w);
            *(uint4*)&Asm[row*36 + c*4]      = h;
            *(uint4*)&Asm[row*36 + 16 + c*4] = l;
        }
        #pragma unroll
        for (int u = 0; u < 4; u++) {
            int cid = tid + u*256;
            int row = cid >> 2, c = cid & 3;
            const float* src = Wenc + (size_t)(n0+row)*512 + kt*32 + c*8;
            float4 v0 = *(const float4*)src;
            float4 v1 = *(const float4*)(src + 4);
            uint4 h, l;
            bfsplit2(v0.x, v0.y, h.x, l.x);
            bfsplit2(v0.z, v0.w, h.y, l.y);
            bfsplit2(v1.x, v1.y, h.z, l.z);
            bfsplit2(v1.z, v1.w, h.w, l.w);
            *(uint4*)&Wsm[row*36 + c*4]      = h;
            *(uint4*)&Wsm[row*36 + 16 + c*4] = l;
        }
        __syncthreads();
        #pragma unroll
        for (int ks = 0; ks < 2; ks++) {
            int ko = ks*8 + tig;
            uint32_t ah[4][4], al[4][4];
            #pragma unroll
            for (int mf = 0; mf < 4; mf++) {
                int r0 = (mf*16 + g)*36, r1 = (mf*16 + g + 8)*36;
                ah[mf][0] = Asm[r0 + ko];      ah[mf][1] = Asm[r1 + ko];
                ah[mf][2] = Asm[r0 + ko + 4];  ah[mf][3] = Asm[r1 + ko + 4];
                al[mf][0] = Asm[r0 + 16 + ko];     al[mf][1] = Asm[r1 + 16 + ko];
                al[mf][2] = Asm[r0 + 16 + ko + 4]; al[mf][3] = Asm[r1 + 16 + ko + 4];
            }
            #pragma unroll
            for (int nf = 0; nf < 4; nf++) {
                int rw = (wp*32 + nf*8 + g)*36 + ko;
                uint32_t bh0 = Wsm[rw], bh1 = Wsm[rw + 4];
                uint32_t bl0 = Wsm[rw + 16], bl1 = Wsm[rw + 20];
                #pragma unroll
                for (int mf = 0; mf < 4; mf++) {
                    mma_bf16(acc[mf][nf], ah[mf][0], ah[mf][1], ah[mf][2], ah[mf][3], bh0, bh1);
                    mma_bf16(acc[mf][nf], al[mf][0], al[mf][1], al[mf][2], al[mf][3], bh0, bh1);
                    mma_bf16(acc[mf][nf], ah[mf][0], ah[mf][1], ah[mf][2], ah[mf][3], bl0, bl1);
                }
            }
        }
        __syncthreads();
    }

    #pragma unroll
    for (int nf = 0; nf < 4; nf++) {
        int n = n0 + wp*32 + nf*8 + 2*tig;
        float2 bb = *(const float2*)&bias[n];
        #pragma unroll
        for (int mf = 0; mf < 4; mf++) {
            int m1 = m0 + mf*16 + g;
            float2 o1; o1.x = acc[mf][nf][0] + bb.x; o1.y = acc[mf][nf][1] + bb.y;
            *(float2*)&d_ea[(size_t)m1*512 + n] = o1;
            int m2 = m1 + 8;
            float2 o2; o2.x = acc[mf][nf][2] + bb.x; o2.y = acc[mf][nf][3] + bb.y;
            *(float2*)&d_ea[(size_t)m2*512 + n] = o2;
        }
    }
}

// ---------------- standalone dagate (step-0 prologue, SIMT) -------------------
__global__ __launch_bounds__(256) void dagate_kernel(
        const float* __restrict__ Wd, const float* __restrict__ bd,
        const float* __restrict__ Wg, const float* __restrict__ bg) {
    __shared__ float sA[32][64];
    __shared__ float sW[32][64];
    const float* hsrc = d_hbuf[0];
    int tid = threadIdx.x;
    int tx = tid & 15, ty = tid >> 4;
    int n0 = blockIdx.x * 64;
    const float* Wmat = (n0 < 512) ? (Wd + (size_t)n0*512) : (Wg + (size_t)(n0-512)*512);
    float acc[4][4] = {};
    for (int k0 = 0; k0 < 512; k0 += 32) {
        #pragma unroll
        for (int u = 0; u < 2; u++) {
            int f4i = tid + u*256;
            int m  = f4i >> 3;
            int kk = (f4i & 7) << 2;
            float4 a = *(const float4*)&hsrc[(size_t)m*512 + k0 + kk];
            sA[kk][m] = a.x; sA[kk+1][m] = a.y; sA[kk+2][m] = a.z; sA[kk+3][m] = a.w;
            float4 w = *(const float4*)&Wmat[(size_t)m*512 + k0 + kk];
            sW[kk][m] = w.x; sW[kk+1][m] = w.y; sW[kk+2][m] = w.z; sW[kk+3][m] = w.w;
        }
        __syncthreads();
        #pragma unroll
        for (int k = 0; k < 32; k++) {
            float4 a = *(const float4*)&sA[k][ty*4];
            float4 w = *(const float4*)&sW[k][tx*4];
            float av[4] = {a.x, a.y, a.z, a.w};
            float wv[4] = {w.x, w.y, w.z, w.w};
            #pragma unroll
            for (int i = 0; i < 4; i++)
                #pragma unroll
                for (int j = 0; j < 4; j++)
                    acc[i][j] += av[i] * wv[j];
        }
        __syncthreads();
    }
    #pragma unroll
    for (int i = 0; i < 4; i++) {
        int m = ty*4 + i;
        #pragma unroll
        for (int j = 0; j < 4; j++) {
            int n = n0 + tx*4 + j;
            if (n < 512) d_da[m*512 + n] = acc[i][j] + bd[n];
            else         d_gate[m*512 + (n-512)] = sigmoidf_(acc[i][j] + bg[n-512]);
        }
    }
}

// ---------------- preds issue + body -------------------------------------------
__device__ __forceinline__ void preds_issue(uint32_t* Asm, uint32_t* Wsm,
        int stage, int kt, int n0, int tid, const uint4* hph, const uint4* hpl) {
    uint32_t* As = Asm + stage*(64*36);
    uint32_t* Ws = Wsm + stage*(256*36);
    #pragma unroll
    for (int u = 0; u < 2; u++) {
        int cid = tid + u*256;
        int row = cid >> 3, c = cid & 7;
        const uint4* src = ((c < 4) ? hph : hpl) + row*64 + kt*4 + (c & 3);
        uint32_t* dst = As + row*36 + ((c < 4) ? c*4 : 16 + (c - 4)*4);
        __pipeline_memcpy_async(dst, src, 16);
    }
    const uint4* wh = (const uint4*)d_wfh16;
    const uint4* wl = (const uint4*)d_wfl16;
    #pragma unroll
    for (int u = 0; u < 8; u++) {
        int cid = tid + u*256;
        int row = cid >> 3, c = cid & 7;
        const uint4* src = ((c < 4) ? wh : wl) + (size_t)(n0 + row)*64 + kt*4 + (c & 3);
        uint32_t* dst = Ws + row*36 + ((c < 4) ? c*4 : 16 + (c - 4)*4);
        __pipeline_memcpy_async(dst, src, 16);
    }
    __pipeline_commit();
}

__device__ void preds_body(int j, uint32_t* sm, int tid,
                           const float* __restrict__ bfc,
                           float* __restrict__ out_pred, int n0) {
    int nact = d_nact[j];
    int mfmax = (nact + 15) >> 4;
    int hb = (j + 1) & 1;
    uint32_t* Asm = sm;
    uint32_t* Wsm = sm + 2*64*36;

    int lane = tid & 31, wp = tid >> 5;
    int g = lane >> 2, tig = lane & 3;
    const uint4* hph = (const uint4*)d_hph[hb];
    const uint4* hpl = (const uint4*)d_hpl[hb];

    float acc[4][4][4];
    #pragma unroll
    for (int a = 0; a < 4; a++)
        #pragma unroll
        for (int b2 = 0; b2 < 4; b2++)
            #pragma unroll
            for (int c2 = 0; c2 < 4; c2++) acc[a][b2][c2] = 0.f;

    preds_issue(Asm, Wsm, 0, 0, n0, tid, hph, hpl);
    for (int kt = 0; kt < 16; kt++) {
        int stage = kt & 1;
        if (kt < 15) {
            preds_issue(Asm, Wsm, stage ^ 1, kt + 1, n0, tid, hph, hpl);
            __pipeline_wait_prior(1);
        } else {
            __pipeline_wait_prior(0);
        }
        __syncthreads();
        const uint32_t* Ahs = Asm + stage*(64*36);
        const uint32_t* Whs = Wsm + stage*(256*36);
        #pragma unroll
        for (int ks = 0; ks < 2; ks++) {
            int ko = ks*8 + tig;
            uint32_t ah[4][4], al[4][4];
            #pragma unroll
            for (int mf = 0; mf < 4; mf++) {
                if (mf >= mfmax) continue;
                int r0 = (mf*16 + g)*36, r1 = (mf*16 + g + 8)*36;
                ah[mf][0] = Ahs[r0 + ko];      ah[mf][1] = Ahs[r1 + ko];
                ah[mf][2] = Ahs[r0 + ko + 4];  ah[mf][3] = Ahs[r1 + ko + 4];
                al[mf][0] = Ahs[r0 + 16 + ko];     al[mf][1] = Ahs[r1 + 16 + ko];
                al[mf][2] = Ahs[r0 + 16 + ko + 4]; al[mf][3] = Ahs[r1 + 16 + ko + 4];
            }
            #pragma unroll
            for (int nf = 0; nf < 4; nf++) {
                int rw = (wp*32 + nf*8 + g)*36 + ko;
                uint32_t bh0 = Whs[rw], bh1 = Whs[rw + 4];
                uint32_t bl0 = Whs[rw + 16], bl1 = Whs[rw + 20];
                #pragma unroll
                for (int mf = 0; mf < 4; mf++) {
                    if (mf >= mfmax) continue;
                    mma_bf16(acc[mf][nf], ah[mf][0], ah[mf][1], ah[mf][2], ah[mf][3], bh0, bh1);
                    mma_bf16(acc[mf][nf], al[mf][0], al[mf][1], al[mf][2], al[mf][3], bh0, bh1);
                    mma_bf16(acc[mf][nf], ah[mf][0], ah[mf][1], ah[mf][2], ah[mf][3], bl0, bl1);
                }
            }
        }
        __syncthreads();
    }

    size_t tbase = (size_t)j * VV;
    #pragma unroll
    for (int nf = 0; nf < 4; nf++) {
        int n = n0 + wp*32 + nf*8 + 2*tig;
        float2 bb = *(const float2*)&bfc[n];
        #pragma unroll
        for (int mf = 0; mf < 4; mf++) {
            int m1 = mf*16 + g;
            float2 o1;
            o1.x = (m1 < nact) ? acc[mf][nf][0] + bb.x : 0.f;
            o1.y = (m1 < nact) ? acc[mf][nf][1] + bb.y : 0.f;
            *(float2*)&out_pred[(size_t)m1*((size_t)TT*VV) + tbase + n] = o1;
            int m2 = m1 + 8;
            float2 o2;
            o2.x = (m2 < nact) ? acc[mf][nf][2] + bb.x : 0.f;
            o2.y = (m2 < nact) ? acc[mf][nf][3] + bb.y : 0.f;
            *(float2*)&out_pred[(size_t)m2*((size_t)TT*VV) + tbase + n] = o2;
        }
    }
}

// ---------------- phase-B issue: A from packed (emb|ctx|h), W from wihh -------
__device__ __forceinline__ void lstm_issue(uint32_t* Asm, uint32_t* Wsm,
        int stage, int c0, int n0, int tid, int t, int hb) {
    uint32_t* As = Asm + stage*(64*36);
    uint32_t* Ws = Wsm + stage*(256*36);
    const uint4* ah4; const uint4* al4; int off4;
    if (c0 < 512) {
        ah4 = (const uint4*)d_embp_h + (size_t)t*BSZ*64;
        al4 = (const uint4*)d_embp_l + (size_t)t*BSZ*64;
        off4 = c0 >> 3;
    } else if (c0 < 1024) {
        ah4 = (const uint4*)d_ctxp_h;
        al4 = (const uint4*)d_ctxp_l;
        off4 = (c0 - 512) >> 3;
    } else {
        ah4 = (const uint4*)d_hph[hb];
        al4 = (const uint4*)d_hpl[hb];
        off4 = (c0 - 1024) >> 3;
    }
    #pragma unroll
    for (int u = 0; u < 2; u++) {
        int cid = tid + u*256;
        int row = cid >> 3, c = cid & 7;
        const uint4* src = ((c < 4) ? ah4 : al4) + (size_t)row*64 + off4 + (c & 3);
        uint32_t* dst = As + row*36 + ((c < 4) ? c*4 : 16 + (c - 4)*4);
        __pipeline_memcpy_async(dst, src, 16);
    }
    const uint4* wh = (const uint4*)d_wihh_h;
    const uint4* wl = (const uint4*)d_wihh_l;
    int woff4 = c0 >> 3;
    #pragma unroll
    for (int u = 0; u < 8; u++) {
        int cid = tid + u*256;
        int row = cid >> 3, c = cid & 7;
        const uint4* src = ((c < 4) ? wh : wl) + (size_t)(n0 + row)*192 + woff4 + (c & 3);
        uint32_t* dst = Ws + row*36 + ((c < 4) ? c*4 : 16 + (c - 4)*4);
        __pipeline_memcpy_async(dst, src, 16);
    }
    __pipeline_commit();
}

// ---------------- phase-D issue: A = h packed, W = wdg packed (N=64) ----------
__device__ __forceinline__ void dg_issue(uint32_t* Asm, uint32_t* Wsm,
        int stage, int kt, int n0, int tid, int hbw) {
    uint32_t* As = Asm + stage*(64*36);
    uint32_t* Ws = Wsm + stage*(64*36);
    const uint4* ah4 = (const uint4*)d_hph[hbw];
    const uint4* al4 = (const uint4*)d_hpl[hbw];
    #pragma unroll
    for (int u = 0; u < 2; u++) {
        int cid = tid + u*256;
        int row = cid >> 3, c = cid & 7;
        const uint4* src = ((c < 4) ? ah4 : al4) + (size_t)row*64 + kt*4 + (c & 3);
        uint32_t* dst = As + row*36 + ((c < 4) ? c*4 : 16 + (c - 4)*4);
        __pipeline_memcpy_async(dst, src, 16);
    }
    const uint4* wh = (const uint4*)d_wdg_h;
    const uint4* wl = (const uint4*)d_wdg_l;
    #pragma unroll
    for (int u = 0; u < 2; u++) {
        int cid = tid + u*256;
        int row = cid >> 3, c = cid & 7;
        const uint4* src = ((c < 4) ? wh : wl) + (size_t)(n0 + row)*64 + kt*4 + (c & 3);
        uint32_t* dst = Ws + row*36 + ((c < 4) ? c*4 : 16 + (c - 4)*4);
        __pipeline_memcpy_async(dst, src, 16);
    }
    __pipeline_commit();
}

// ============ FUSED: recurrence(t) on blocks 0..63 || preds(t-1) on 64+ =======
__global__ void __launch_bounds__(256, 2) fused_kernel(int t,
        const float* __restrict__ wf, const float* __restrict__ bf_scalar,
        const float* __restrict__ bih, const float* __restrict__ bhh,
        const float* __restrict__ bd, const float* __restrict__ bg,
        const float* __restrict__ bfc,
        float* __restrict__ out_alphas, float* __restrict__ out_pred) {
    extern __shared__ __align__(16) uint32_t smem_u[];
    int bid = blockIdx.x;
    int tid = threadIdx.x;

    if (bid >= RBLK) {                     // ---- preds for step t-1 ----
        if (t >= 1) preds_body(t - 1, smem_u, tid, bfc, out_pred, (bid - RBLK) * 256);
        return;
    }
    if (t >= TT) return;

    int hb  = t & 1;
    int hbw = (t + 1) & 1;

    // ---------------- phase A: attention (blocks 0..63) -----------------------
    if (t < d_declen[bid]) {
        int b = bid;
        int lane = tid & 31, warp = tid >> 5;
        float4* s_da = (float4*)smem_u;
        float4* s_wf = s_da + 128;
        float*  sc   = (float*)(s_wf + 128);
        float*  red  = sc + 200;

        if (tid < 128) {
            s_da[tid] = ((const float4*)d_da)[b*128 + tid];
            s_wf[tid] = ((const float4*)wf)[tid];
        }
        __syncthreads();

        const float4* ea4 = ((const float4*)d_ea) + (size_t)b*NPIX*128;
        float bfull = bf_scalar[0];
        for (int p0 = warp*2; p0 < NPIX; p0 += 16) {
            int p1 = p0 + 1;
            float s0 = 0.f, s1 = 0.f;
            #pragma unroll
            for (int j = 0; j < 4; j++) {
                int k4 = lane + j*32;
                float4 e0 = ea4[p0*128 + k4];
                float4 e1 = ea4[p1*128 + k4];
                float4 da = s_da[k4];
                float4 w  = s_wf[k4];
                s0 += fmaxf(e0.x + da.x, 0.f) * w.x;
                s0 += fmaxf(e0.y + da.y, 0.f) * w.y;
                s0 += fmaxf(e0.z + da.z, 0.f) * w.z;
                s0 += fmaxf(e0.w + da.w, 0.f) * w.w;
                s1 += fmaxf(e1.x + da.x, 0.f) * w.x;
                s1 += fmaxf(e1.y + da.y, 0.f) * w.y;
                s1 += fmaxf(e1.z + da.z, 0.f) * w.z;
                s1 += fmaxf(e1.w + da.w, 0.f) * w.w;
            }
            s0 = warp_sum(s0);
            s1 = warp_sum(s1);
            if (lane == 0) { sc[p0] = s0 + bfull; sc[p1] = s1 + bfull; }
        }
        __syncthreads();

        float v = (tid < NPIX) ? sc[tid] : -1e30f;
        float wm = warp_max(v);
        if (lane == 0) red[warp] = wm;
        __syncthreads();
        if (tid == 0) {
            float mm = red[0];
            #pragma unroll
            for (int i = 1; i < 8; i++) mm = fmaxf(mm, red[i]);
            red[16] = mm;
        }
        __syncthreads();
        float gmax = red[16];
        float e = (tid < NPIX) ? __expf(v - gmax) : 0.f;
        float ws = warp_sum(e);
        if (lane == 0) red[8 + warp] = ws;
        __syncthreads();
        if (tid == 0) {
            float ss = 0.f;
            #pragma unroll
            for (int i = 0; i < 8; i++) ss += red[8 + i];
            red[17] = ss;
        }
        __syncthreads();
        float alpha = e / red[17];
        __syncthreads();
        if (tid < NPIX) {
            sc[tid] = alpha;
            out_alphas[(size_t)b*TT*NPIX + (size_t)t*NPIX + tid] = alpha;
        }
        __syncthreads();

        const float2* encb2 = (const float2*)(d_enc_s + (size_t)b*NPIX*512);
        float sx[16], sy[16];
        #pragma unroll
        for (int u = 0; u < 16; u++) { sx[u] = 0.f; sy[u] = 0.f; }
        #pragma unroll 2
        for (int p0 = 0; p0 < 192; p0 += 16) {
            #pragma unroll
            for (int u = 0; u < 16; u++) {
                float2 vv = encb2[(p0+u)*256 + tid];
                float al = sc[p0+u];
                sx[u] += al * vv.x;
                sy[u] += al * vv.y;
            }
        }
        #pragma unroll
        for (int u = 0; u < 4; u++) {
            float2 vv = encb2[(192+u)*256 + tid];
            float al = sc[192+u];
            sx[u] += al * vv.x;
            sy[u] += al * vv.y;
        }
        float X = 0.f, Y = 0.f;
        #pragma unroll
        for (int u = 0; u < 16; u++) { X += sx[u]; Y += sy[u]; }
        float2 g2 = ((const float2*)d_gate)[b*256 + tid];
        float cx = X * g2.x, cy = Y * g2.y;
        uint32_t chi, clo; bfsplit2(cx, cy, chi, clo);
        d_ctxp_h[b*256 + tid] = chi;
        d_ctxp_l[b*256 + tid] = clo;
    }
    rec_bar(tid);

    // ---------------- phase B: LSTM gate GEMM via mma (64 blocks) -------------
    {
        uint32_t* Asm = smem_u;
        uint32_t* Wsm = smem_u + 2*64*36;
        int n0 = (bid & 7) * 256;
        int ksplit = bid >> 3;
        int kbase = ksplit * 192;
        int lane = tid & 31, wp = tid >> 5;
        int g = lane >> 2, tig = lane & 3;

        float acc[4][4][4];
        #pragma unroll
        for (int a = 0; a < 4; a++)
            #pragma unroll
            for (int b2 = 0; b2 < 4; b2++)
                #pragma unroll
                for (int c2 = 0; c2 < 4; c2++) acc[a][b2][c2] = 0.f;

        lstm_issue(Asm, Wsm, 0, kbase, n0, tid, t, hb);
        for (int kt = 0; kt < 6; kt++) {
            int stage = kt & 1;
            if (kt < 5) {
                lstm_issue(Asm, Wsm, stage ^ 1, kbase + (kt+1)*32, n0, tid, t, hb);
                __pipeline_wait_prior(1);
            } else {
                __pipeline_wait_prior(0);
            }
            __syncthreads();
            const uint32_t* Ahs = Asm + stage*(64*36);
            const uint32_t* Whs = Wsm + stage*(256*36);
            #pragma unroll
            for (int ks = 0; ks < 2; ks++) {
                int ko = ks*8 + tig;
                uint32_t ah[4][4], al[4][4];
                #pragma unroll
                for (int mf = 0; mf < 4; mf++) {
                    int r0 = (mf*16 + g)*36, r1 = (mf*16 + g + 8)*36;
                    ah[mf][0] = Ahs[r0 + ko];      ah[mf][1] = Ahs[r1 + ko];
                    ah[mf][2] = Ahs[r0 + ko + 4];  ah[mf][3] = Ahs[r1 + ko + 4];
                    al[mf][0] = Ahs[r0 + 16 + ko];     al[mf][1] = Ahs[r1 + 16 + ko];
                    al[mf][2] = Ahs[r0 + 16 + ko + 4]; al[mf][3] = Ahs[r1 + 16 + ko + 4];
                }
                #pragma unroll
                for (int nf = 0; nf < 4; nf++) {
                    int rw = (wp*32 + nf*8 + g)*36 + ko;
                    uint32_t bh0 = Whs[rw], bh1 = Whs[rw + 4];
                    uint32_t bl0 = Whs[rw + 16], bl1 = Whs[rw + 20];
                    #pragma unroll
                    for (int mf = 0; mf < 4; mf++) {
                        mma_bf16(acc[mf][nf], ah[mf][0], ah[mf][1], ah[mf][2], ah[mf][3], bh0, bh1);
                        mma_bf16(acc[mf][nf], al[mf][0], al[mf][1], al[mf][2], al[mf][3], bh0, bh1);
                        mma_bf16(acc[mf][nf], ah[mf][0], ah[mf][1], ah[mf][2], ah[mf][3], bl0, bl1);
                    }
                }
            }
            __syncthreads();
        }

        float* gp = d_gates_p + (size_t)ksplit * (BSZ*2048);
        #pragma unroll
        for (int nf = 0; nf < 4; nf++) {
            int n = n0 + wp*32 + nf*8 + 2*tig;
            #pragma unroll
            for (int mf = 0; mf < 4; mf++) {
                int m1 = mf*16 + g;
                float2 o1; o1.x = acc[mf][nf][0]; o1.y = acc[mf][nf][1];
                *(float2*)&gp[m1*2048 + n] = o1;
                int m2 = m1 + 8;
                float2 o2; o2.x = acc[mf][nf][2]; o2.y = acc[mf][nf][3];
                *(float2*)&gp[m2*2048 + n] = o2;
            }
        }
    }
    rec_bar(tid);

    // ---------------- phase C: LSTM apply + bf16 pack (blocks 0..15) ----------
    if (bid < 16) {
        int gid = bid*256 + tid;
        int idx0 = gid*8;
        int b = idx0 >> 9;
        int f0 = (idx0 & 511) >> 2;
        float acc[4][8];
        #pragma unroll
        for (int q = 0; q < 4; q++)
            #pragma unroll
            for (int e = 0; e < 8; e++) acc[q][e] = 0.f;
        #pragma unroll
        for (int s = 0; s < NSPLIT; s++) {
            const float4* g4 = (const float4*)(d_gates_p + (size_t)s*(BSZ*2048) + b*2048);
            #pragma unroll
            for (int q = 0; q < 4; q++) {
                float4 v0 = g4[q*128 + f0];
                float4 v1 = g4[q*128 + f0 + 1];
                acc[q][0] += v0.x; acc[q][1] += v0.y; acc[q][2] += v0.z; acc[q][3] += v0.w;
                acc[q][4] += v1.x; acc[q][5] += v1.y; acc[q][6] += v1.z; acc[q][7] += v1.w;
            }
        }
        const float4* bi4 = (const float4*)bih;
        const float4* bh4 = (const float4*)bhh;
        #pragma unroll
        for (int q = 0; q < 4; q++) {
            float4 u0 = bi4[q*128 + f0], u1 = bi4[q*128 + f0 + 1];
            float4 w0 = bh4[q*128 + f0], w1 = bh4[q*128 + f0 + 1];
            acc[q][0] += u0.x + w0.x; acc[q][1] += u0.y + w0.y;
            acc[q][2] += u0.z + w0.z; acc[q][3] += u0.w + w0.w;
            acc[q][4] += u1.x + w1.x; acc[q][5] += u1.y + w1.y;
            acc[q][6] += u1.z + w1.z; acc[q][7] += u1.w + w1.w;
        }
        float hv[8];
        #pragma unroll
        for (int e = 0; e < 8; e++) {
            float ig = sigmoidf_(acc[0][e]);
            float fg = sigmoidf_(acc[1][e]);
            float g2 = tanhf(acc[2][e]);
            float og = sigmoidf_(acc[3][e]);
            float c  = fg * d_c[idx0 + e] + ig * g2;
            float h  = og * tanhf(c);
            d_c[idx0 + e] = c;
            hv[e] = h;
        }
        uint4 ph, pl;
        bfsplit2(hv[0], hv[1], ph.x, pl.x);
        bfsplit2(hv[2], hv[3], ph.y, pl.y);
        bfsplit2(hv[4], hv[5], ph.z, pl.z);
        bfsplit2(hv[6], hv[7], ph.w, pl.w);
        ((uint4*)d_hph[hbw])[gid] = ph;
        ((uint4*)d_hpl[hbw])[gid] = pl;
    }
    rec_bar(tid);

    // ---------------- phase D: dagate via mma (blocks 0..15, N=64) ------------
    if (bid < 16) {
        uint32_t* Asm = smem_u;
        uint32_t* Wsm = smem_u + 2*64*36;
        int n0 = bid * 64;
        int lane = tid & 31, wp = tid >> 5;
        int g = lane >> 2, tig = lane & 3;

        float acc[4][4];
        #pragma unroll
        for (int a = 0; a < 4; a++)
            #pragma unroll
            for (int c2 = 0; c2 < 4; c2++) acc[a][c2] = 0.f;

        dg_issue(Asm, Wsm, 0, 0, n0, tid, hbw);
        for (int kt = 0; kt < 16; kt++) {
            int stage = kt & 1;
            if (kt < 15) {
                dg_issue(Asm, Wsm, stage ^ 1, kt + 1, n0, tid, hbw);
                __pipeline_wait_prior(1);
            } else {
                __pipeline_wait_prior(0);
            }
            __syncthreads();
            const uint32_t* Ahs = Asm + stage*(64*36);
            const uint32_t* Whs = Wsm + stage*(64*36);
            #pragma unroll
            for (int ks = 0; ks < 2; ks++) {
                int ko = ks*8 + tig;
                int rw = (wp*8 + g)*36 + ko;
                uint32_t bh0 = Whs[rw], bh1 = Whs[rw + 4];
                uint32_t bl0 = Whs[rw + 16], bl1 = Whs[rw + 20];
                #pragma unroll
                for (int mf = 0; mf < 4; mf++) {
                    int r0 = (mf*16 + g)*36, r1 = (mf*16 + g + 8)*36;
                    uint32_t a0 = Ahs[r0 + ko],      a1 = Ahs[r1 + ko];
                    uint32_t a2 = Ahs[r0 + ko + 4],  a3 = Ahs[r1 + ko + 4];
                    uint32_t l0 = Ahs[r0 + 16 + ko],     l1 = Ahs[r1 + 16 + ko];
                    uint32_t l2 = Ahs[r0 + 16 + ko + 4], l3 = Ahs[r1 + 16 + ko + 4];
                    mma_bf16(acc[mf], a0, a1, a2, a3, bh0, bh1);
                    mma_bf16(acc[mf], l0, l1, l2, l3, bh0, bh1);
                    mma_bf16(acc[mf], a0, a1, a2, a3, bl0, bl1);
                }
            }
            __syncthreads();
        }

        int n = n0 + wp*8 + 2*tig;
        #pragma unroll
        for (int mf = 0; mf < 4; mf++) {
            int m1 = mf*16 + g;
            int m2 = m1 + 8;
            if (n < 512) {
                float2 bb = *(const float2*)&bd[n];
                float2 o1; o1.x = acc[mf][0] + bb.x; o1.y = acc[mf][1] + bb.y;
                *(float2*)&d_da[m1*512 + n] = o1;
                float2 o2; o2.x = acc[mf][2] + bb.x; o2.y = acc[mf][3] + bb.y;
                *(float2*)&d_da[m2*512 + n] = o2;
            } else {
                int ng = n - 512;
                float2 bb = *(const float2*)&bg[ng];
                float2 o1; o1.x = sigmoidf_(acc[mf][0] + bb.x); o1.y = sigmoidf_(acc[mf][1] + bb.y);
                *(float2*)&d_gate[m1*512 + ng] = o1;
                float2 o2; o2.x = sigmoidf_(acc[mf][2] + bb.x); o2.y = sigmoidf_(acc[mf][3] + bb.y);
                *(float2*)&d_gate[m2*512 + ng] = o2;
            }
        }
    }
}

// ---------------- launch ------------------------------------------------------
extern "C" void kernel_launch(void* const* d_in, const int* in_sizes, int n_in,
                              void* d_out, int out_size) {
    const float* encoder_out = (const float*)d_in[0];
    const int*   caps        = (const int*)  d_in[1];
    const int*   cap_len     = (const int*)  d_in[2];
    const float* W_enc_attn  = (const float*)d_in[3];
    const float* b_enc_attn  = (const float*)d_in[4];
    const float* W_dec_attn  = (const float*)d_in[5];
    const float* b_dec_attn  = (const float*)d_in[6];
    const float* w_full_attn = (const float*)d_in[7];
    const float* b_full_attn = (const float*)d_in[8];
    const float* emb_table   = (const float*)d_in[9];
    const float* W_ih        = (const float*)d_in[10];
    const float* W_hh        = (const float*)d_in[11];
    const float* b_ih        = (const float*)d_in[12];
    const float* b_hh        = (const float*)d_in[13];
    const float* W_init_h    = (const float*)d_in[14];
    const float* b_init_h    = (const float*)d_in[15];
    const float* W_init_c    = (const float*)d_in[16];
    const float* b_init_c    = (const float*)d_in[17];
    const float* W_f_beta    = (const float*)d_in[18];
    const float* b_f_beta    = (const float*)d_in[19];
    const float* W_fc        = (const float*)d_in[20];
    const float* b_fc        = (const float*)d_in[21];

    float* out = (float*)d_out;
    const size_t OFF_PRED   = 0;
    const size_t OFF_CAPS   = OFF_PRED + (size_t)BSZ*TT*VV;
    const size_t OFF_DECLEN = OFF_CAPS + (size_t)BSZ*ML;
    const size_t OFF_ALPHA  = OFF_DECLEN + BSZ;
    const size_t OFF_ORDER  = OFF_ALPHA + (size_t)BSZ*TT*NPIX;
    float* out_pred   = out + OFF_PRED;
    float* out_caps   = out + OFF_CAPS;
    float* out_declen = out + OFF_DECLEN;
    float* out_alphas = out + OFF_ALPHA;
    float* out_order  = out + OFF_ORDER;

    static cudaStream_t s2 = nullptr;
    static cudaEvent_t evRoot, evCvt;
    static bool inited = false;
    const int FUSED_SMEM = (2*64*36 + 2*256*36) * 4;   // 92160 B
    const int EA_SMEM = (64*36 + 256*36) * 4;          // 46080 B
    if (!inited) {
        cudaStreamCreateWithFlags(&s2, cudaStreamNonBlocking);
        cudaEventCreateWithFlags(&evRoot, cudaEventDisableTiming);
        cudaEventCreateWithFlags(&evCvt, cudaEventDisableTiming);
        cudaFuncSetAttribute(fused_kernel, cudaFuncAttributeMaxDynamicSharedMemorySize,
                             FUSED_SMEM);
        cudaFuncSetAttribute(ea_mma_kernel, cudaFuncAttributeMaxDynamicSharedMemorySize,
                             EA_SMEM);
        inited = true;
    }

    size_t tail = (size_t)out_size - OFF_CAPS;
    cudaMemsetAsync(out + OFF_CAPS, 0, tail * sizeof(float));

    // weight converts on s2, overlapped with main prologue on stream 0
    cudaEventRecord(evRoot, 0);
    cudaStreamWaitEvent(s2, evRoot, 0);
    convert_wfc_kernel<<<(VV*64)/256, 256, 0, s2>>>((const float4*)W_fc);
    convert_wihh_kernel<<<(2048*768)/256, 256, 0, s2>>>(W_ih, W_hh);
    convert_wdg_kernel<<<(1024*256)/256, 256, 0, s2>>>(W_dec_attn, W_f_beta);
    cudaEventRecord(evCvt, s2);

    sort_kernel<<<1, 64>>>(cap_len, caps, out_caps, out_declen, out_order);
    convert_emb_kernel<<<dim3(BSZ, ML), 256>>>(emb_table);
    reorder_mean_kernel<<<BSZ, 256>>>(encoder_out);
    ea_mma_kernel<<<dim3(2, 196), 256, EA_SMEM>>>(W_enc_attn, b_enc_attn);
    gemm64_kernel<<<dim3(8, 1), 256>>>(1, W_init_h, b_init_h, 512, 512);
    gemm64_kernel<<<dim3(8, 1), 256>>>(2, W_init_c, b_init_c, 512, 512);
    convert_h0_kernel<<<64, 256>>>();
    dagate_kernel<<<16, 256>>>(W_dec_attn, b_dec_attn, W_f_beta, b_f_beta);

    cudaStreamWaitEvent((cudaStream_t)0, evCvt, 0);

    for (int t = 0; t <= TT; t++) {
        fused_kernel<<<GRID, 256, FUSED_SMEM>>>(t, w_full_attn, b_full_attn,
                                                b_ih, b_hh, b_dec_attn, b_f_beta,
                                                b_fc, out_alphas, out_pred);
    }
}

// round 14
// speedup vs baseline: 1.4885x; 1.0062x over previous
#include <cuda_runtime.h>
#include <cuda_bf16.h>
#include <cuda_pipeline.h>
#include <math.h>
#include <stdint.h>

#define BSZ 64
#define NPIX 196
#define ENCD 512
#define DD 512
#define VV 32000
#define TT 50
#define ML 51
#define NSPLIT 8
#define RBLK 64                  // recurrence blocks (barrier group)
#define NTILE 128                // preds n-tile width
#define PBLK (VV/NTILE)          // 250 preds blocks
#define GRID (RBLK + PBLK)       // 314

// ---------------- scratch (static device globals; no runtime alloc) ----------
__device__ float d_enc_s[BSZ*NPIX*ENCD];
__device__ float d_ea[BSZ*NPIX*ENCD];
__device__ float d_mean[BSZ*ENCD];
__device__ float d_hbuf[2][BSZ*DD];
__device__ uint32_t d_hph[2][BSZ*DD/2];      // h bf16-hi pairs
__device__ uint32_t d_hpl[2][BSZ*DD/2];      // h bf16-lo pairs
__device__ float d_c[BSZ*DD];
__device__ uint32_t d_ctxp_h[BSZ*DD/2];      // ctx bf16 packed
__device__ uint32_t d_ctxp_l[BSZ*DD/2];
__device__ float d_da[BSZ*DD];
__device__ float d_gate[BSZ*ENCD];
__device__ float d_gates_p[NSPLIT*BSZ*4*DD];
__device__ uint32_t d_wfh16[(size_t)VV*256];   // W_fc bf16 hi
__device__ uint32_t d_wfl16[(size_t)VV*256];   // W_fc bf16 lo
__device__ uint32_t d_wihh_h[2048*768];        // [Wih|Whh] bf16 hi (k-pairs)
__device__ uint32_t d_wihh_l[2048*768];
__device__ uint32_t d_wdg_h[1024*256];         // [Wd;Wg] bf16 hi
__device__ uint32_t d_wdg_l[1024*256];
__device__ uint32_t d_embp_h[(size_t)ML*BSZ*256];  // sorted emb rows packed
__device__ uint32_t d_embp_l[(size_t)ML*BSZ*256];
__device__ unsigned int d_bar;
__device__ int   d_order[BSZ];
__device__ int   d_declen[BSZ];
__device__ int   d_caps_s[BSZ*ML];
__device__ int   d_nact[TT];

// ---------------- helpers ----------------------------------------------------
__device__ __forceinline__ float warp_sum(float v) {
    #pragma unroll
    for (int o = 16; o > 0; o >>= 1) v += __shfl_down_sync(0xffffffffu, v, o);
    return v;
}
__device__ __forceinline__ float warp_max(float v) {
    #pragma unroll
    for (int o = 16; o > 0; o >>= 1) v = fmaxf(v, __shfl_down_sync(0xffffffffu, v, o));
    return v;
}
__device__ __forceinline__ float sigmoidf_(float x) { return 1.0f / (1.0f + __expf(-x)); }

__device__ __forceinline__ void bfsplit2(float a, float b, uint32_t& hi, uint32_t& lo) {
    __nv_bfloat162 h2 = __floats2bfloat162_rn(a, b);
    float ra = a - __bfloat162float(h2.x);
    float rb = b - __bfloat162float(h2.y);
    __nv_bfloat162 l2 = __floats2bfloat162_rn(ra, rb);
    hi = *(uint32_t*)&h2;
    lo = *(uint32_t*)&l2;
}

__device__ __forceinline__ void mma_bf16(float c[4], uint32_t a0, uint32_t a1,
                                         uint32_t a2, uint32_t a3,
                                         uint32_t b0, uint32_t b1) {
    asm volatile(
        "mma.sync.aligned.m16n8k16.row.col.f32.bf16.bf16.f32 "
        "{%0,%1,%2,%3}, {%4,%5,%6,%7}, {%8,%9}, {%0,%1,%2,%3};\n"
        : "+f"(c[0]), "+f"(c[1]), "+f"(c[2]), "+f"(c[3])
        : "r"(a0), "r"(a1), "r"(a2), "r"(a3), "r"(b0), "r"(b1));
}

// barrier among the first RBLK blocks only: atomic arrive, acquire-poll
__device__ __forceinline__ void rec_bar(int tid) {
    __threadfence();
    __syncthreads();
    if (tid == 0) {
        unsigned t0 = atomicAdd(&d_bar, 1u);
        unsigned target = t0 - (t0 % RBLK) + RBLK;
        unsigned v;
        do {
            asm volatile("ld.global.acquire.gpu.u32 %0, [%1];" : "=r"(v) : "l"(&d_bar));
        } while (v < target);
    }
    __syncthreads();
}

// ---------------- one-time converts -------------------------------------------
__global__ __launch_bounds__(256) void convert_wfc_kernel(const float4* __restrict__ W) {
    size_t gi = (size_t)blockIdx.x*256 + threadIdx.x;
    float4 v0 = W[gi*2];
    float4 v1 = W[gi*2+1];
    uint4 h, l;
    bfsplit2(v0.x, v0.y, h.x, l.x);
    bfsplit2(v0.z, v0.w, h.y, l.y);
    bfsplit2(v1.x, v1.y, h.z, l.z);
    bfsplit2(v1.z, v1.w, h.w, l.w);
    ((uint4*)d_wfh16)[gi] = h;
    ((uint4*)d_wfl16)[gi] = l;
}

__global__ __launch_bounds__(256) void convert_wihh_kernel(
        const float* __restrict__ Wih, const float* __restrict__ Whh) {
    int idx = blockIdx.x*256 + threadIdx.x;
    int n = idx / 768, p = idx % 768;
    int k = p * 2;
    float a, b;
    if (k < 1024) { a = Wih[(size_t)n*1024 + k]; b = Wih[(size_t)n*1024 + k + 1]; }
    else          { a = Whh[(size_t)n*512 + (k-1024)]; b = Whh[(size_t)n*512 + (k-1023)]; }
    uint32_t hi, lo; bfsplit2(a, b, hi, lo);
    d_wihh_h[idx] = hi; d_wihh_l[idx] = lo;
}

__global__ __launch_bounds__(256) void convert_wdg_kernel(
        const float* __restrict__ Wd, const float* __restrict__ Wg) {
    int idx = blockIdx.x*256 + threadIdx.x;
    int n = idx >> 8, p = idx & 255;
    int k = p * 2;
    const float* W = (n < 512) ? (Wd + (size_t)n*512) : (Wg + (size_t)(n-512)*512);
    uint32_t hi, lo; bfsplit2(W[k], W[k+1], hi, lo);
    d_wdg_h[idx] = hi; d_wdg_l[idx] = lo;
}

__global__ __launch_bounds__(256) void convert_emb_kernel(const float* __restrict__ emb) {
    int b = blockIdx.x, tt = blockIdx.y, tid = threadIdx.x;
    int tok = d_caps_s[b*ML + tt];
    const float* src = emb + (size_t)tok*512 + tid*2;
    uint32_t hi, lo; bfsplit2(src[0], src[1], hi, lo);
    size_t o = ((size_t)tt*BSZ + b)*256 + tid;
    d_embp_h[o] = hi; d_embp_l[o] = lo;
}

__global__ __launch_bounds__(256) void convert_h0_kernel() {
    int pid = blockIdx.x*256 + threadIdx.x;
    float a = d_hbuf[0][pid*2];
    float b = d_hbuf[0][pid*2+1];
    uint32_t hi, lo; bfsplit2(a, b, hi, lo);
    d_hph[0][pid] = hi; d_hpl[0][pid] = lo;
}

// ---------------- sort (stable, descending cap_len) ---------------------------
__global__ void sort_kernel(const int* __restrict__ cap_len,
                            const int* __restrict__ caps,
                            float* __restrict__ out_caps,
                            float* __restrict__ out_declen,
                            float* __restrict__ out_order) {
    int i = threadIdx.x;
    int cl = cap_len[i];
    int r = 0;
    for (int j = 0; j < BSZ; j++) {
        int cj = cap_len[j];
        if (cj > cl || (cj == cl && j < i)) r++;
    }
    d_order[r]  = i;
    d_declen[r] = cl - 1;
    __syncthreads();
    out_order[i]  = (float)d_order[i];
    out_declen[i] = (float)d_declen[i];
    int src = d_order[i];
    for (int tt = 0; tt < ML; tt++) {
        int tok = caps[src*ML + tt];
        d_caps_s[i*ML + tt] = tok;
        out_caps[i*ML + tt] = (float)tok;
    }
    if (i < TT) {
        int cnt = 0;
        for (int j = 0; j < BSZ; j++) if (d_declen[j] > i) cnt++;
        d_nact[i] = cnt;
    }
}

// ---------------- reorder encoder + per-batch pixel mean ----------------------
__global__ __launch_bounds__(256) void reorder_mean_kernel(const float* __restrict__ enc) {
    int b = blockIdx.x;
    int tid = threadIdx.x;
    int src = d_order[b];
    const float* Ein = enc + (size_t)src*NPIX*ENCD;
    float* Eo = d_enc_s + (size_t)b*NPIX*ENCD;
    float s0 = 0.f, s1 = 0.f;
    for (int p = 0; p < NPIX; p++) {
        float v0 = Ein[p*ENCD + tid];
        float v1 = Ein[p*ENCD + tid + 256];
        Eo[p*ENCD + tid]       = v0;
        Eo[p*ENCD + tid + 256] = v1;
        s0 += v0; s1 += v1;
    }
    d_mean[b*ENCD + tid]       = s0 * (1.0f/NPIX);
    d_mean[b*ENCD + tid + 256] = s1 * (1.0f/NPIX);
}

// ---------------- small GEMM for h0/c0: C = A @ W^T + bias -------------------
__global__ __launch_bounds__(256) void gemm64_kernel(int sel,
        const float* __restrict__ Wmat, const float* __restrict__ bias,
        int K, int N) {
    const float* Amat = d_mean;
    float*       Cmat = (sel == 1) ? d_hbuf[0] : d_c;
    __shared__ float sA[32][64];
    __shared__ float sW[32][64];
    int tid = threadIdx.x;
    int tx = tid & 15, ty = tid >> 4;
    int m0 = blockIdx.y * 64;
    int n0 = blockIdx.x * 64;
    float acc[4][4] = {};
    for (int k0 = 0; k0 < K; k0 += 32) {
        #pragma unroll
        for (int u = 0; u < 2; u++) {
            int f4i = tid + u*256;
            int m  = f4i >> 3;
            int kk = (f4i & 7) << 2;
            float4 a = *(const float4*)&Amat[(size_t)(m0+m)*K + k0 + kk];
            sA[kk][m] = a.x; sA[kk+1][m] = a.y; sA[kk+2][m] = a.z; sA[kk+3][m] = a.w;
            float4 w = *(const float4*)&Wmat[(size_t)(n0+m)*K + k0 + kk];
            sW[kk][m] = w.x; sW[kk+1][m] = w.y; sW[kk+2][m] = w.z; sW[kk+3][m] = w.w;
        }
        __syncthreads();
        #pragma unroll
        for (int k = 0; k < 32; k++) {
            float4 a = *(const float4*)&sA[k][ty*4];
            float4 w = *(const float4*)&sW[k][tx*4];
            float av[4] = {a.x, a.y, a.z, a.w};
            float wv[4] = {w.x, w.y, w.z, w.w};
            #pragma unroll
            for (int i = 0; i < 4; i++)
                #pragma unroll
                for (int j = 0; j < 4; j++)
                    acc[i][j] += av[i] * wv[j];
        }
        __syncthreads();
    }
    #pragma unroll
    for (int i = 0; i < 4; i++) {
        int m = m0 + ty*4 + i;
        #pragma unroll
        for (int j = 0; j < 4; j++) {
            int n = n0 + tx*4 + j;
            Cmat[(size_t)m*N + n] = acc[i][j] + bias[n];
        }
    }
}

// ---------------- ea = enc_s @ W_enc^T + b via bf16 3-term split mma ----------
__global__ void __launch_bounds__(256, 2) ea_mma_kernel(
        const float* __restrict__ Wenc, const float* __restrict__ bias) {
    extern __shared__ __align__(16) uint32_t sm[];
    uint32_t* Asm = sm;                  // [64][36]
    uint32_t* Wsm = sm + 64*36;          // [256][36]

    int m0 = blockIdx.y * 64;
    int n0 = blockIdx.x * 256;
    int tid = threadIdx.x;
    int lane = tid & 31, wp = tid >> 5;
    int g = lane >> 2, tig = lane & 3;

    float acc[4][4][4];
    #pragma unroll
    for (int a = 0; a < 4; a++)
        #pragma unroll
        for (int b2 = 0; b2 < 4; b2++)
            #pragma unroll
            for (int c2 = 0; c2 < 4; c2++) acc[a][b2][c2] = 0.f;

    for (int kt = 0; kt < 16; kt++) {
        {
            int row = tid >> 2, c = tid & 3;
            const float* src = d_enc_s + (size_t)(m0+row)*512 + kt*32 + c*8;
            float4 v0 = *(const float4*)src;
            float4 v1 = *(const float4*)(src + 4);
            uint4 h, l;
            bfsplit2(v0.x, v0.y, h.x, l.x);
            bfsplit2(v0.z, v0.w, h.y, l.y);
            bfsplit2(v1.x, v1.y, h.z, l.z);
            bfsplit2(v1.z, v1.w, h.w, l.w);
            *(uint4*)&Asm[row*36 + c*4]      = h;
            *(uint4*)&Asm[row*36 + 16 + c*4] = l;
        }
        #pragma unroll
        for (int u = 0; u < 4; u++) {
            int cid = tid + u*256;
            int row = cid >> 2, c = cid & 3;
            const float* src = Wenc + (size_t)(n0+row)*512 + kt*32 + c*8;
            float4 v0 = *(const float4*)src;
            float4 v1 = *(const float4*)(src + 4);
            uint4 h, l;
            bfsplit2(v0.x, v0.y, h.x, l.x);
            bfsplit2(v0.z, v0.w, h.y, l.y);
            bfsplit2(v1.x, v1.y, h.z, l.z);
            bfsplit2(v1.z, v1.w, h.w, l.w);
            *(uint4*)&Wsm[row*36 + c*4]      = h;
            *(uint4*)&Wsm[row*36 + 16 + c*4] = l;
        }
        __syncthreads();
        #pragma unroll
        for (int ks = 0; ks < 2; ks++) {
            int ko = ks*8 + tig;
            uint32_t ah[4][4], al[4][4];
            #pragma unroll
            for (int mf = 0; mf < 4; mf++) {
                int r0 = (mf*16 + g)*36, r1 = (mf*16 + g + 8)*36;
                ah[mf][0] = Asm[r0 + ko];      ah[mf][1] = Asm[r1 + ko];
                ah[mf][2] = Asm[r0 + ko + 4];  ah[mf][3] = Asm[r1 + ko + 4];
                al[mf][0] = Asm[r0 + 16 + ko];     al[mf][1] = Asm[r1 + 16 + ko];
                al[mf][2] = Asm[r0 + 16 + ko + 4]; al[mf][3] = Asm[r1 + 16 + ko + 4];
            }
            #pragma unroll
            for (int nf = 0; nf < 4; nf++) {
                int rw = (wp*32 + nf*8 + g)*36 + ko;
                uint32_t bh0 = Wsm[rw], bh1 = Wsm[rw + 4];
                uint32_t bl0 = Wsm[rw + 16], bl1 = Wsm[rw + 20];
                #pragma unroll
                for (int mf = 0; mf < 4; mf++) {
                    mma_bf16(acc[mf][nf], ah[mf][0], ah[mf][1], ah[mf][2], ah[mf][3], bh0, bh1);
                    mma_bf16(acc[mf][nf], al[mf][0], al[mf][1], al[mf][2], al[mf][3], bh0, bh1);
                    mma_bf16(acc[mf][nf], ah[mf][0], ah[mf][1], ah[mf][2], ah[mf][3], bl0, bl1);
                }
            }
        }
        __syncthreads();
    }

    #pragma unroll
    for (int nf = 0; nf < 4; nf++) {
        int n = n0 + wp*32 + nf*8 + 2*tig;
        float2 bb = *(const float2*)&bias[n];
        #pragma unroll
        for (int mf = 0; mf < 4; mf++) {
            int m1 = m0 + mf*16 + g;
            float2 o1; o1.x = acc[mf][nf][0] + bb.x; o1.y = acc[mf][nf][1] + bb.y;
            *(float2*)&d_ea[(size_t)m1*512 + n] = o1;
            int m2 = m1 + 8;
            float2 o2; o2.x = acc[mf][nf][2] + bb.x; o2.y = acc[mf][nf][3] + bb.y;
            *(float2*)&d_ea[(size_t)m2*512 + n] = o2;
        }
    }
}

// ---------------- standalone dagate (step-0 prologue, SIMT) -------------------
__global__ __launch_bounds__(256) void dagate_kernel(
        const float* __restrict__ Wd, const float* __restrict__ bd,
        const float* __restrict__ Wg, const float* __restrict__ bg) {
    __shared__ float sA[32][64];
    __shared__ float sW[32][64];
    const float* hsrc = d_hbuf[0];
    int tid = threadIdx.x;
    int tx = tid & 15, ty = tid >> 4;
    int n0 = blockIdx.x * 64;
    const float* Wmat = (n0 < 512) ? (Wd + (size_t)n0*512) : (Wg + (size_t)(n0-512)*512);
    float acc[4][4] = {};
    for (int k0 = 0; k0 < 512; k0 += 32) {
        #pragma unroll
        for (int u = 0; u < 2; u++) {
            int f4i = tid + u*256;
            int m  = f4i >> 3;
            int kk = (f4i & 7) << 2;
            float4 a = *(const float4*)&hsrc[(size_t)m*512 + k0 + kk];
            sA[kk][m] = a.x; sA[kk+1][m] = a.y; sA[kk+2][m] = a.z; sA[kk+3][m] = a.w;
            float4 w = *(const float4*)&Wmat[(size_t)m*512 + k0 + kk];
            sW[kk][m] = w.x; sW[kk+1][m] = w.y; sW[kk+2][m] = w.z; sW[kk+3][m] = w.w;
        }
        __syncthreads();
        #pragma unroll
        for (int k = 0; k < 32; k++) {
            float4 a = *(const float4*)&sA[k][ty*4];
            float4 w = *(const float4*)&sW[k][tx*4];
            float av[4] = {a.x, a.y, a.z, a.w};
            float wv[4] = {w.x, w.y, w.z, w.w};
            #pragma unroll
            for (int i = 0; i < 4; i++)
                #pragma unroll
                for (int j = 0; j < 4; j++)
                    acc[i][j] += av[i] * wv[j];
        }
        __syncthreads();
    }
    #pragma unroll
    for (int i = 0; i < 4; i++) {
        int m = ty*4 + i;
        #pragma unroll
        for (int j = 0; j < 4; j++) {
            int n = n0 + tx*4 + j;
            if (n < 512) d_da[m*512 + n] = acc[i][j] + bd[n];
            else         d_gate[m*512 + (n-512)] = sigmoidf_(acc[i][j] + bg[n-512]);
        }
    }
}

// ---------------- preds (NTILE=128): issue + body ------------------------------
__device__ __forceinline__ void preds_issue(uint32_t* Asm, uint32_t* Wsm,
        int stage, int kt, int n0, int tid, const uint4* hph, const uint4* hpl) {
    uint32_t* As = Asm + stage*(64*36);
    uint32_t* Ws = Wsm + stage*(NTILE*36);
    #pragma unroll
    for (int u = 0; u < 2; u++) {
        int cid = tid + u*256;
        int row = cid >> 3, c = cid & 7;
        const uint4* src = ((c < 4) ? hph : hpl) + row*64 + kt*4 + (c & 3);
        uint32_t* dst = As + row*36 + ((c < 4) ? c*4 : 16 + (c - 4)*4);
        __pipeline_memcpy_async(dst, src, 16);
    }
    const uint4* wh = (const uint4*)d_wfh16;
    const uint4* wl = (const uint4*)d_wfl16;
    #pragma unroll
    for (int u = 0; u < 4; u++) {      // 128 rows x 8 chunks = 1024
        int cid = tid + u*256;
        int row = cid >> 3, c = cid & 7;
        const uint4* src = ((c < 4) ? wh : wl) + (size_t)(n0 + row)*64 + kt*4 + (c & 3);
        uint32_t* dst = Ws + row*36 + ((c < 4) ? c*4 : 16 + (c - 4)*4);
        __pipeline_memcpy_async(dst, src, 16);
    }
    __pipeline_commit();
}

__device__ void preds_body(int j, uint32_t* sm, int tid,
                           const float* __restrict__ bfc,
                           float* __restrict__ out_pred, int n0) {
    int nact = d_nact[j];
    int mfmax = (nact + 15) >> 4;
    int hb = (j + 1) & 1;
    uint32_t* Asm = sm;
    uint32_t* Wsm = sm + 2*64*36;

    int lane = tid & 31, wp = tid >> 5;
    int g = lane >> 2, tig = lane & 3;
    const uint4* hph = (const uint4*)d_hph[hb];
    const uint4* hpl = (const uint4*)d_hpl[hb];

    float acc[4][2][4];
    #pragma unroll
    for (int a = 0; a < 4; a++)
        #pragma unroll
        for (int b2 = 0; b2 < 2; b2++)
            #pragma unroll
            for (int c2 = 0; c2 < 4; c2++) acc[a][b2][c2] = 0.f;

    preds_issue(Asm, Wsm, 0, 0, n0, tid, hph, hpl);
    for (int kt = 0; kt < 16; kt++) {
        int stage = kt & 1;
        if (kt < 15) {
            preds_issue(Asm, Wsm, stage ^ 1, kt + 1, n0, tid, hph, hpl);
            __pipeline_wait_prior(1);
        } else {
            __pipeline_wait_prior(0);
        }
        __syncthreads();
        const uint32_t* Ahs = Asm + stage*(64*36);
        const uint32_t* Whs = Wsm + stage*(NTILE*36);
        #pragma unroll
        for (int ks = 0; ks < 2; ks++) {
            int ko = ks*8 + tig;
            uint32_t ah[4][4], al[4][4];
            #pragma unroll
            for (int mf = 0; mf < 4; mf++) {
                if (mf >= mfmax) continue;
                int r0 = (mf*16 + g)*36, r1 = (mf*16 + g + 8)*36;
                ah[mf][0] = Ahs[r0 + ko];      ah[mf][1] = Ahs[r1 + ko];
                ah[mf][2] = Ahs[r0 + ko + 4];  ah[mf][3] = Ahs[r1 + ko + 4];
                al[mf][0] = Ahs[r0 + 16 + ko];     al[mf][1] = Ahs[r1 + 16 + ko];
                al[mf][2] = Ahs[r0 + 16 + ko + 4]; al[mf][3] = Ahs[r1 + 16 + ko + 4];
            }
            #pragma unroll
            for (int nf = 0; nf < 2; nf++) {
                int rw = (wp*16 + nf*8 + g)*36 + ko;
                uint32_t bh0 = Whs[rw], bh1 = Whs[rw + 4];
                uint32_t bl0 = Whs[rw + 16], bl1 = Whs[rw + 20];
                #pragma unroll
                for (int mf = 0; mf < 4; mf++) {
                    if (mf >= mfmax) continue;
                    mma_bf16(acc[mf][nf], ah[mf][0], ah[mf][1], ah[mf][2], ah[mf][3], bh0, bh1);
                    mma_bf16(acc[mf][nf], al[mf][0], al[mf][1], al[mf][2], al[mf][3], bh0, bh1);
                    mma_bf16(acc[mf][nf], ah[mf][0], ah[mf][1], ah[mf][2], ah[mf][3], bl0, bl1);
                }
            }
        }
        __syncthreads();
    }

    size_t tbase = (size_t)j * VV;
    #pragma unroll
    for (int nf = 0; nf < 2; nf++) {
        int n = n0 + wp*16 + nf*8 + 2*tig;
        float2 bb = *(const float2*)&bfc[n];
        #pragma unroll
        for (int mf = 0; mf < 4; mf++) {
            int m1 = mf*16 + g;
            float2 o1;
            o1.x = (m1 < nact) ? acc[mf][nf][0] + bb.x : 0.f;
            o1.y = (m1 < nact) ? acc[mf][nf][1] + bb.y : 0.f;
            *(float2*)&out_pred[(size_t)m1*((size_t)TT*VV) + tbase + n] = o1;
            int m2 = m1 + 8;
            float2 o2;
            o2.x = (m2 < nact) ? acc[mf][nf][2] + bb.x : 0.f;
            o2.y = (m2 < nact) ? acc[mf][nf][3] + bb.y : 0.f;
            *(float2*)&out_pred[(size_t)m2*((size_t)TT*VV) + tbase + n] = o2;
        }
    }
}

// ---------------- phase-B issue: A from packed (emb|ctx|h), W from wihh -------
__device__ __forceinline__ void lstm_issue(uint32_t* Asm, uint32_t* Wsm,
        int stage, int c0, int n0, int tid, int t, int hb) {
    uint32_t* As = Asm + stage*(64*36);
    uint32_t* Ws = Wsm + stage*(256*36);
    const uint4* ah4; const uint4* al4; int off4;
    if (c0 < 512) {
        ah4 = (const uint4*)d_embp_h + (size_t)t*BSZ*64;
        al4 = (const uint4*)d_embp_l + (size_t)t*BSZ*64;
        off4 = c0 >> 3;
    } else if (c0 < 1024) {
        ah4 = (const uint4*)d_ctxp_h;
        al4 = (const uint4*)d_ctxp_l;
        off4 = (c0 - 512) >> 3;
    } else {
        ah4 = (const uint4*)d_hph[hb];
        al4 = (const uint4*)d_hpl[hb];
        off4 = (c0 - 1024) >> 3;
    }
    #pragma unroll
    for (int u = 0; u < 2; u++) {
        int cid = tid + u*256;
        int row = cid >> 3, c = cid & 7;
        const uint4* src = ((c < 4) ? ah4 : al4) + (size_t)row*64 + off4 + (c & 3);
        uint32_t* dst = As + row*36 + ((c < 4) ? c*4 : 16 + (c - 4)*4);
        __pipeline_memcpy_async(dst, src, 16);
    }
    const uint4* wh = (const uint4*)d_wihh_h;
    const uint4* wl = (const uint4*)d_wihh_l;
    int woff4 = c0 >> 3;
    #pragma unroll
    for (int u = 0; u < 8; u++) {
        int cid = tid + u*256;
        int row = cid >> 3, c = cid & 7;
        const uint4* src = ((c < 4) ? wh : wl) + (size_t)(n0 + row)*192 + woff4 + (c & 3);
        uint32_t* dst = Ws + row*36 + ((c < 4) ? c*4 : 16 + (c - 4)*4);
        __pipeline_memcpy_async(dst, src, 16);
    }
    __pipeline_commit();
}

// ---------------- phase-D issue: A = h packed, W = wdg packed (N=64) ----------
__device__ __forceinline__ void dg_issue(uint32_t* Asm, uint32_t* Wsm,
        int stage, int kt, int n0, int tid, int hbw) {
    uint32_t* As = Asm + stage*(64*36);
    uint32_t* Ws = Wsm + stage*(64*36);
    const uint4* ah4 = (const uint4*)d_hph[hbw];
    const uint4* al4 = (const uint4*)d_hpl[hbw];
    #pragma unroll
    for (int u = 0; u < 2; u++) {
        int cid = tid + u*256;
        int row = cid >> 3, c = cid & 7;
        const uint4* src = ((c < 4) ? ah4 : al4) + (size_t)row*64 + kt*4 + (c & 3);
        uint32_t* dst = As + row*36 + ((c < 4) ? c*4 : 16 + (c - 4)*4);
        __pipeline_memcpy_async(dst, src, 16);
    }
    const uint4* wh = (const uint4*)d_wdg_h;
    const uint4* wl = (const uint4*)d_wdg_l;
    #pragma unroll
    for (int u = 0; u < 2; u++) {
        int cid = tid + u*256;
        int row = cid >> 3, c = cid & 7;
        const uint4* src = ((c < 4) ? wh : wl) + (size_t)(n0 + row)*64 + kt*4 + (c & 3);
        uint32_t* dst = Ws + row*36 + ((c < 4) ? c*4 : 16 + (c - 4)*4);
        __pipeline_memcpy_async(dst, src, 16);
    }
    __pipeline_commit();
}

// ============ FUSED: recurrence(t) on blocks 0..63 || preds(t-1) on 64+ =======
__global__ void __launch_bounds__(256, 2) fused_kernel(int t,
        const float* __restrict__ wf, const float* __restrict__ bf_scalar,
        const float* __restrict__ bih, const float* __restrict__ bhh,
        const float* __restrict__ bd, const float* __restrict__ bg,
        const float* __restrict__ bfc,
        float* __restrict__ out_alphas, float* __restrict__ out_pred) {
    extern __shared__ __align__(16) uint32_t smem_u[];
    int bid = blockIdx.x;
    int tid = threadIdx.x;

    if (bid >= RBLK) {                     // ---- preds for step t-1 ----
        if (t >= 1) preds_body(t - 1, smem_u, tid, bfc, out_pred, (bid - RBLK) * NTILE);
        return;
    }
    if (t >= TT) return;

    int hb  = t & 1;
    int hbw = (t + 1) & 1;

    // ---------------- phase A: attention (blocks 0..63) -----------------------
    if (t < d_declen[bid]) {
        int b = bid;
        int lane = tid & 31, warp = tid >> 5;
        float4* s_da = (float4*)smem_u;
        float4* s_wf = s_da + 128;
        float*  sc   = (float*)(s_wf + 128);
        float*  red  = sc + 200;

        if (tid < 128) {
            s_da[tid] = ((const float4*)d_da)[b*128 + tid];
            s_wf[tid] = ((const float4*)wf)[tid];
        }
        __syncthreads();

        const float4* ea4 = ((const float4*)d_ea) + (size_t)b*NPIX*128;
        float bfull = bf_scalar[0];
        for (int p0 = warp*2; p0 < NPIX; p0 += 16) {
            int p1 = p0 + 1;
            float s0 = 0.f, s1 = 0.f;
            #pragma unroll
            for (int j = 0; j < 4; j++) {
                int k4 = lane + j*32;
                float4 e0 = ea4[p0*128 + k4];
                float4 e1 = ea4[p1*128 + k4];
                float4 da = s_da[k4];
                float4 w  = s_wf[k4];
                s0 += fmaxf(e0.x + da.x, 0.f) * w.x;
                s0 += fmaxf(e0.y + da.y, 0.f) * w.y;
                s0 += fmaxf(e0.z + da.z, 0.f) * w.z;
                s0 += fmaxf(e0.w + da.w, 0.f) * w.w;
                s1 += fmaxf(e1.x + da.x, 0.f) * w.x;
                s1 += fmaxf(e1.y + da.y, 0.f) * w.y;
                s1 += fmaxf(e1.z + da.z, 0.f) * w.z;
                s1 += fmaxf(e1.w + da.w, 0.f) * w.w;
            }
            s0 = warp_sum(s0);
            s1 = warp_sum(s1);
            if (lane == 0) { sc[p0] = s0 + bfull; sc[p1] = s1 + bfull; }
        }
        __syncthreads();

        float v = (tid < NPIX) ? sc[tid] : -1e30f;
        float wm = warp_max(v);
        if (lane == 0) red[warp] = wm;
        __syncthreads();
        if (tid == 0) {
            float mm = red[0];
            #pragma unroll
            for (int i = 1; i < 8; i++) mm = fmaxf(mm, red[i]);
            red[16] = mm;
        }
        __syncthreads();
        float gmax = red[16];
        float e = (tid < NPIX) ? __expf(v - gmax) : 0.f;
        float ws = warp_sum(e);
        if (lane == 0) red[8 + warp] = ws;
        __syncthreads();
        if (tid == 0) {
            float ss = 0.f;
            #pragma unroll
            for (int i = 0; i < 8; i++) ss += red[8 + i];
            red[17] = ss;
        }
        __syncthreads();
        float alpha = e / red[17];
        __syncthreads();
        if (tid < NPIX) {
            sc[tid] = alpha;
            out_alphas[(size_t)b*TT*NPIX + (size_t)t*NPIX + tid] = alpha;
        }
        __syncthreads();

        const float2* encb2 = (const float2*)(d_enc_s + (size_t)b*NPIX*512);
        float sx[16], sy[16];
        #pragma unroll
        for (int u = 0; u < 16; u++) { sx[u] = 0.f; sy[u] = 0.f; }
        #pragma unroll 2
        for (int p0 = 0; p0 < 192; p0 += 16) {
            #pragma unroll
            for (int u = 0; u < 16; u++) {
                float2 vv = encb2[(p0+u)*256 + tid];
                float al = sc[p0+u];
                sx[u] += al * vv.x;
                sy[u] += al * vv.y;
            }
        }
        #pragma unroll
        for (int u = 0; u < 4; u++) {
            float2 vv = encb2[(192+u)*256 + tid];
            float al = sc[192+u];
            sx[u] += al * vv.x;
            sy[u] += al * vv.y;
        }
        float X = 0.f, Y = 0.f;
        #pragma unroll
        for (int u = 0; u < 16; u++) { X += sx[u]; Y += sy[u]; }
        float2 g2 = ((const float2*)d_gate)[b*256 + tid];
        float cx = X * g2.x, cy = Y * g2.y;
        uint32_t chi, clo; bfsplit2(cx, cy, chi, clo);
        d_ctxp_h[b*256 + tid] = chi;
        d_ctxp_l[b*256 + tid] = clo;
    }
    rec_bar(tid);

    // ---------------- phase B: LSTM gate GEMM via mma (64 blocks) -------------
    {
        uint32_t* Asm = smem_u;
        uint32_t* Wsm = smem_u + 2*64*36;
        int n0 = (bid & 7) * 256;
        int ksplit = bid >> 3;
        int kbase = ksplit * 192;
        int lane = tid & 31, wp = tid >> 5;
        int g = lane >> 2, tig = lane & 3;

        float acc[4][4][4];
        #pragma unroll
        for (int a = 0; a < 4; a++)
            #pragma unroll
            for (int b2 = 0; b2 < 4; b2++)
                #pragma unroll
                for (int c2 = 0; c2 < 4; c2++) acc[a][b2][c2] = 0.f;

        lstm_issue(Asm, Wsm, 0, kbase, n0, tid, t, hb);
        for (int kt = 0; kt < 6; kt++) {
            int stage = kt & 1;
            if (kt < 5) {
                lstm_issue(Asm, Wsm, stage ^ 1, kbase + (kt+1)*32, n0, tid, t, hb);
                __pipeline_wait_prior(1);
            } else {
                __pipeline_wait_prior(0);
            }
            __syncthreads();
            const uint32_t* Ahs = Asm + stage*(64*36);
            const uint32_t* Whs = Wsm + stage*(256*36);
            #pragma unroll
            for (int ks = 0; ks < 2; ks++) {
                int ko = ks*8 + tig;
                uint32_t ah[4][4], al[4][4];
                #pragma unroll
                for (int mf = 0; mf < 4; mf++) {
                    int r0 = (mf*16 + g)*36, r1 = (mf*16 + g + 8)*36;
                    ah[mf][0] = Ahs[r0 + ko];      ah[mf][1] = Ahs[r1 + ko];
                    ah[mf][2] = Ahs[r0 + ko + 4];  ah[mf][3] = Ahs[r1 + ko + 4];
                    al[mf][0] = Ahs[r0 + 16 + ko];     al[mf][1] = Ahs[r1 + 16 + ko];
                    al[mf][2] = Ahs[r0 + 16 + ko + 4]; al[mf][3] = Ahs[r1 + 16 + ko + 4];
                }
                #pragma unroll
                for (int nf = 0; nf < 4; nf++) {
                    int rw = (wp*32 + nf*8 + g)*36 + ko;
                    uint32_t bh0 = Whs[rw], bh1 = Whs[rw + 4];
                    uint32_t bl0 = Whs[rw + 16], bl1 = Whs[rw + 20];
                    #pragma unroll
                    for (int mf = 0; mf < 4; mf++) {
                        mma_bf16(acc[mf][nf], ah[mf][0], ah[mf][1], ah[mf][2], ah[mf][3], bh0, bh1);
                        mma_bf16(acc[mf][nf], al[mf][0], al[mf][1], al[mf][2], al[mf][3], bh0, bh1);
                        mma_bf16(acc[mf][nf], ah[mf][0], ah[mf][1], ah[mf][2], ah[mf][3], bl0, bl1);
                    }
                }
            }
            __syncthreads();
        }

        float* gp = d_gates_p + (size_t)ksplit * (BSZ*2048);
        #pragma unroll
        for (int nf = 0; nf < 4; nf++) {
            int n = n0 + wp*32 + nf*8 + 2*tig;
            #pragma unroll
            for (int mf = 0; mf < 4; mf++) {
                int m1 = mf*16 + g;
                float2 o1; o1.x = acc[mf][nf][0]; o1.y = acc[mf][nf][1];
                *(float2*)&gp[m1*2048 + n] = o1;
                int m2 = m1 + 8;
                float2 o2; o2.x = acc[mf][nf][2]; o2.y = acc[mf][nf][3];
                *(float2*)&gp[m2*2048 + n] = o2;
            }
        }
    }
    rec_bar(tid);

    // ---------------- phase C: LSTM apply + bf16 pack (blocks 0..15) ----------
    if (bid < 16) {
        int gid = bid*256 + tid;
        int idx0 = gid*8;
        int b = idx0 >> 9;
        int f0 = (idx0 & 511) >> 2;
        float acc[4][8];
        #pragma unroll
        for (int q = 0; q < 4; q++)
            #pragma unroll
            for (int e = 0; e < 8; e++) acc[q][e] = 0.f;
        #pragma unroll
        for (int s = 0; s < NSPLIT; s++) {
            const float4* g4 = (const float4*)(d_gates_p + (size_t)s*(BSZ*2048) + b*2048);
            #pragma unroll
            for (int q = 0; q < 4; q++) {
                float4 v0 = g4[q*128 + f0];
                float4 v1 = g4[q*128 + f0 + 1];
                acc[q][0] += v0.x; acc[q][1] += v0.y; acc[q][2] += v0.z; acc[q][3] += v0.w;
                acc[q][4] += v1.x; acc[q][5] += v1.y; acc[q][6] += v1.z; acc[q][7] += v1.w;
            }
        }
        const float4* bi4 = (const float4*)bih;
        const float4* bh4 = (const float4*)bhh;
        #pragma unroll
        for (int q = 0; q < 4; q++) {
            float4 u0 = bi4[q*128 + f0], u1 = bi4[q*128 + f0 + 1];
            float4 w0 = bh4[q*128 + f0], w1 = bh4[q*128 + f0 + 1];
            acc[q][0] += u0.x + w0.x; acc[q][1] += u0.y + w0.y;
            acc[q][2] += u0.z + w0.z; acc[q][3] += u0.w + w0.w;
            acc[q][4] += u1.x + w1.x; acc[q][5] += u1.y + w1.y;
            acc[q][6] += u1.z + w1.z; acc[q][7] += u1.w + w1.w;
        }
        float hv[8];
        #pragma unroll
        for (int e = 0; e < 8; e++) {
            float ig = sigmoidf_(acc[0][e]);
            float fg = sigmoidf_(acc[1][e]);
            float g2 = tanhf(acc[2][e]);
            float og = sigmoidf_(acc[3][e]);
            float c  = fg * d_c[idx0 + e] + ig * g2;
            float h  = og * tanhf(c);
            d_c[idx0 + e] = c;
            hv[e] = h;
        }
        uint4 ph, pl;
        bfsplit2(hv[0], hv[1], ph.x, pl.x);
        bfsplit2(hv[2], hv[3], ph.y, pl.y);
        bfsplit2(hv[4], hv[5], ph.z, pl.z);
        bfsplit2(hv[6], hv[7], ph.w, pl.w);
        ((uint4*)d_hph[hbw])[gid] = ph;
        ((uint4*)d_hpl[hbw])[gid] = pl;
    }
    rec_bar(tid);

    // ---------------- phase D: dagate via mma (blocks 0..15, N=64) ------------
    if (bid < 16) {
        uint32_t* Asm = smem_u;
        uint32_t* Wsm = smem_u + 2*64*36;
        int n0 = bid * 64;
        int lane = tid & 31, wp = tid >> 5;
        int g = lane >> 2, tig = lane & 3;

        float acc[4][4];
        #pragma unroll
        for (int a = 0; a < 4; a++)
            #pragma unroll
            for (int c2 = 0; c2 < 4; c2++) acc[a][c2] = 0.f;

        dg_issue(Asm, Wsm, 0, 0, n0, tid, hbw);
        for (int kt = 0; kt < 16; kt++) {
            int stage = kt & 1;
            if (kt < 15) {
                dg_issue(Asm, Wsm, stage ^ 1, kt + 1, n0, tid, hbw);
                __pipeline_wait_prior(1);
            } else {
                __pipeline_wait_prior(0);
            }
            __syncthreads();
            const uint32_t* Ahs = Asm + stage*(64*36);
            const uint32_t* Whs = Wsm + stage*(64*36);
            #pragma unroll
            for (int ks = 0; ks < 2; ks++) {
                int ko = ks*8 + tig;
                int rw = (wp*8 + g)*36 + ko;
                uint32_t bh0 = Whs[rw], bh1 = Whs[rw + 4];
                uint32_t bl0 = Whs[rw + 16], bl1 = Whs[rw + 20];
                #pragma unroll
                for (int mf = 0; mf < 4; mf++) {
                    int r0 = (mf*16 + g)*36, r1 = (mf*16 + g + 8)*36;
                    uint32_t a0 = Ahs[r0 + ko],      a1 = Ahs[r1 + ko];
                    uint32_t a2 = Ahs[r0 + ko + 4],  a3 = Ahs[r1 + ko + 4];
                    uint32_t l0 = Ahs[r0 + 16 + ko],     l1 = Ahs[r1 + 16 + ko];
                    uint32_t l2 = Ahs[r0 + 16 + ko + 4], l3 = Ahs[r1 + 16 + ko + 4];
                    mma_bf16(acc[mf], a0, a1, a2, a3, bh0, bh1);
                    mma_bf16(acc[mf], l0, l1, l2, l3, bh0, bh1);
                    mma_bf16(acc[mf], a0, a1, a2, a3, bl0, bl1);
                }
            }
            __syncthreads();
        }

        int n = n0 + wp*8 + 2*tig;
        #pragma unroll
        for (int mf = 0; mf < 4; mf++) {
            int m1 = mf*16 + g;
            int m2 = m1 + 8;
            if (n < 512) {
                float2 bb = *(const float2*)&bd[n];
                float2 o1; o1.x = acc[mf][0] + bb.x; o1.y = acc[mf][1] + bb.y;
                *(float2*)&d_da[m1*512 + n] = o1;
                float2 o2; o2.x = acc[mf][2] + bb.x; o2.y = acc[mf][3] + bb.y;
                *(float2*)&d_da[m2*512 + n] = o2;
            } else {
                int ng = n - 512;
                float2 bb = *(const float2*)&bg[ng];
                float2 o1; o1.x = sigmoidf_(acc[mf][0] + bb.x); o1.y = sigmoidf_(acc[mf][1] + bb.y);
                *(float2*)&d_gate[m1*512 + ng] = o1;
                float2 o2; o2.x = sigmoidf_(acc[mf][2] + bb.x); o2.y = sigmoidf_(acc[mf][3] + bb.y);
                *(float2*)&d_gate[m2*512 + ng] = o2;
            }
        }
    }
}

// ---------------- launch ------------------------------------------------------
extern "C" void kernel_launch(void* const* d_in, const int* in_sizes, int n_in,
                              void* d_out, int out_size) {
    const float* encoder_out = (const float*)d_in[0];
    const int*   caps        = (const int*)  d_in[1];
    const int*   cap_len     = (const int*)  d_in[2];
    const float* W_enc_attn  = (const float*)d_in[3];
    const float* b_enc_attn  = (const float*)d_in[4];
    const float* W_dec_attn  = (const float*)d_in[5];
    const float* b_dec_attn  = (const float*)d_in[6];
    const float* w_full_attn = (const float*)d_in[7];
    const float* b_full_attn = (const float*)d_in[8];
    const float* emb_table   = (const float*)d_in[9];
    const float* W_ih        = (const float*)d_in[10];
    const float* W_hh        = (const float*)d_in[11];
    const float* b_ih        = (const float*)d_in[12];
    const float* b_hh        = (const float*)d_in[13];
    const float* W_init_h    = (const float*)d_in[14];
    const float* b_init_h    = (const float*)d_in[15];
    const float* W_init_c    = (const float*)d_in[16];
    const float* b_init_c    = (const float*)d_in[17];
    const float* W_f_beta    = (const float*)d_in[18];
    const float* b_f_beta    = (const float*)d_in[19];
    const float* W_fc        = (const float*)d_in[20];
    const float* b_fc        = (const float*)d_in[21];

    float* out = (float*)d_out;
    const size_t OFF_PRED   = 0;
    const size_t OFF_CAPS   = OFF_PRED + (size_t)BSZ*TT*VV;
    const size_t OFF_DECLEN = OFF_CAPS + (size_t)BSZ*ML;
    const size_t OFF_ALPHA  = OFF_DECLEN + BSZ;
    const size_t OFF_ORDER  = OFF_ALPHA + (size_t)BSZ*TT*NPIX;
    float* out_pred   = out + OFF_PRED;
    float* out_caps   = out + OFF_CAPS;
    float* out_declen = out + OFF_DECLEN;
    float* out_alphas = out + OFF_ALPHA;
    float* out_order  = out + OFF_ORDER;

    static cudaStream_t s2 = nullptr;
    static cudaEvent_t evRoot, evCvt;
    static bool inited = false;
    const int FUSED_SMEM = (2*64*36 + 2*256*36) * 4;   // 92160 B
    const int EA_SMEM = (64*36 + 256*36) * 4;          // 46080 B
    if (!inited) {
        cudaStreamCreateWithFlags(&s2, cudaStreamNonBlocking);
        cudaEventCreateWithFlags(&evRoot, cudaEventDisableTiming);
        cudaEventCreateWithFlags(&evCvt, cudaEventDisableTiming);
        cudaFuncSetAttribute(fused_kernel, cudaFuncAttributeMaxDynamicSharedMemorySize,
                             FUSED_SMEM);
        cudaFuncSetAttribute(ea_mma_kernel, cudaFuncAttributeMaxDynamicSharedMemorySize,
                             EA_SMEM);
        inited = true;
    }

    size_t tail = (size_t)out_size - OFF_CAPS;
    cudaMemsetAsync(out + OFF_CAPS, 0, tail * sizeof(float));

    // weight converts on s2, overlapped with main prologue on stream 0
    cudaEventRecord(evRoot, 0);
    cudaStreamWaitEvent(s2, evRoot, 0);
    convert_wfc_kernel<<<(VV*64)/256, 256, 0, s2>>>((const float4*)W_fc);
    convert_wihh_kernel<<<(2048*768)/256, 256, 0, s2>>>(W_ih, W_hh);
    convert_wdg_kernel<<<(1024*256)/256, 256, 0, s2>>>(W_dec_attn, W_f_beta);
    cudaEventRecord(evCvt, s2);

    sort_kernel<<<1, 64>>>(cap_len, caps, out_caps, out_declen, out_order);
    convert_emb_kernel<<<dim3(BSZ, ML), 256>>>(emb_table);
    reorder_mean_kernel<<<BSZ, 256>>>(encoder_out);
    ea_mma_kernel<<<dim3(2, 196), 256, EA_SMEM>>>(W_enc_attn, b_enc_attn);
    gemm64_kernel<<<dim3(8, 1), 256>>>(1, W_init_h, b_init_h, 512, 512);
    gemm64_kernel<<<dim3(8, 1), 256>>>(2, W_init_c, b_init_c, 512, 512);
    convert_h0_kernel<<<64, 256>>>();
    dagate_kernel<<<16, 256>>>(W_dec_attn, b_dec_attn, W_f_beta, b_f_beta);

    cudaStreamWaitEvent((cudaStream_t)0, evCvt, 0);

    for (int t = 0; t <= TT; t++) {
        fused_kernel<<<GRID, 256, FUSED_SMEM>>>(t, w_full_attn, b_full_attn,
                                                b_ih, b_hh, b_dec_attn, b_f_beta,
                                                b_fc, out_alphas, out_pred);
    }
}

// round 15
// speedup vs baseline: 1.7241x; 1.1583x over previous
#include <cuda_runtime.h>
#include <cuda_bf16.h>
#include <cuda_pipeline.h>
#include <math.h>
#include <stdint.h>

#define BSZ 64
#define NPIX 196
#define ENCD 512
#define DD 512
#define VV 32000
#define TT 50
#define ML 51
#define NSPLIT 8
#define RBLK 64                  // recurrence blocks (barrier group)
#define NTILE 128                // preds n-tile width
#define PBLK (VV/NTILE)          // 250 preds blocks
#define GRID (RBLK + PBLK)       // 314

// ---------------- scratch (static device globals; no runtime alloc) ----------
__device__ float d_enc_s[BSZ*NPIX*ENCD];
__device__ float d_ea[BSZ*NPIX*ENCD];
__device__ float d_mean[BSZ*ENCD];
__device__ float d_hbuf[2][BSZ*DD];
__device__ uint32_t d_hph[2][BSZ*DD/2];      // h bf16-hi pairs
__device__ uint32_t d_hpl[2][BSZ*DD/2];      // h bf16-lo pairs
__device__ float d_c[BSZ*DD];
__device__ uint32_t d_ctxp_h[BSZ*DD/2];      // ctx bf16 packed
__device__ uint32_t d_ctxp_l[BSZ*DD/2];
__device__ float d_da[BSZ*DD];
__device__ float d_gate[BSZ*ENCD];
__device__ float d_gates_p[NSPLIT*BSZ*4*DD];
__device__ uint32_t d_wfh16[(size_t)VV*256];   // W_fc bf16 hi
__device__ uint32_t d_wfl16[(size_t)VV*256];   // W_fc bf16 lo
__device__ uint32_t d_wihh_h[2048*768];        // [Wih|Whh] bf16 hi (k-pairs)
__device__ uint32_t d_wihh_l[2048*768];
__device__ uint32_t d_wdg_h[1024*256];         // [Wd;Wg] bf16 hi
__device__ uint32_t d_wdg_l[1024*256];
__device__ uint32_t d_embp_h[(size_t)ML*BSZ*256];  // sorted emb rows packed
__device__ uint32_t d_embp_l[(size_t)ML*BSZ*256];
__device__ unsigned int d_bar;
__device__ int   d_order[BSZ];
__device__ int   d_declen[BSZ];
__device__ int   d_caps_s[BSZ*ML];
__device__ int   d_nact[TT];

// ---------------- helpers ----------------------------------------------------
__device__ __forceinline__ float warp_sum(float v) {
    #pragma unroll
    for (int o = 16; o > 0; o >>= 1) v += __shfl_down_sync(0xffffffffu, v, o);
    return v;
}
__device__ __forceinline__ float warp_max(float v) {
    #pragma unroll
    for (int o = 16; o > 0; o >>= 1) v = fmaxf(v, __shfl_down_sync(0xffffffffu, v, o));
    return v;
}
__device__ __forceinline__ float sigmoidf_(float x) { return 1.0f / (1.0f + __expf(-x)); }

__device__ __forceinline__ void bfsplit2(float a, float b, uint32_t& hi, uint32_t& lo) {
    __nv_bfloat162 h2 = __floats2bfloat162_rn(a, b);
    float ra = a - __bfloat162float(h2.x);
    float rb = b - __bfloat162float(h2.y);
    __nv_bfloat162 l2 = __floats2bfloat162_rn(ra, rb);
    hi = *(uint32_t*)&h2;
    lo = *(uint32_t*)&l2;
}

__device__ __forceinline__ void mma_bf16(float c[4], uint32_t a0, uint32_t a1,
                                         uint32_t a2, uint32_t a3,
                                         uint32_t b0, uint32_t b1) {
    asm volatile(
        "mma.sync.aligned.m16n8k16.row.col.f32.bf16.bf16.f32 "
        "{%0,%1,%2,%3}, {%4,%5,%6,%7}, {%8,%9}, {%0,%1,%2,%3};\n"
        : "+f"(c[0]), "+f"(c[1]), "+f"(c[2]), "+f"(c[3])
        : "r"(a0), "r"(a1), "r"(a2), "r"(a3), "r"(b0), "r"(b1));
}

// cp.async 16B with L2 evict_first policy (single-use streaming weights)
__device__ __forceinline__ void cp_async16_ef(void* dst_smem, const void* src) {
    uint32_t d = (uint32_t)__cvta_generic_to_shared(dst_smem);
    asm volatile(
        "{\n\t.reg .b64 p;\n\t"
        "createpolicy.fractional.L2::evict_first.b64 p, 1.0;\n\t"
        "cp.async.cg.shared.global.L2::cache_hint [%0], [%1], 16, p;\n\t}"
        :: "r"(d), "l"(src) : "memory");
}

// streaming float2 store (avoid polluting L2 with prediction output)
__device__ __forceinline__ void st_cs_f2(float* p, float x, float y) {
    asm volatile("st.global.cs.v2.f32 [%0], {%1, %2};"
                 :: "l"(p), "f"(x), "f"(y) : "memory");
}

// barrier among the first RBLK blocks only: atomic arrive, acquire-poll
__device__ __forceinline__ void rec_bar(int tid) {
    __threadfence();
    __syncthreads();
    if (tid == 0) {
        unsigned t0 = atomicAdd(&d_bar, 1u);
        unsigned target = t0 - (t0 % RBLK) + RBLK;
        unsigned v;
        do {
            asm volatile("ld.global.acquire.gpu.u32 %0, [%1];" : "=r"(v) : "l"(&d_bar));
        } while (v < target);
    }
    __syncthreads();
}

// ---------------- one-time converts -------------------------------------------
__global__ __launch_bounds__(256) void convert_wfc_kernel(const float4* __restrict__ W) {
    size_t gi = (size_t)blockIdx.x*256 + threadIdx.x;
    float4 v0 = W[gi*2];
    float4 v1 = W[gi*2+1];
    uint4 h, l;
    bfsplit2(v0.x, v0.y, h.x, l.x);
    bfsplit2(v0.z, v0.w, h.y, l.y);
    bfsplit2(v1.x, v1.y, h.z, l.z);
    bfsplit2(v1.z, v1.w, h.w, l.w);
    ((uint4*)d_wfh16)[gi] = h;
    ((uint4*)d_wfl16)[gi] = l;
}

__global__ __launch_bounds__(256) void convert_wihh_kernel(
        const float* __restrict__ Wih, const float* __restrict__ Whh) {
    int idx = blockIdx.x*256 + threadIdx.x;
    int n = idx / 768, p = idx % 768;
    int k = p * 2;
    float a, b;
    if (k < 1024) { a = Wih[(size_t)n*1024 + k]; b = Wih[(size_t)n*1024 + k + 1]; }
    else          { a = Whh[(size_t)n*512 + (k-1024)]; b = Whh[(size_t)n*512 + (k-1023)]; }
    uint32_t hi, lo; bfsplit2(a, b, hi, lo);
    d_wihh_h[idx] = hi; d_wihh_l[idx] = lo;
}

__global__ __launch_bounds__(256) void convert_wdg_kernel(
        const float* __restrict__ Wd, const float* __restrict__ Wg) {
    int idx = blockIdx.x*256 + threadIdx.x;
    int n = idx >> 8, p = idx & 255;
    int k = p * 2;
    const float* W = (n < 512) ? (Wd + (size_t)n*512) : (Wg + (size_t)(n-512)*512);
    uint32_t hi, lo; bfsplit2(W[k], W[k+1], hi, lo);
    d_wdg_h[idx] = hi; d_wdg_l[idx] = lo;
}

__global__ __launch_bounds__(256) void convert_emb_kernel(const float* __restrict__ emb) {
    int b = blockIdx.x, tt = blockIdx.y, tid = threadIdx.x;
    int tok = d_caps_s[b*ML + tt];
    const float* src = emb + (size_t)tok*512 + tid*2;
    uint32_t hi, lo; bfsplit2(src[0], src[1], hi, lo);
    size_t o = ((size_t)tt*BSZ + b)*256 + tid;
    d_embp_h[o] = hi; d_embp_l[o] = lo;
}

__global__ __launch_bounds__(256) void convert_h0_kernel() {
    int pid = blockIdx.x*256 + threadIdx.x;
    float a = d_hbuf[0][pid*2];
    float b = d_hbuf[0][pid*2+1];
    uint32_t hi, lo; bfsplit2(a, b, hi, lo);
    d_hph[0][pid] = hi; d_hpl[0][pid] = lo;
}

// ---------------- sort (stable, descending cap_len) ---------------------------
__global__ void sort_kernel(const int* __restrict__ cap_len,
                            const int* __restrict__ caps,
                            float* __restrict__ out_caps,
                            float* __restrict__ out_declen,
                            float* __restrict__ out_order) {
    int i = threadIdx.x;
    int cl = cap_len[i];
    int r = 0;
    for (int j = 0; j < BSZ; j++) {
        int cj = cap_len[j];
        if (cj > cl || (cj == cl && j < i)) r++;
    }
    d_order[r]  = i;
    d_declen[r] = cl - 1;
    __syncthreads();
    out_order[i]  = (float)d_order[i];
    out_declen[i] = (float)d_declen[i];
    int src = d_order[i];
    for (int tt = 0; tt < ML; tt++) {
        int tok = caps[src*ML + tt];
        d_caps_s[i*ML + tt] = tok;
        out_caps[i*ML + tt] = (float)tok;
    }
    if (i < TT) {
        int cnt = 0;
        for (int j = 0; j < BSZ; j++) if (d_declen[j] > i) cnt++;
        d_nact[i] = cnt;
    }
}

// ---------------- reorder encoder + per-batch pixel mean ----------------------
__global__ __launch_bounds__(256) void reorder_mean_kernel(const float* __restrict__ enc) {
    int b = blockIdx.x;
    int tid = threadIdx.x;
    int src = d_order[b];
    const float* Ein = enc + (size_t)src*NPIX*ENCD;
    float* Eo = d_enc_s + (size_t)b*NPIX*ENCD;
    float s0 = 0.f, s1 = 0.f;
    for (int p = 0; p < NPIX; p++) {
        float v0 = Ein[p*ENCD + tid];
        float v1 = Ein[p*ENCD + tid + 256];
        Eo[p*ENCD + tid]       = v0;
        Eo[p*ENCD + tid + 256] = v1;
        s0 += v0; s1 += v1;
    }
    d_mean[b*ENCD + tid]       = s0 * (1.0f/NPIX);
    d_mean[b*ENCD + tid + 256] = s1 * (1.0f/NPIX);
}

// ---------------- small GEMM for h0/c0: C = A @ W^T + bias -------------------
__global__ __launch_bounds__(256) void gemm64_kernel(int sel,
        const float* __restrict__ Wmat, const float* __restrict__ bias,
        int K, int N) {
    const float* Amat = d_mean;
    float*       Cmat = (sel == 1) ? d_hbuf[0] : d_c;
    __shared__ float sA[32][64];
    __shared__ float sW[32][64];
    int tid = threadIdx.x;
    int tx = tid & 15, ty = tid >> 4;
    int m0 = blockIdx.y * 64;
    int n0 = blockIdx.x * 64;
    float acc[4][4] = {};
    for (int k0 = 0; k0 < K; k0 += 32) {
        #pragma unroll
        for (int u = 0; u < 2; u++) {
            int f4i = tid + u*256;
            int m  = f4i >> 3;
            int kk = (f4i & 7) << 2;
            float4 a = *(const float4*)&Amat[(size_t)(m0+m)*K + k0 + kk];
            sA[kk][m] = a.x; sA[kk+1][m] = a.y; sA[kk+2][m] = a.z; sA[kk+3][m] = a.w;
            float4 w = *(const float4*)&Wmat[(size_t)(n0+m)*K + k0 + kk];
            sW[kk][m] = w.x; sW[kk+1][m] = w.y; sW[kk+2][m] = w.z; sW[kk+3][m] = w.w;
        }
        __syncthreads();
        #pragma unroll
        for (int k = 0; k < 32; k++) {
            float4 a = *(const float4*)&sA[k][ty*4];
            float4 w = *(const float4*)&sW[k][tx*4];
            float av[4] = {a.x, a.y, a.z, a.w};
            float wv[4] = {w.x, w.y, w.z, w.w};
            #pragma unroll
            for (int i = 0; i < 4; i++)
                #pragma unroll
                for (int j = 0; j < 4; j++)
                    acc[i][j] += av[i] * wv[j];
        }
        __syncthreads();
    }
    #pragma unroll
    for (int i = 0; i < 4; i++) {
        int m = m0 + ty*4 + i;
        #pragma unroll
        for (int j = 0; j < 4; j++) {
            int n = n0 + tx*4 + j;
            Cmat[(size_t)m*N + n] = acc[i][j] + bias[n];
        }
    }
}

// ---------------- ea = enc_s @ W_enc^T + b via bf16 3-term split mma ----------
__global__ void __launch_bounds__(256, 2) ea_mma_kernel(
        const float* __restrict__ Wenc, const float* __restrict__ bias) {
    extern __shared__ __align__(16) uint32_t sm[];
    uint32_t* Asm = sm;                  // [64][36]
    uint32_t* Wsm = sm + 64*36;          // [256][36]

    int m0 = blockIdx.y * 64;
    int n0 = blockIdx.x * 256;
    int tid = threadIdx.x;
    int lane = tid & 31, wp = tid >> 5;
    int g = lane >> 2, tig = lane & 3;

    float acc[4][4][4];
    #pragma unroll
    for (int a = 0; a < 4; a++)
        #pragma unroll
        for (int b2 = 0; b2 < 4; b2++)
            #pragma unroll
            for (int c2 = 0; c2 < 4; c2++) acc[a][b2][c2] = 0.f;

    for (int kt = 0; kt < 16; kt++) {
        {
            int row = tid >> 2, c = tid & 3;
            const float* src = d_enc_s + (size_t)(m0+row)*512 + kt*32 + c*8;
            float4 v0 = *(const float4*)src;
            float4 v1 = *(const float4*)(src + 4);
            uint4 h, l;
            bfsplit2(v0.x, v0.y, h.x, l.x);
            bfsplit2(v0.z, v0.w, h.y, l.y);
            bfsplit2(v1.x, v1.y, h.z, l.z);
            bfsplit2(v1.z, v1.w, h.w, l.w);
            *(uint4*)&Asm[row*36 + c*4]      = h;
            *(uint4*)&Asm[row*36 + 16 + c*4] = l;
        }
        #pragma unroll
        for (int u = 0; u < 4; u++) {
            int cid = tid + u*256;
            int row = cid >> 2, c = cid & 3;
            const float* src = Wenc + (size_t)(n0+row)*512 + kt*32 + c*8;
            float4 v0 = *(const float4*)src;
            float4 v1 = *(const float4*)(src + 4);
            uint4 h, l;
            bfsplit2(v0.x, v0.y, h.x, l.x);
            bfsplit2(v0.z, v0.w, h.y, l.y);
            bfsplit2(v1.x, v1.y, h.z, l.z);
            bfsplit2(v1.z, v1.w, h.w, l.w);
            *(uint4*)&Wsm[row*36 + c*4]      = h;
            *(uint4*)&Wsm[row*36 + 16 + c*4] = l;
        }
        __syncthreads();
        #pragma unroll
        for (int ks = 0; ks < 2; ks++) {
            int ko = ks*8 + tig;
            uint32_t ah[4][4], al[4][4];
            #pragma unroll
            for (int mf = 0; mf < 4; mf++) {
                int r0 = (mf*16 + g)*36, r1 = (mf*16 + g + 8)*36;
                ah[mf][0] = Asm[r0 + ko];      ah[mf][1] = Asm[r1 + ko];
                ah[mf][2] = Asm[r0 + ko + 4];  ah[mf][3] = Asm[r1 + ko + 4];
                al[mf][0] = Asm[r0 + 16 + ko];     al[mf][1] = Asm[r1 + 16 + ko];
                al[mf][2] = Asm[r0 + 16 + ko + 4]; al[mf][3] = Asm[r1 + 16 + ko + 4];
            }
            #pragma unroll
            for (int nf = 0; nf < 4; nf++) {
                int rw = (wp*32 + nf*8 + g)*36 + ko;
                uint32_t bh0 = Wsm[rw], bh1 = Wsm[rw + 4];
                uint32_t bl0 = Wsm[rw + 16], bl1 = Wsm[rw + 20];
                #pragma unroll
                for (int mf = 0; mf < 4; mf++) {
                    mma_bf16(acc[mf][nf], ah[mf][0], ah[mf][1], ah[mf][2], ah[mf][3], bh0, bh1);
                    mma_bf16(acc[mf][nf], al[mf][0], al[mf][1], al[mf][2], al[mf][3], bh0, bh1);
                    mma_bf16(acc[mf][nf], ah[mf][0], ah[mf][1], ah[mf][2], ah[mf][3], bl0, bl1);
                }
            }
        }
        __syncthreads();
    }

    #pragma unroll
    for (int nf = 0; nf < 4; nf++) {
        int n = n0 + wp*32 + nf*8 + 2*tig;
        float2 bb = *(const float2*)&bias[n];
        #pragma unroll
        for (int mf = 0; mf < 4; mf++) {
            int m1 = m0 + mf*16 + g;
            float2 o1; o1.x = acc[mf][nf][0] + bb.x; o1.y = acc[mf][nf][1] + bb.y;
            *(float2*)&d_ea[(size_t)m1*512 + n] = o1;
            int m2 = m1 + 8;
            float2 o2; o2.x = acc[mf][nf][2] + bb.x; o2.y = acc[mf][nf][3] + bb.y;
            *(float2*)&d_ea[(size_t)m2*512 + n] = o2;
        }
    }
}

// ---------------- standalone dagate (step-0 prologue, SIMT) -------------------
__global__ __launch_bounds__(256) void dagate_kernel(
        const float* __restrict__ Wd, const float* __restrict__ bd,
        const float* __restrict__ Wg, const float* __restrict__ bg) {
    __shared__ float sA[32][64];
    __shared__ float sW[32][64];
    const float* hsrc = d_hbuf[0];
    int tid = threadIdx.x;
    int tx = tid & 15, ty = tid >> 4;
    int n0 = blockIdx.x * 64;
    const float* Wmat = (n0 < 512) ? (Wd + (size_t)n0*512) : (Wg + (size_t)(n0-512)*512);
    float acc[4][4] = {};
    for (int k0 = 0; k0 < 512; k0 += 32) {
        #pragma unroll
        for (int u = 0; u < 2; u++) {
            int f4i = tid + u*256;
            int m  = f4i >> 3;
            int kk = (f4i & 7) << 2;
            float4 a = *(const float4*)&hsrc[(size_t)m*512 + k0 + kk];
            sA[kk][m] = a.x; sA[kk+1][m] = a.y; sA[kk+2][m] = a.z; sA[kk+3][m] = a.w;
            float4 w = *(const float4*)&Wmat[(size_t)m*512 + k0 + kk];
            sW[kk][m] = w.x; sW[kk+1][m] = w.y; sW[kk+2][m] = w.z; sW[kk+3][m] = w.w;
        }
        __syncthreads();
        #pragma unroll
        for (int k = 0; k < 32; k++) {
            float4 a = *(const float4*)&sA[k][ty*4];
            float4 w = *(const float4*)&sW[k][tx*4];
            float av[4] = {a.x, a.y, a.z, a.w};
            float wv[4] = {w.x, w.y, w.z, w.w};
            #pragma unroll
            for (int i = 0; i < 4; i++)
                #pragma unroll
                for (int j = 0; j < 4; j++)
                    acc[i][j] += av[i] * wv[j];
        }
        __syncthreads();
    }
    #pragma unroll
    for (int i = 0; i < 4; i++) {
        int m = ty*4 + i;
        #pragma unroll
        for (int j = 0; j < 4; j++) {
            int n = n0 + tx*4 + j;
            if (n < 512) d_da[m*512 + n] = acc[i][j] + bd[n];
            else         d_gate[m*512 + (n-512)] = sigmoidf_(acc[i][j] + bg[n-512]);
        }
    }
}

// ---------------- preds (NTILE=128): issue + body ------------------------------
__device__ __forceinline__ void preds_issue(uint32_t* Asm, uint32_t* Wsm,
        int stage, int kt, int n0, int tid, const uint4* hph, const uint4* hpl) {
    uint32_t* As = Asm + stage*(64*36);
    uint32_t* Ws = Wsm + stage*(NTILE*36);
    #pragma unroll
    for (int u = 0; u < 2; u++) {
        int cid = tid + u*256;
        int row = cid >> 3, c = cid & 7;
        const uint4* src = ((c < 4) ? hph : hpl) + row*64 + kt*4 + (c & 3);
        uint32_t* dst = As + row*36 + ((c < 4) ? c*4 : 16 + (c - 4)*4);
        __pipeline_memcpy_async(dst, src, 16);
    }
    const uint4* wh = (const uint4*)d_wfh16;
    const uint4* wl = (const uint4*)d_wfl16;
    #pragma unroll
    for (int u = 0; u < 4; u++) {      // 128 rows x 8 chunks = 1024
        int cid = tid + u*256;
        int row = cid >> 3, c = cid & 7;
        const uint4* src = ((c < 4) ? wh : wl) + (size_t)(n0 + row)*64 + kt*4 + (c & 3);
        uint32_t* dst = Ws + row*36 + ((c < 4) ? c*4 : 16 + (c - 4)*4);
        cp_async16_ef(dst, src);       // W_fc: single-use stream, evict_first
    }
    __pipeline_commit();
}

__device__ void preds_body(int j, uint32_t* sm, int tid,
                           const float* __restrict__ bfc,
                           float* __restrict__ out_pred, int n0) {
    int nact = d_nact[j];
    int mfmax = (nact + 15) >> 4;
    int hb = (j + 1) & 1;
    uint32_t* Asm = sm;
    uint32_t* Wsm = sm + 2*64*36;

    int lane = tid & 31, wp = tid >> 5;
    int g = lane >> 2, tig = lane & 3;
    const uint4* hph = (const uint4*)d_hph[hb];
    const uint4* hpl = (const uint4*)d_hpl[hb];

    float acc[4][2][4];
    #pragma unroll
    for (int a = 0; a < 4; a++)
        #pragma unroll
        for (int b2 = 0; b2 < 2; b2++)
            #pragma unroll
            for (int c2 = 0; c2 < 4; c2++) acc[a][b2][c2] = 0.f;

    preds_issue(Asm, Wsm, 0, 0, n0, tid, hph, hpl);
    for (int kt = 0; kt < 16; kt++) {
        int stage = kt & 1;
        if (kt < 15) {
            preds_issue(Asm, Wsm, stage ^ 1, kt + 1, n0, tid, hph, hpl);
            __pipeline_wait_prior(1);
        } else {
            __pipeline_wait_prior(0);
        }
        __syncthreads();
        const uint32_t* Ahs = Asm + stage*(64*36);
        const uint32_t* Whs = Wsm + stage*(NTILE*36);
        #pragma unroll
        for (int ks = 0; ks < 2; ks++) {
            int ko = ks*8 + tig;
            uint32_t ah[4][4], al[4][4];
            #pragma unroll
            for (int mf = 0; mf < 4; mf++) {
                if (mf >= mfmax) continue;
                int r0 = (mf*16 + g)*36, r1 = (mf*16 + g + 8)*36;
                ah[mf][0] = Ahs[r0 + ko];      ah[mf][1] = Ahs[r1 + ko];
                ah[mf][2] = Ahs[r0 + ko + 4];  ah[mf][3] = Ahs[r1 + ko + 4];
                al[mf][0] = Ahs[r0 + 16 + ko];     al[mf][1] = Ahs[r1 + 16 + ko];
                al[mf][2] = Ahs[r0 + 16 + ko + 4]; al[mf][3] = Ahs[r1 + 16 + ko + 4];
            }
            #pragma unroll
            for (int nf = 0; nf < 2; nf++) {
                int rw = (wp*16 + nf*8 + g)*36 + ko;
                uint32_t bh0 = Whs[rw], bh1 = Whs[rw + 4];
                uint32_t bl0 = Whs[rw + 16], bl1 = Whs[rw + 20];
                #pragma unroll
                for (int mf = 0; mf < 4; mf++) {
                    if (mf >= mfmax) continue;
                    mma_bf16(acc[mf][nf], ah[mf][0], ah[mf][1], ah[mf][2], ah[mf][3], bh0, bh1);
                    mma_bf16(acc[mf][nf], al[mf][0], al[mf][1], al[mf][2], al[mf][3], bh0, bh1);
                    mma_bf16(acc[mf][nf], ah[mf][0], ah[mf][1], ah[mf][2], ah[mf][3], bl0, bl1);
                }
            }
        }
        __syncthreads();
    }

    size_t tbase = (size_t)j * VV;
    #pragma unroll
    for (int nf = 0; nf < 2; nf++) {
        int n = n0 + wp*16 + nf*8 + 2*tig;
        float2 bb = *(const float2*)&bfc[n];
        #pragma unroll
        for (int mf = 0; mf < 4; mf++) {
            int m1 = mf*16 + g;
            float o1x = (m1 < nact) ? acc[mf][nf][0] + bb.x : 0.f;
            float o1y = (m1 < nact) ? acc[mf][nf][1] + bb.y : 0.f;
            st_cs_f2(&out_pred[(size_t)m1*((size_t)TT*VV) + tbase + n], o1x, o1y);
            int m2 = m1 + 8;
            float o2x = (m2 < nact) ? acc[mf][nf][2] + bb.x : 0.f;
            float o2y = (m2 < nact) ? acc[mf][nf][3] + bb.y : 0.f;
            st_cs_f2(&out_pred[(size_t)m2*((size_t)TT*VV) + tbase + n], o2x, o2y);
        }
    }
}

// ---------------- phase-B issue: A from packed (emb|ctx|h), W from wihh -------
__device__ __forceinline__ void lstm_issue(uint32_t* Asm, uint32_t* Wsm,
        int stage, int c0, int n0, int tid, int t, int hb) {
    uint32_t* As = Asm + stage*(64*36);
    uint32_t* Ws = Wsm + stage*(256*36);
    const uint4* ah4; const uint4* al4; int off4;
    if (c0 < 512) {
        ah4 = (const uint4*)d_embp_h + (size_t)t*BSZ*64;
        al4 = (const uint4*)d_embp_l + (size_t)t*BSZ*64;
        off4 = c0 >> 3;
    } else if (c0 < 1024) {
        ah4 = (const uint4*)d_ctxp_h;
        al4 = (const uint4*)d_ctxp_l;
        off4 = (c0 - 512) >> 3;
    } else {
        ah4 = (const uint4*)d_hph[hb];
        al4 = (const uint4*)d_hpl[hb];
        off4 = (c0 - 1024) >> 3;
    }
    #pragma unroll
    for (int u = 0; u < 2; u++) {
        int cid = tid + u*256;
        int row = cid >> 3, c = cid & 7;
        const uint4* src = ((c < 4) ? ah4 : al4) + (size_t)row*64 + off4 + (c & 3);
        uint32_t* dst = As + row*36 + ((c < 4) ? c*4 : 16 + (c - 4)*4);
        __pipeline_memcpy_async(dst, src, 16);
    }
    const uint4* wh = (const uint4*)d_wihh_h;
    const uint4* wl = (const uint4*)d_wihh_l;
    int woff4 = c0 >> 3;
    #pragma unroll
    for (int u = 0; u < 8; u++) {
        int cid = tid + u*256;
        int row = cid >> 3, c = cid & 7;
        const uint4* src = ((c < 4) ? wh : wl) + (size_t)(n0 + row)*192 + woff4 + (c & 3);
        uint32_t* dst = Ws + row*36 + ((c < 4) ? c*4 : 16 + (c - 4)*4);
        __pipeline_memcpy_async(dst, src, 16);
    }
    __pipeline_commit();
}

// ---------------- phase-D issue: 64-k per stage, stride 68 --------------------
__device__ __forceinline__ void dg_issue64(uint32_t* Asm, uint32_t* Wsm,
        int stage, int kt, int n0, int tid, int hbw) {
    uint32_t* As = Asm + stage*(64*68);
    uint32_t* Ws = Wsm + stage*(64*68);
    const uint4* ah4 = (const uint4*)d_hph[hbw];
    const uint4* al4 = (const uint4*)d_hpl[hbw];
    #pragma unroll
    for (int u = 0; u < 4; u++) {
        int cid = tid + u*256;          // 0..1023
        int row = cid >> 4, c = cid & 15;
        const uint4* src = ((c < 8) ? ah4 : al4) + (size_t)row*64 + kt*8 + (c & 7);
        uint32_t* dst = As + row*68 + ((c < 8) ? c*4 : 32 + (c - 8)*4);
        __pipeline_memcpy_async(dst, src, 16);
    }
    const uint4* wh = (const uint4*)d_wdg_h;
    const uint4* wl = (const uint4*)d_wdg_l;
    #pragma unroll
    for (int u = 0; u < 4; u++) {
        int cid = tid + u*256;
        int row = cid >> 4, c = cid & 15;
        const uint4* src = ((c < 8) ? wh : wl) + (size_t)(n0 + row)*64 + kt*8 + (c & 7);
        uint32_t* dst = Ws + row*68 + ((c < 8) ? c*4 : 32 + (c - 8)*4);
        __pipeline_memcpy_async(dst, src, 16);
    }
    __pipeline_commit();
}

// ============ FUSED: recurrence(t) on blocks 0..63 || preds(t-1) on 64+ =======
__global__ void __launch_bounds__(256, 2) fused_kernel(int t,
        const float* __restrict__ wf, const float* __restrict__ bf_scalar,
        const float* __restrict__ bih, const float* __restrict__ bhh,
        const float* __restrict__ bd, const float* __restrict__ bg,
        const float* __restrict__ bfc,
        float* __restrict__ out_alphas, float* __restrict__ out_pred) {
    extern __shared__ __align__(16) uint32_t smem_u[];
    int bid = blockIdx.x;
    int tid = threadIdx.x;

    if (bid >= RBLK) {                     // ---- preds for step t-1 ----
        if (t >= 1) preds_body(t - 1, smem_u, tid, bfc, out_pred, (bid - RBLK) * NTILE);
        return;
    }
    if (t >= TT) return;

    int hb  = t & 1;
    int hbw = (t + 1) & 1;

    // ---------------- phase A: attention (blocks 0..63) -----------------------
    if (t < d_declen[bid]) {
        int b = bid;
        int lane = tid & 31, warp = tid >> 5;
        float4* s_da = (float4*)smem_u;
        float4* s_wf = s_da + 128;
        float*  sc   = (float*)(s_wf + 128);
        float*  red  = sc + 200;

        if (tid < 128) {
            s_da[tid] = ((const float4*)d_da)[b*128 + tid];
            s_wf[tid] = ((const float4*)wf)[tid];
        }
        __syncthreads();

        const float4* ea4 = ((const float4*)d_ea) + (size_t)b*NPIX*128;
        float bfull = bf_scalar[0];
        for (int p0 = warp*2; p0 < NPIX; p0 += 16) {
            int p1 = p0 + 1;
            float s0 = 0.f, s1 = 0.f;
            #pragma unroll
            for (int j = 0; j < 4; j++) {
                int k4 = lane + j*32;
                float4 e0 = ea4[p0*128 + k4];
                float4 e1 = ea4[p1*128 + k4];
                float4 da = s_da[k4];
                float4 w  = s_wf[k4];
                s0 += fmaxf(e0.x + da.x, 0.f) * w.x;
                s0 += fmaxf(e0.y + da.y, 0.f) * w.y;
                s0 += fmaxf(e0.z + da.z, 0.f) * w.z;
                s0 += fmaxf(e0.w + da.w, 0.f) * w.w;
                s1 += fmaxf(e1.x + da.x, 0.f) * w.x;
                s1 += fmaxf(e1.y + da.y, 0.f) * w.y;
                s1 += fmaxf(e1.z + da.z, 0.f) * w.z;
                s1 += fmaxf(e1.w + da.w, 0.f) * w.w;
            }
            s0 = warp_sum(s0);
            s1 = warp_sum(s1);
            if (lane == 0) { sc[p0] = s0 + bfull; sc[p1] = s1 + bfull; }
        }
        __syncthreads();

        float v = (tid < NPIX) ? sc[tid] : -1e30f;
        float wm = warp_max(v);
        if (lane == 0) red[warp] = wm;
        __syncthreads();
        if (tid == 0) {
            float mm = red[0];
            #pragma unroll
            for (int i = 1; i < 8; i++) mm = fmaxf(mm, red[i]);
            red[16] = mm;
        }
        __syncthreads();
        float gmax = red[16];
        float e = (tid < NPIX) ? __expf(v - gmax) : 0.f;
        float ws = warp_sum(e);
        if (lane == 0) red[8 + warp] = ws;
        __syncthreads();
        if (tid == 0) {
            float ss = 0.f;
            #pragma unroll
            for (int i = 0; i < 8; i++) ss += red[8 + i];
            red[17] = ss;
        }
        __syncthreads();
        float alpha = e / red[17];
        __syncthreads();
        if (tid < NPIX) {
            sc[tid] = alpha;
            out_alphas[(size_t)b*TT*NPIX + (size_t)t*NPIX + tid] = alpha;
        }
        __syncthreads();

        const float2* encb2 = (const float2*)(d_enc_s + (size_t)b*NPIX*512);
        float sx[16], sy[16];
        #pragma unroll
        for (int u = 0; u < 16; u++) { sx[u] = 0.f; sy[u] = 0.f; }
        #pragma unroll 2
        for (int p0 = 0; p0 < 192; p0 += 16) {
            #pragma unroll
            for (int u = 0; u < 16; u++) {
                float2 vv = encb2[(p0+u)*256 + tid];
                float al = sc[p0+u];
                sx[u] += al * vv.x;
                sy[u] += al * vv.y;
            }
        }
        #pragma unroll
        for (int u = 0; u < 4; u++) {
            float2 vv = encb2[(192+u)*256 + tid];
            float al = sc[192+u];
            sx[u] += al * vv.x;
            sy[u] += al * vv.y;
        }
        float X = 0.f, Y = 0.f;
        #pragma unroll
        for (int u = 0; u < 16; u++) { X += sx[u]; Y += sy[u]; }
        float2 g2 = ((const float2*)d_gate)[b*256 + tid];
        float cx = X * g2.x, cy = Y * g2.y;
        uint32_t chi, clo; bfsplit2(cx, cy, chi, clo);
        d_ctxp_h[b*256 + tid] = chi;
        d_ctxp_l[b*256 + tid] = clo;
    }
    rec_bar(tid);

    // ---------------- phase B: LSTM gate GEMM via mma (64 blocks) -------------
    {
        uint32_t* Asm = smem_u;
        uint32_t* Wsm = smem_u + 2*64*36;
        int n0 = (bid & 7) * 256;
        int ksplit = bid >> 3;
        int kbase = ksplit * 192;
        int lane = tid & 31, wp = tid >> 5;
        int g = lane >> 2, tig = lane & 3;

        float acc[4][4][4];
        #pragma unroll
        for (int a = 0; a < 4; a++)
            #pragma unroll
            for (int b2 = 0; b2 < 4; b2++)
                #pragma unroll
                for (int c2 = 0; c2 < 4; c2++) acc[a][b2][c2] = 0.f;

        lstm_issue(Asm, Wsm, 0, kbase, n0, tid, t, hb);
        for (int kt = 0; kt < 6; kt++) {
            int stage = kt & 1;
            if (kt < 5) {
                lstm_issue(Asm, Wsm, stage ^ 1, kbase + (kt+1)*32, n0, tid, t, hb);
                __pipeline_wait_prior(1);
            } else {
                __pipeline_wait_prior(0);
            }
            __syncthreads();
            const uint32_t* Ahs = Asm + stage*(64*36);
            const uint32_t* Whs = Wsm + stage*(256*36);
            #pragma unroll
            for (int ks = 0; ks < 2; ks++) {
                int ko = ks*8 + tig;
                uint32_t ah[4][4], al[4][4];
                #pragma unroll
                for (int mf = 0; mf < 4; mf++) {
                    int r0 = (mf*16 + g)*36, r1 = (mf*16 + g + 8)*36;
                    ah[mf][0] = Ahs[r0 + ko];      ah[mf][1] = Ahs[r1 + ko];
                    ah[mf][2] = Ahs[r0 + ko + 4];  ah[mf][3] = Ahs[r1 + ko + 4];
                    al[mf][0] = Ahs[r0 + 16 + ko];     al[mf][1] = Ahs[r1 + 16 + ko];
                    al[mf][2] = Ahs[r0 + 16 + ko + 4]; al[mf][3] = Ahs[r1 + 16 + ko + 4];
                }
                #pragma unroll
                for (int nf = 0; nf < 4; nf++) {
                    int rw = (wp*32 + nf*8 + g)*36 + ko;
                    uint32_t bh0 = Whs[rw], bh1 = Whs[rw + 4];
                    uint32_t bl0 = Whs[rw + 16], bl1 = Whs[rw + 20];
                    #pragma unroll
                    for (int mf = 0; mf < 4; mf++) {
                        mma_bf16(acc[mf][nf], ah[mf][0], ah[mf][1], ah[mf][2], ah[mf][3], bh0, bh1);
                        mma_bf16(acc[mf][nf], al[mf][0], al[mf][1], al[mf][2], al[mf][3], bh0, bh1);
                        mma_bf16(acc[mf][nf], ah[mf][0], ah[mf][1], ah[mf][2], ah[mf][3], bl0, bl1);
                    }
                }
            }
            __syncthreads();
        }

        float* gp = d_gates_p + (size_t)ksplit * (BSZ*2048);
        #pragma unroll
        for (int nf = 0; nf < 4; nf++) {
            int n = n0 + wp*32 + nf*8 + 2*tig;
            #pragma unroll
            for (int mf = 0; mf < 4; mf++) {
                int m1 = mf*16 + g;
                float2 o1; o1.x = acc[mf][nf][0]; o1.y = acc[mf][nf][1];
                *(float2*)&gp[m1*2048 + n] = o1;
                int m2 = m1 + 8;
                float2 o2; o2.x = acc[mf][nf][2]; o2.y = acc[mf][nf][3];
                *(float2*)&gp[m2*2048 + n] = o2;
            }
        }
    }
    rec_bar(tid);

    // ---------------- phase C: LSTM apply + bf16 pack (blocks 0..15) ----------
    if (bid < 16) {
        int gid = bid*256 + tid;
        int idx0 = gid*8;
        int b = idx0 >> 9;
        int f0 = (idx0 & 511) >> 2;
        float acc[4][8];
        #pragma unroll
        for (int q = 0; q < 4; q++)
            #pragma unroll
            for (int e = 0; e < 8; e++) acc[q][e] = 0.f;
        #pragma unroll
        for (int s = 0; s < NSPLIT; s++) {
            const float4* g4 = (const float4*)(d_gates_p + (size_t)s*(BSZ*2048) + b*2048);
            #pragma unroll
            for (int q = 0; q < 4; q++) {
                float4 v0 = g4[q*128 + f0];
                float4 v1 = g4[q*128 + f0 + 1];
                acc[q][0] += v0.x; acc[q][1] += v0.y; acc[q][2] += v0.z; acc[q][3] += v0.w;
                acc[q][4] += v1.x; acc[q][5] += v1.y; acc[q][6] += v1.z; acc[q][7] += v1.w;
            }
        }
        const float4* bi4 = (const float4*)bih;
        const float4* bh4 = (const float4*)bhh;
        #pragma unroll
        for (int q = 0; q < 4; q++) {
            float4 u0 = bi4[q*128 + f0], u1 = bi4[q*128 + f0 + 1];
            float4 w0 = bh4[q*128 + f0], w1 = bh4[q*128 + f0 + 1];
            acc[q][0] += u0.x + w0.x; acc[q][1] += u0.y + w0.y;
            acc[q][2] += u0.z + w0.z; acc[q][3] += u0.w + w0.w;
            acc[q][4] += u1.x + w1.x; acc[q][5] += u1.y + w1.y;
            acc[q][6] += u1.z + w1.z; acc[q][7] += u1.w + w1.w;
        }
        float hv[8];
        #pragma unroll
        for (int e = 0; e < 8; e++) {
            float ig = sigmoidf_(acc[0][e]);
            float fg = sigmoidf_(acc[1][e]);
            float g2 = tanhf(acc[2][e]);
            float og = sigmoidf_(acc[3][e]);
            float c  = fg * d_c[idx0 + e] + ig * g2;
            float h  = og * tanhf(c);
            d_c[idx0 + e] = c;
            hv[e] = h;
        }
        uint4 ph, pl;
        bfsplit2(hv[0], hv[1], ph.x, pl.x);
        bfsplit2(hv[2], hv[3], ph.y, pl.y);
        bfsplit2(hv[4], hv[5], ph.z, pl.z);
        bfsplit2(hv[6], hv[7], ph.w, pl.w);
        ((uint4*)d_hph[hbw])[gid] = ph;
        ((uint4*)d_hpl[hbw])[gid] = pl;
    }
    rec_bar(tid);

    // ---------------- phase D: dagate via mma (blocks 0..15, 8 stages) --------
    if (bid < 16) {
        uint32_t* Asm = smem_u;              // [2][64*68]
        uint32_t* Wsm = smem_u + 2*64*68;    // [2][64*68]
        int n0 = bid * 64;
        int lane = tid & 31, wp = tid >> 5;
        int g = lane >> 2, tig = lane & 3;

        float acc[4][4];
        #pragma unroll
        for (int a = 0; a < 4; a++)
            #pragma unroll
            for (int c2 = 0; c2 < 4; c2++) acc[a][c2] = 0.f;

        dg_issue64(Asm, Wsm, 0, 0, n0, tid, hbw);
        for (int kt = 0; kt < 8; kt++) {
            int stage = kt & 1;
            if (kt < 7) {
                dg_issue64(Asm, Wsm, stage ^ 1, kt + 1, n0, tid, hbw);
                __pipeline_wait_prior(1);
            } else {
                __pipeline_wait_prior(0);
            }
            __syncthreads();
            const uint32_t* Ahs = Asm + stage*(64*68);
            const uint32_t* Whs = Wsm + stage*(64*68);
            #pragma unroll
            for (int ks = 0; ks < 4; ks++) {
                int ko = ks*8 + tig;
                int rw = (wp*8 + g)*68 + ko;
                uint32_t bh0 = Whs[rw], bh1 = Whs[rw + 4];
                uint32_t bl0 = Whs[rw + 32], bl1 = Whs[rw + 36];
                #pragma unroll
                for (int mf = 0; mf < 4; mf++) {
                    int r0 = (mf*16 + g)*68, r1 = (mf*16 + g + 8)*68;
                    uint32_t a0 = Ahs[r0 + ko],      a1 = Ahs[r1 + ko];
                    uint32_t a2 = Ahs[r0 + ko + 4],  a3 = Ahs[r1 + ko + 4];
                    uint32_t l0 = Ahs[r0 + 32 + ko],     l1 = Ahs[r1 + 32 + ko];
                    uint32_t l2 = Ahs[r0 + 32 + ko + 4], l3 = Ahs[r1 + 32 + ko + 4];
                    mma_bf16(acc[mf], a0, a1, a2, a3, bh0, bh1);
                    mma_bf16(acc[mf], l0, l1, l2, l3, bh0, bh1);
                    mma_bf16(acc[mf], a0, a1, a2, a3, bl0, bl1);
                }
            }
            __syncthreads();
        }

        int n = n0 + wp*8 + 2*tig;
        #pragma unroll
        for (int mf = 0; mf < 4; mf++) {
            int m1 = mf*16 + g;
            int m2 = m1 + 8;
            if (n < 512) {
                float2 bb = *(const float2*)&bd[n];
                float2 o1; o1.x = acc[mf][0] + bb.x; o1.y = acc[mf][1] + bb.y;
                *(float2*)&d_da[m1*512 + n] = o1;
                float2 o2; o2.x = acc[mf][2] + bb.x; o2.y = acc[mf][3] + bb.y;
                *(float2*)&d_da[m2*512 + n] = o2;
            } else {
                int ng = n - 512;
                float2 bb = *(const float2*)&bg[ng];
                float2 o1; o1.x = sigmoidf_(acc[mf][0] + bb.x); o1.y = sigmoidf_(acc[mf][1] + bb.y);
                *(float2*)&d_gate[m1*512 + ng] = o1;
                float2 o2; o2.x = sigmoidf_(acc[mf][2] + bb.x); o2.y = sigmoidf_(acc[mf][3] + bb.y);
                *(float2*)&d_gate[m2*512 + ng] = o2;
            }
        }
    }
}

// ---------------- launch ------------------------------------------------------
extern "C" void kernel_launch(void* const* d_in, const int* in_sizes, int n_in,
                              void* d_out, int out_size) {
    const float* encoder_out = (const float*)d_in[0];
    const int*   caps        = (const int*)  d_in[1];
    const int*   cap_len     = (const int*)  d_in[2];
    const float* W_enc_attn  = (const float*)d_in[3];
    const float* b_enc_attn  = (const float*)d_in[4];
    const float* W_dec_attn  = (const float*)d_in[5];
    const float* b_dec_attn  = (const float*)d_in[6];
    const float* w_full_attn = (const float*)d_in[7];
    const float* b_full_attn = (const float*)d_in[8];
    const float* emb_table   = (const float*)d_in[9];
    const float* W_ih        = (const float*)d_in[10];
    const float* W_hh        = (const float*)d_in[11];
    const float* b_ih        = (const float*)d_in[12];
    const float* b_hh        = (const float*)d_in[13];
    const float* W_init_h    = (const float*)d_in[14];
    const float* b_init_h    = (const float*)d_in[15];
    const float* W_init_c    = (const float*)d_in[16];
    const float* b_init_c    = (const float*)d_in[17];
    const float* W_f_beta    = (const float*)d_in[18];
    const float* b_f_beta    = (const float*)d_in[19];
    const float* W_fc        = (const float*)d_in[20];
    const float* b_fc        = (const float*)d_in[21];

    float* out = (float*)d_out;
    const size_t OFF_PRED   = 0;
    const size_t OFF_CAPS   = OFF_PRED + (size_t)BSZ*TT*VV;
    const size_t OFF_DECLEN = OFF_CAPS + (size_t)BSZ*ML;
    const size_t OFF_ALPHA  = OFF_DECLEN + BSZ;
    const size_t OFF_ORDER  = OFF_ALPHA + (size_t)BSZ*TT*NPIX;
    float* out_pred   = out + OFF_PRED;
    float* out_caps   = out + OFF_CAPS;
    float* out_declen = out + OFF_DECLEN;
    float* out_alphas = out + OFF_ALPHA;
    float* out_order  = out + OFF_ORDER;

    static cudaStream_t s2 = nullptr;
    static cudaEvent_t evRoot, evCvt;
    static bool inited = false;
    const int FUSED_SMEM = (2*64*36 + 2*256*36) * 4;   // 92160 B (>= 4*64*68*4)
    const int EA_SMEM = (64*36 + 256*36) * 4;          // 46080 B
    if (!inited) {
        cudaStreamCreateWithFlags(&s2, cudaStreamNonBlocking);
        cudaEventCreateWithFlags(&evRoot, cudaEventDisableTiming);
        cudaEventCreateWithFlags(&evCvt, cudaEventDisableTiming);
        cudaFuncSetAttribute(fused_kernel, cudaFuncAttributeMaxDynamicSharedMemorySize,
                             FUSED_SMEM);
        cudaFuncSetAttribute(ea_mma_kernel, cudaFuncAttributeMaxDynamicSharedMemorySize,
                             EA_SMEM);
        inited = true;
    }

    size_t tail = (size_t)out_size - OFF_CAPS;
    cudaMemsetAsync(out + OFF_CAPS, 0, tail * sizeof(float));

    // weight converts on s2, overlapped with main prologue on stream 0
    cudaEventRecord(evRoot, 0);
    cudaStreamWaitEvent(s2, evRoot, 0);
    convert_wfc_kernel<<<(VV*64)/256, 256, 0, s2>>>((const float4*)W_fc);
    convert_wihh_kernel<<<(2048*768)/256, 256, 0, s2>>>(W_ih, W_hh);
    convert_wdg_kernel<<<(1024*256)/256, 256, 0, s2>>>(W_dec_attn, W_f_beta);
    cudaEventRecord(evCvt, s2);

    sort_kernel<<<1, 64>>>(cap_len, caps, out_caps, out_declen, out_order);
    convert_emb_kernel<<<dim3(BSZ, ML), 256>>>(emb_table);
    reorder_mean_kernel<<<BSZ, 256>>>(encoder_out);
    ea_mma_kernel<<<dim3(2, 196), 256, EA_SMEM>>>(W_enc_attn, b_enc_attn);
    gemm64_kernel<<<dim3(8, 1), 256>>>(1, W_init_h, b_init_h, 512, 512);
    gemm64_kernel<<<dim3(8, 1), 256>>>(2, W_init_c, b_init_c, 512, 512);
    convert_h0_kernel<<<64, 256>>>();
    dagate_kernel<<<16, 256>>>(W_dec_attn, b_dec_attn, W_f_beta, b_f_beta);

    cudaStreamWaitEvent((cudaStream_t)0, evCvt, 0);

    for (int t = 0; t <= TT; t++) {
        fused_kernel<<<GRID, 256, FUSED_SMEM>>>(t, w_full_attn, b_full_attn,
                                                b_ih, b_hh, b_dec_attn, b_f_beta,
                                                b_fc, out_alphas, out_pred);
    }
}

// round 16
// speedup vs baseline: 1.8998x; 1.1019x over previous
#include <cuda_runtime.h>
#include <cuda_bf16.h>
#include <cuda_pipeline.h>
#include <math.h>
#include <stdint.h>

#define BSZ 64
#define NPIX 196
#define ENCD 512
#define DD 512
#define VV 32000
#define TT 50
#define ML 51
#define NSPLIT 8
#define RBLK 64                  // recurrence blocks (barrier group)
#define NTILE 128                // preds n-tile width
#define PBLK (VV/NTILE)          // 250 preds blocks
#define GRID (RBLK + PBLK)       // 314

// ---------------- scratch (static device globals; no runtime alloc) ----------
__device__ float d_enc_s[BSZ*NPIX*ENCD];
__device__ float d_ea[BSZ*NPIX*ENCD];
__device__ float d_mean[BSZ*ENCD];
__device__ float d_hbuf[BSZ*DD];             // prologue h0 only
__device__ uint32_t d_hph[2][BSZ*DD/2];      // h bf16-hi pairs
__device__ uint32_t d_hpl[2][BSZ*DD/2];      // h bf16-lo pairs
__device__ float d_c[BSZ*DD];
__device__ uint32_t d_ctxp_h[BSZ*DD/2];      // ctx bf16 packed
__device__ uint32_t d_ctxp_l[BSZ*DD/2];
__device__ float d_da[BSZ*DD];
__device__ float d_gate[BSZ*ENCD];
__device__ float d_gates_p[NSPLIT*BSZ*4*DD];
__device__ uint32_t d_wfh16[(size_t)VV*256];   // W_fc bf16 hi
__device__ uint32_t d_wfl16[(size_t)VV*256];   // W_fc bf16 lo
__device__ uint32_t d_wihh_h[2048*768];        // [Wih|Whh] bf16 hi (k-pairs)
__device__ uint32_t d_wihh_l[2048*768];
__device__ uint32_t d_wdg_h[1024*256];         // [Wd;Wg] bf16 hi
__device__ uint32_t d_wdg_l[1024*256];
__device__ uint32_t d_embp_h[(size_t)ML*BSZ*256];  // sorted emb rows packed
__device__ uint32_t d_embp_l[(size_t)ML*BSZ*256];
__device__ unsigned int d_bar;
__device__ int   d_order[BSZ];
__device__ int   d_declen[BSZ];
__device__ int   d_caps_s[BSZ*ML];
__device__ int   d_nact[TT];

// ---------------- helpers ----------------------------------------------------
__device__ __forceinline__ float warp_sum(float v) {
    #pragma unroll
    for (int o = 16; o > 0; o >>= 1) v += __shfl_down_sync(0xffffffffu, v, o);
    return v;
}
__device__ __forceinline__ float warp_max(float v) {
    #pragma unroll
    for (int o = 16; o > 0; o >>= 1) v = fmaxf(v, __shfl_down_sync(0xffffffffu, v, o));
    return v;
}
__device__ __forceinline__ float sigmoidf_(float x) { return 1.0f / (1.0f + __expf(-x)); }

__device__ __forceinline__ void bfsplit2(float a, float b, uint32_t& hi, uint32_t& lo) {
    __nv_bfloat162 h2 = __floats2bfloat162_rn(a, b);
    float ra = a - __bfloat162float(h2.x);
    float rb = b - __bfloat162float(h2.y);
    __nv_bfloat162 l2 = __floats2bfloat162_rn(ra, rb);
    hi = *(uint32_t*)&h2;
    lo = *(uint32_t*)&l2;
}

__device__ __forceinline__ void mma_bf16(float c[4], uint32_t a0, uint32_t a1,
                                         uint32_t a2, uint32_t a3,
                                         uint32_t b0, uint32_t b1) {
    asm volatile(
        "mma.sync.aligned.m16n8k16.row.col.f32.bf16.bf16.f32 "
        "{%0,%1,%2,%3}, {%4,%5,%6,%7}, {%8,%9}, {%0,%1,%2,%3};\n"
        : "+f"(c[0]), "+f"(c[1]), "+f"(c[2]), "+f"(c[3])
        : "r"(a0), "r"(a1), "r"(a2), "r"(a3), "r"(b0), "r"(b1));
}

// cp.async 16B with L2 evict_first policy (single-use streaming weights)
__device__ __forceinline__ void cp_async16_ef(void* dst_smem, const void* src) {
    uint32_t d = (uint32_t)__cvta_generic_to_shared(dst_smem);
    asm volatile(
        "{\n\t.reg .b64 p;\n\t"
        "createpolicy.fractional.L2::evict_first.b64 p, 1.0;\n\t"
        "cp.async.cg.shared.global.L2::cache_hint [%0], [%1], 16, p;\n\t}"
        :: "r"(d), "l"(src) : "memory");
}

// streaming float2 store (avoid polluting L2 with prediction output)
__device__ __forceinline__ void st_cs_f2(float* p, float x, float y) {
    asm volatile("st.global.cs.v2.f32 [%0], {%1, %2};"
                 :: "l"(p), "f"(x), "f"(y) : "memory");
}

// barrier among the first RBLK blocks only: atomic arrive, acquire-poll
__device__ __forceinline__ void rec_bar(int tid) {
    __threadfence();
    __syncthreads();
    if (tid == 0) {
        unsigned t0 = atomicAdd(&d_bar, 1u);
        unsigned target = t0 - (t0 % RBLK) + RBLK;
        unsigned v;
        do {
            asm volatile("ld.global.acquire.gpu.u32 %0, [%1];" : "=r"(v) : "l"(&d_bar));
        } while (v < target);
    }
    __syncthreads();
}

// ---------------- one-time converts -------------------------------------------
__global__ __launch_bounds__(256) void convert_wfc_kernel(const float4* __restrict__ W) {
    size_t gi = (size_t)blockIdx.x*256 + threadIdx.x;
    float4 v0 = W[gi*2];
    float4 v1 = W[gi*2+1];
    uint4 h, l;
    bfsplit2(v0.x, v0.y, h.x, l.x);
    bfsplit2(v0.z, v0.w, h.y, l.y);
    bfsplit2(v1.x, v1.y, h.z, l.z);
    bfsplit2(v1.z, v1.w, h.w, l.w);
    ((uint4*)d_wfh16)[gi] = h;
    ((uint4*)d_wfl16)[gi] = l;
}

__global__ __launch_bounds__(256) void convert_wihh_kernel(
        const float* __restrict__ Wih, const float* __restrict__ Whh) {
    int idx = blockIdx.x*256 + threadIdx.x;
    int n = idx / 768, p = idx % 768;
    int k = p * 2;
    float a, b;
    if (k < 1024) { a = Wih[(size_t)n*1024 + k]; b = Wih[(size_t)n*1024 + k + 1]; }
    else          { a = Whh[(size_t)n*512 + (k-1024)]; b = Whh[(size_t)n*512 + (k-1023)]; }
    uint32_t hi, lo; bfsplit2(a, b, hi, lo);
    d_wihh_h[idx] = hi; d_wihh_l[idx] = lo;
}

__global__ __launch_bounds__(256) void convert_wdg_kernel(
        const float* __restrict__ Wd, const float* __restrict__ Wg) {
    int idx = blockIdx.x*256 + threadIdx.x;
    int n = idx >> 8, p = idx & 255;
    int k = p * 2;
    const float* W = (n < 512) ? (Wd + (size_t)n*512) : (Wg + (size_t)(n-512)*512);
    uint32_t hi, lo; bfsplit2(W[k], W[k+1], hi, lo);
    d_wdg_h[idx] = hi; d_wdg_l[idx] = lo;
}

__global__ __launch_bounds__(256) void convert_emb_kernel(const float* __restrict__ emb) {
    int b = blockIdx.x, tt = blockIdx.y, tid = threadIdx.x;
    int tok = d_caps_s[b*ML + tt];
    const float* src = emb + (size_t)tok*512 + tid*2;
    uint32_t hi, lo; bfsplit2(src[0], src[1], hi, lo);
    size_t o = ((size_t)tt*BSZ + b)*256 + tid;
    d_embp_h[o] = hi; d_embp_l[o] = lo;
}

__global__ __launch_bounds__(256) void convert_h0_kernel() {
    int pid = blockIdx.x*256 + threadIdx.x;
    float a = d_hbuf[pid*2];
    float b = d_hbuf[pid*2+1];
    uint32_t hi, lo; bfsplit2(a, b, hi, lo);
    d_hph[0][pid] = hi; d_hpl[0][pid] = lo;
}

// ---------------- sort (stable, descending cap_len) ---------------------------
__global__ void sort_kernel(const int* __restrict__ cap_len,
                            const int* __restrict__ caps,
                            float* __restrict__ out_caps,
                            float* __restrict__ out_declen,
                            float* __restrict__ out_order) {
    int i = threadIdx.x;
    int cl = cap_len[i];
    int r = 0;
    for (int j = 0; j < BSZ; j++) {
        int cj = cap_len[j];
        if (cj > cl || (cj == cl && j < i)) r++;
    }
    d_order[r]  = i;
    d_declen[r] = cl - 1;
    __syncthreads();
    out_order[i]  = (float)d_order[i];
    out_declen[i] = (float)d_declen[i];
    int src = d_order[i];
    for (int tt = 0; tt < ML; tt++) {
        int tok = caps[src*ML + tt];
        d_caps_s[i*ML + tt] = tok;
        out_caps[i*ML + tt] = (float)tok;
    }
    if (i < TT) {
        int cnt = 0;
        for (int j = 0; j < BSZ; j++) if (d_declen[j] > i) cnt++;
        d_nact[i] = cnt;
    }
}

// ---------------- reorder encoder + per-batch pixel mean ----------------------
__global__ __launch_bounds__(256) void reorder_mean_kernel(const float* __restrict__ enc) {
    int b = blockIdx.x;
    int tid = threadIdx.x;
    int src = d_order[b];
    const float* Ein = enc + (size_t)src*NPIX*ENCD;
    float* Eo = d_enc_s + (size_t)b*NPIX*ENCD;
    float s0 = 0.f, s1 = 0.f;
    for (int p = 0; p < NPIX; p++) {
        float v0 = Ein[p*ENCD + tid];
        float v1 = Ein[p*ENCD + tid + 256];
        Eo[p*ENCD + tid]       = v0;
        Eo[p*ENCD + tid + 256] = v1;
        s0 += v0; s1 += v1;
    }
    d_mean[b*ENCD + tid]       = s0 * (1.0f/NPIX);
    d_mean[b*ENCD + tid + 256] = s1 * (1.0f/NPIX);
}

// ---------------- small GEMM for h0/c0: C = A @ W^T + bias -------------------
__global__ __launch_bounds__(256) void gemm64_kernel(int sel,
        const float* __restrict__ Wmat, const float* __restrict__ bias,
        int K, int N) {
    const float* Amat = d_mean;
    float*       Cmat = (sel == 1) ? d_hbuf : d_c;
    __shared__ float sA[32][64];
    __shared__ float sW[32][64];
    int tid = threadIdx.x;
    int tx = tid & 15, ty = tid >> 4;
    int m0 = blockIdx.y * 64;
    int n0 = blockIdx.x * 64;
    float acc[4][4] = {};
    for (int k0 = 0; k0 < K; k0 += 32) {
        #pragma unroll
        for (int u = 0; u < 2; u++) {
            int f4i = tid + u*256;
            int m  = f4i >> 3;
            int kk = (f4i & 7) << 2;
            float4 a = *(const float4*)&Amat[(size_t)(m0+m)*K + k0 + kk];
            sA[kk][m] = a.x; sA[kk+1][m] = a.y; sA[kk+2][m] = a.z; sA[kk+3][m] = a.w;
            float4 w = *(const float4*)&Wmat[(size_t)(n0+m)*K + k0 + kk];
            sW[kk][m] = w.x; sW[kk+1][m] = w.y; sW[kk+2][m] = w.z; sW[kk+3][m] = w.w;
        }
        __syncthreads();
        #pragma unroll
        for (int k = 0; k < 32; k++) {
            float4 a = *(const float4*)&sA[k][ty*4];
            float4 w = *(const float4*)&sW[k][tx*4];
            float av[4] = {a.x, a.y, a.z, a.w};
            float wv[4] = {w.x, w.y, w.z, w.w};
            #pragma unroll
            for (int i = 0; i < 4; i++)
                #pragma unroll
                for (int j = 0; j < 4; j++)
                    acc[i][j] += av[i] * wv[j];
        }
        __syncthreads();
    }
    #pragma unroll
    for (int i = 0; i < 4; i++) {
        int m = m0 + ty*4 + i;
        #pragma unroll
        for (int j = 0; j < 4; j++) {
            int n = n0 + tx*4 + j;
            Cmat[(size_t)m*N + n] = acc[i][j] + bias[n];
        }
    }
}

// ---------------- ea = enc_s @ W_enc^T + b via bf16 3-term split mma ----------
__global__ void __launch_bounds__(256, 2) ea_mma_kernel(
        const float* __restrict__ Wenc, const float* __restrict__ bias) {
    extern __shared__ __align__(16) uint32_t sm[];
    uint32_t* Asm = sm;                  // [64][36]
    uint32_t* Wsm = sm + 64*36;          // [256][36]

    int m0 = blockIdx.y * 64;
    int n0 = blockIdx.x * 256;
    int tid = threadIdx.x;
    int lane = tid & 31, wp = tid >> 5;
    int g = lane >> 2, tig = lane & 3;

    float acc[4][4][4];
    #pragma unroll
    for (int a = 0; a < 4; a++)
        #pragma unroll
        for (int b2 = 0; b2 < 4; b2++)
            #pragma unroll
            for (int c2 = 0; c2 < 4; c2++) acc[a][b2][c2] = 0.f;

    for (int kt = 0; kt < 16; kt++) {
        {
            int row = tid >> 2, c = tid & 3;
            const float* src = d_enc_s + (size_t)(m0+row)*512 + kt*32 + c*8;
            float4 v0 = *(const float4*)src;
            float4 v1 = *(const float4*)(src + 4);
            uint4 h, l;
            bfsplit2(v0.x, v0.y, h.x, l.x);
            bfsplit2(v0.z, v0.w, h.y, l.y);
            bfsplit2(v1.x, v1.y, h.z, l.z);
            bfsplit2(v1.z, v1.w, h.w, l.w);
            *(uint4*)&Asm[row*36 + c*4]      = h;
            *(uint4*)&Asm[row*36 + 16 + c*4] = l;
        }
        #pragma unroll
        for (int u = 0; u < 4; u++) {
            int cid = tid + u*256;
            int row = cid >> 2, c = cid & 3;
            const float* src = Wenc + (size_t)(n0+row)*512 + kt*32 + c*8;
            float4 v0 = *(const float4*)src;
            float4 v1 = *(const float4*)(src + 4);
            uint4 h, l;
            bfsplit2(v0.x, v0.y, h.x, l.x);
            bfsplit2(v0.z, v0.w, h.y, l.y);
            bfsplit2(v1.x, v1.y, h.z, l.z);
            bfsplit2(v1.z, v1.w, h.w, l.w);
            *(uint4*)&Wsm[row*36 + c*4]      = h;
            *(uint4*)&Wsm[row*36 + 16 + c*4] = l;
        }
        __syncthreads();
        #pragma unroll
        for (int ks = 0; ks < 2; ks++) {
            int ko = ks*8 + tig;
            uint32_t ah[4][4], al[4][4];
            #pragma unroll
            for (int mf = 0; mf < 4; mf++) {
                int r0 = (mf*16 + g)*36, r1 = (mf*16 + g + 8)*36;
                ah[mf][0] = Asm[r0 + ko];      ah[mf][1] = Asm[r1 + ko];
                ah[mf][2] = Asm[r0 + ko + 4];  ah[mf][3] = Asm[r1 + ko + 4];
                al[mf][0] = Asm[r0 + 16 + ko];     al[mf][1] = Asm[r1 + 16 + ko];
                al[mf][2] = Asm[r0 + 16 + ko + 4]; al[mf][3] = Asm[r1 + 16 + ko + 4];
            }
            #pragma unroll
            for (int nf = 0; nf < 4; nf++) {
                int rw = (wp*32 + nf*8 + g)*36 + ko;
                uint32_t bh0 = Wsm[rw], bh1 = Wsm[rw + 4];
                uint32_t bl0 = Wsm[rw + 16], bl1 = Wsm[rw + 20];
                #pragma unroll
                for (int mf = 0; mf < 4; mf++) {
                    mma_bf16(acc[mf][nf], ah[mf][0], ah[mf][1], ah[mf][2], ah[mf][3], bh0, bh1);
                    mma_bf16(acc[mf][nf], al[mf][0], al[mf][1], al[mf][2], al[mf][3], bh0, bh1);
                    mma_bf16(acc[mf][nf], ah[mf][0], ah[mf][1], ah[mf][2], ah[mf][3], bl0, bl1);
                }
            }
        }
        __syncthreads();
    }

    #pragma unroll
    for (int nf = 0; nf < 4; nf++) {
        int n = n0 + wp*32 + nf*8 + 2*tig;
        float2 bb = *(const float2*)&bias[n];
        #pragma unroll
        for (int mf = 0; mf < 4; mf++) {
            int m1 = m0 + mf*16 + g;
            float2 o1; o1.x = acc[mf][nf][0] + bb.x; o1.y = acc[mf][nf][1] + bb.y;
            *(float2*)&d_ea[(size_t)m1*512 + n] = o1;
            int m2 = m1 + 8;
            float2 o2; o2.x = acc[mf][nf][2] + bb.x; o2.y = acc[mf][nf][3] + bb.y;
            *(float2*)&d_ea[(size_t)m2*512 + n] = o2;
        }
    }
}

// ---------------- standalone dagate (step-0 prologue, SIMT) -------------------
__global__ __launch_bounds__(256) void dagate_kernel(
        const float* __restrict__ Wd, const float* __restrict__ bd,
        const float* __restrict__ Wg, const float* __restrict__ bg) {
    __shared__ float sA[32][64];
    __shared__ float sW[32][64];
    const float* hsrc = d_hbuf;
    int tid = threadIdx.x;
    int tx = tid & 15, ty = tid >> 4;
    int n0 = blockIdx.x * 64;
    const float* Wmat = (n0 < 512) ? (Wd + (size_t)n0*512) : (Wg + (size_t)(n0-512)*512);
    float acc[4][4] = {};
    for (int k0 = 0; k0 < 512; k0 += 32) {
        #pragma unroll
        for (int u = 0; u < 2; u++) {
            int f4i = tid + u*256;
            int m  = f4i >> 3;
            int kk = (f4i & 7) << 2;
            float4 a = *(const float4*)&hsrc[(size_t)m*512 + k0 + kk];
            sA[kk][m] = a.x; sA[kk+1][m] = a.y; sA[kk+2][m] = a.z; sA[kk+3][m] = a.w;
            float4 w = *(const float4*)&Wmat[(size_t)m*512 + k0 + kk];
            sW[kk][m] = w.x; sW[kk+1][m] = w.y; sW[kk+2][m] = w.z; sW[kk+3][m] = w.w;
        }
        __syncthreads();
        #pragma unroll
        for (int k = 0; k < 32; k++) {
            float4 a = *(const float4*)&sA[k][ty*4];
            float4 w = *(const float4*)&sW[k][tx*4];
            float av[4] = {a.x, a.y, a.z, a.w};
            float wv[4] = {w.x, w.y, w.z, w.w};
            #pragma unroll
            for (int i = 0; i < 4; i++)
                #pragma unroll
                for (int j = 0; j < 4; j++)
                    acc[i][j] += av[i] * wv[j];
        }
        __syncthreads();
    }
    #pragma unroll
    for (int i = 0; i < 4; i++) {
        int m = ty*4 + i;
        #pragma unroll
        for (int j = 0; j < 4; j++) {
            int n = n0 + tx*4 + j;
            if (n < 512) d_da[m*512 + n] = acc[i][j] + bd[n];
            else         d_gate[m*512 + (n-512)] = sigmoidf_(acc[i][j] + bg[n-512]);
        }
    }
}

// ---------------- preds (NTILE=128): issue + body ------------------------------
__device__ __forceinline__ void preds_issue(uint32_t* Asm, uint32_t* Wsm,
        int stage, int kt, int n0, int tid, const uint4* hph, const uint4* hpl) {
    uint32_t* As = Asm + stage*(64*36);
    uint32_t* Ws = Wsm + stage*(NTILE*36);
    #pragma unroll
    for (int u = 0; u < 2; u++) {
        int cid = tid + u*256;
        int row = cid >> 3, c = cid & 7;
        const uint4* src = ((c < 4) ? hph : hpl) + row*64 + kt*4 + (c & 3);
        uint32_t* dst = As + row*36 + ((c < 4) ? c*4 : 16 + (c - 4)*4);
        __pipeline_memcpy_async(dst, src, 16);
    }
    const uint4* wh = (const uint4*)d_wfh16;
    const uint4* wl = (const uint4*)d_wfl16;
    #pragma unroll
    for (int u = 0; u < 4; u++) {
        int cid = tid + u*256;
        int row = cid >> 3, c = cid & 7;
        const uint4* src = ((c < 4) ? wh : wl) + (size_t)(n0 + row)*64 + kt*4 + (c & 3);
        uint32_t* dst = Ws + row*36 + ((c < 4) ? c*4 : 16 + (c - 4)*4);
        cp_async16_ef(dst, src);       // W_fc: single-use stream, evict_first
    }
    __pipeline_commit();
}

__device__ void preds_body(int j, uint32_t* sm, int tid,
                           const float* __restrict__ bfc,
                           float* __restrict__ out_pred, int n0) {
    int nact = d_nact[j];
    int mfmax = (nact + 15) >> 4;
    int hb = (j + 1) & 1;
    uint32_t* Asm = sm;
    uint32_t* Wsm = sm + 2*64*36;

    int lane = tid & 31, wp = tid >> 5;
    int g = lane >> 2, tig = lane & 3;
    const uint4* hph = (const uint4*)d_hph[hb];
    const uint4* hpl = (const uint4*)d_hpl[hb];

    float acc[4][2][4];
    #pragma unroll
    for (int a = 0; a < 4; a++)
        #pragma unroll
        for (int b2 = 0; b2 < 2; b2++)
            #pragma unroll
            for (int c2 = 0; c2 < 4; c2++) acc[a][b2][c2] = 0.f;

    preds_issue(Asm, Wsm, 0, 0, n0, tid, hph, hpl);
    for (int kt = 0; kt < 16; kt++) {
        int stage = kt & 1;
        if (kt < 15) {
            preds_issue(Asm, Wsm, stage ^ 1, kt + 1, n0, tid, hph, hpl);
            __pipeline_wait_prior(1);
        } else {
            __pipeline_wait_prior(0);
        }
        __syncthreads();
        const uint32_t* Ahs = Asm + stage*(64*36);
        const uint32_t* Whs = Wsm + stage*(NTILE*36);
        #pragma unroll
        for (int ks = 0; ks < 2; ks++) {
            int ko = ks*8 + tig;
            uint32_t ah[4][4], al[4][4];
            #pragma unroll
            for (int mf = 0; mf < 4; mf++) {
                if (mf >= mfmax) continue;
                int r0 = (mf*16 + g)*36, r1 = (mf*16 + g + 8)*36;
                ah[mf][0] = Ahs[r0 + ko];      ah[mf][1] = Ahs[r1 + ko];
                ah[mf][2] = Ahs[r0 + ko + 4];  ah[mf][3] = Ahs[r1 + ko + 4];
                al[mf][0] = Ahs[r0 + 16 + ko];     al[mf][1] = Ahs[r1 + 16 + ko];
                al[mf][2] = Ahs[r0 + 16 + ko + 4]; al[mf][3] = Ahs[r1 + 16 + ko + 4];
            }
            #pragma unroll
            for (int nf = 0; nf < 2; nf++) {
                int rw = (wp*16 + nf*8 + g)*36 + ko;
                uint32_t bh0 = Whs[rw], bh1 = Whs[rw + 4];
                uint32_t bl0 = Whs[rw + 16], bl1 = Whs[rw + 20];
                #pragma unroll
                for (int mf = 0; mf < 4; mf++) {
                    if (mf >= mfmax) continue;
                    mma_bf16(acc[mf][nf], ah[mf][0], ah[mf][1], ah[mf][2], ah[mf][3], bh0, bh1);
                    mma_bf16(acc[mf][nf], al[mf][0], al[mf][1], al[mf][2], al[mf][3], bh0, bh1);
                    mma_bf16(acc[mf][nf], ah[mf][0], ah[mf][1], ah[mf][2], ah[mf][3], bl0, bl1);
                }
            }
        }
        __syncthreads();
    }

    size_t tbase = (size_t)j * VV;
    #pragma unroll
    for (int nf = 0; nf < 2; nf++) {
        int n = n0 + wp*16 + nf*8 + 2*tig;
        float2 bb = *(const float2*)&bfc[n];
        #pragma unroll
        for (int mf = 0; mf < 4; mf++) {
            int m1 = mf*16 + g;
            float o1x = (m1 < nact) ? acc[mf][nf][0] + bb.x : 0.f;
            float o1y = (m1 < nact) ? acc[mf][nf][1] + bb.y : 0.f;
            st_cs_f2(&out_pred[(size_t)m1*((size_t)TT*VV) + tbase + n], o1x, o1y);
            int m2 = m1 + 8;
            float o2x = (m2 < nact) ? acc[mf][nf][2] + bb.x : 0.f;
            float o2y = (m2 < nact) ? acc[mf][nf][3] + bb.y : 0.f;
            st_cs_f2(&out_pred[(size_t)m2*((size_t)TT*VV) + tbase + n], o2x, o2y);
        }
    }
}

// ---------------- phase-B issue: A from packed (emb|ctx|h), W from wihh -------
__device__ __forceinline__ void lstm_issue(uint32_t* Asm, uint32_t* Wsm,
        int stage, int c0, int n0, int tid, int t, int hb) {
    uint32_t* As = Asm + stage*(64*36);
    uint32_t* Ws = Wsm + stage*(256*36);
    const uint4* ah4; const uint4* al4; int off4;
    if (c0 < 512) {
        ah4 = (const uint4*)d_embp_h + (size_t)t*BSZ*64;
        al4 = (const uint4*)d_embp_l + (size_t)t*BSZ*64;
        off4 = c0 >> 3;
    } else if (c0 < 1024) {
        ah4 = (const uint4*)d_ctxp_h;
        al4 = (const uint4*)d_ctxp_l;
        off4 = (c0 - 512) >> 3;
    } else {
        ah4 = (const uint4*)d_hph[hb];
        al4 = (const uint4*)d_hpl[hb];
        off4 = (c0 - 1024) >> 3;
    }
    #pragma unroll
    for (int u = 0; u < 2; u++) {
        int cid = tid + u*256;
        int row = cid >> 3, c = cid & 7;
        const uint4* src = ((c < 4) ? ah4 : al4) + (size_t)row*64 + off4 + (c & 3);
        uint32_t* dst = As + row*36 + ((c < 4) ? c*4 : 16 + (c - 4)*4);
        __pipeline_memcpy_async(dst, src, 16);
    }
    const uint4* wh = (const uint4*)d_wihh_h;
    const uint4* wl = (const uint4*)d_wihh_l;
    int woff4 = c0 >> 3;
    #pragma unroll
    for (int u = 0; u < 8; u++) {
        int cid = tid + u*256;
        int row = cid >> 3, c = cid & 7;
        const uint4* src = ((c < 4) ? wh : wl) + (size_t)(n0 + row)*192 + woff4 + (c & 3);
        uint32_t* dst = Ws + row*36 + ((c < 4) ? c*4 : 16 + (c - 4)*4);
        __pipeline_memcpy_async(dst, src, 16);
    }
    __pipeline_commit();
}

// ---------------- phase-D issue (64 blocks, N=16): A full, W 16 rows ----------
__device__ __forceinline__ void dg_issue16(uint32_t* Asm, uint32_t* Wsm,
        int stage, int kt, int n0, int tid, int hbw) {
    uint32_t* As = Asm + stage*(64*68);
    uint32_t* Ws = Wsm + stage*(16*68);
    const uint4* ah4 = (const uint4*)d_hph[hbw];
    const uint4* al4 = (const uint4*)d_hpl[hbw];
    #pragma unroll
    for (int u = 0; u < 4; u++) {
        int cid = tid + u*256;          // 0..1023
        int row = cid >> 4, c = cid & 15;
        const uint4* src = ((c < 8) ? ah4 : al4) + (size_t)row*64 + kt*8 + (c & 7);
        uint32_t* dst = As + row*68 + ((c < 8) ? c*4 : 32 + (c - 8)*4);
        __pipeline_memcpy_async(dst, src, 16);
    }
    {   // W: 16 rows x 16 chunks = 256, one per thread
        int row = tid >> 4, c = tid & 15;
        const uint4* src = (((c < 8) ? (const uint4*)d_wdg_h : (const uint4*)d_wdg_l))
                           + (size_t)(n0 + row)*64 + kt*8 + (c & 7);
        uint32_t* dst = Ws + row*68 + ((c < 8) ? c*4 : 32 + (c - 8)*4);
        __pipeline_memcpy_async(dst, src, 16);
    }
    __pipeline_commit();
}

// ============ FUSED: recurrence(t) on blocks 0..63 || preds(t-1) on 64+ =======
__global__ void __launch_bounds__(256, 2) fused_kernel(int t,
        const float* __restrict__ wf, const float* __restrict__ bf_scalar,
        const float* __restrict__ bih, const float* __restrict__ bhh,
        const float* __restrict__ bd, const float* __restrict__ bg,
        const float* __restrict__ bfc,
        float* __restrict__ out_alphas, float* __restrict__ out_pred) {
    extern __shared__ __align__(16) uint32_t smem_u[];
    int bid = blockIdx.x;
    int tid = threadIdx.x;

    if (bid >= RBLK) {                     // ---- preds for step t-1 ----
        if (t >= 1) preds_body(t - 1, smem_u, tid, bfc, out_pred, (bid - RBLK) * NTILE);
        return;
    }
    if (t >= TT) return;

    int hb  = t & 1;
    int hbw = (t + 1) & 1;

    // ---------------- phase A: attention (blocks 0..63) -----------------------
    if (t < d_declen[bid]) {
        int b = bid;
        int lane = tid & 31, warp = tid >> 5;
        float4* s_da = (float4*)smem_u;
        float4* s_wf = s_da + 128;
        float*  sc   = (float*)(s_wf + 128);
        float*  red  = sc + 200;

        if (tid < 128) {
            s_da[tid] = ((const float4*)d_da)[b*128 + tid];
            s_wf[tid] = ((const float4*)wf)[tid];
        }
        __syncthreads();

        const float4* ea4 = ((const float4*)d_ea) + (size_t)b*NPIX*128;
        float bfull = bf_scalar[0];
        for (int p0 = warp*2; p0 < NPIX; p0 += 16) {
            int p1 = p0 + 1;
            float s0 = 0.f, s1 = 0.f;
            #pragma unroll
            for (int j = 0; j < 4; j++) {
                int k4 = lane + j*32;
                float4 e0 = ea4[p0*128 + k4];
                float4 e1 = ea4[p1*128 + k4];
                float4 da = s_da[k4];
                float4 w  = s_wf[k4];
                s0 += fmaxf(e0.x + da.x, 0.f) * w.x;
                s0 += fmaxf(e0.y + da.y, 0.f) * w.y;
                s0 += fmaxf(e0.z + da.z, 0.f) * w.z;
                s0 += fmaxf(e0.w + da.w, 0.f) * w.w;
                s1 += fmaxf(e1.x + da.x, 0.f) * w.x;
                s1 += fmaxf(e1.y + da.y, 0.f) * w.y;
                s1 += fmaxf(e1.z + da.z, 0.f) * w.z;
                s1 += fmaxf(e1.w + da.w, 0.f) * w.w;
            }
            s0 = warp_sum(s0);
            s1 = warp_sum(s1);
            if (lane == 0) { sc[p0] = s0 + bfull; sc[p1] = s1 + bfull; }
        }
        __syncthreads();

        float v = (tid < NPIX) ? sc[tid] : -1e30f;
        float wm = warp_max(v);
        if (lane == 0) red[warp] = wm;
        __syncthreads();
        if (tid == 0) {
            float mm = red[0];
            #pragma unroll
            for (int i = 1; i < 8; i++) mm = fmaxf(mm, red[i]);
            red[16] = mm;
        }
        __syncthreads();
        float gmax = red[16];
        float e = (tid < NPIX) ? __expf(v - gmax) : 0.f;
        float ws = warp_sum(e);
        if (lane == 0) red[8 + warp] = ws;
        __syncthreads();
        if (tid == 0) {
            float ss = 0.f;
            #pragma unroll
            for (int i = 0; i < 8; i++) ss += red[8 + i];
            red[17] = ss;
        }
        __syncthreads();
        float alpha = e / red[17];
        __syncthreads();
        if (tid < NPIX) {
            sc[tid] = alpha;
            out_alphas[(size_t)b*TT*NPIX + (size_t)t*NPIX + tid] = alpha;
        }
        __syncthreads();

        const float2* encb2 = (const float2*)(d_enc_s + (size_t)b*NPIX*512);
        float sx[16], sy[16];
        #pragma unroll
        for (int u = 0; u < 16; u++) { sx[u] = 0.f; sy[u] = 0.f; }
        #pragma unroll 2
        for (int p0 = 0; p0 < 192; p0 += 16) {
            #pragma unroll
            for (int u = 0; u < 16; u++) {
                float2 vv = encb2[(p0+u)*256 + tid];
                float al = sc[p0+u];
                sx[u] += al * vv.x;
                sy[u] += al * vv.y;
            }
        }
        #pragma unroll
        for (int u = 0; u < 4; u++) {
            float2 vv = encb2[(192+u)*256 + tid];
            float al = sc[192+u];
            sx[u] += al * vv.x;
            sy[u] += al * vv.y;
        }
        float X = 0.f, Y = 0.f;
        #pragma unroll
        for (int u = 0; u < 16; u++) { X += sx[u]; Y += sy[u]; }
        float2 g2 = ((const float2*)d_gate)[b*256 + tid];
        float cx = X * g2.x, cy = Y * g2.y;
        uint32_t chi, clo; bfsplit2(cx, cy, chi, clo);
        d_ctxp_h[b*256 + tid] = chi;
        d_ctxp_l[b*256 + tid] = clo;
    }
    rec_bar(tid);

    // ---------------- phase B: LSTM gate GEMM via mma (64 blocks) -------------
    {
        uint32_t* Asm = smem_u;
        uint32_t* Wsm = smem_u + 2*64*36;
        int n0 = (bid & 7) * 256;
        int ksplit = bid >> 3;
        int kbase = ksplit * 192;
        int lane = tid & 31, wp = tid >> 5;
        int g = lane >> 2, tig = lane & 3;

        float acc[4][4][4];
        #pragma unroll
        for (int a = 0; a < 4; a++)
            #pragma unroll
            for (int b2 = 0; b2 < 4; b2++)
                #pragma unroll
                for (int c2 = 0; c2 < 4; c2++) acc[a][b2][c2] = 0.f;

        lstm_issue(Asm, Wsm, 0, kbase, n0, tid, t, hb);
        for (int kt = 0; kt < 6; kt++) {
            int stage = kt & 1;
            if (kt < 5) {
                lstm_issue(Asm, Wsm, stage ^ 1, kbase + (kt+1)*32, n0, tid, t, hb);
                __pipeline_wait_prior(1);
            } else {
                __pipeline_wait_prior(0);
            }
            __syncthreads();
            const uint32_t* Ahs = Asm + stage*(64*36);
            const uint32_t* Whs = Wsm + stage*(256*36);
            #pragma unroll
            for (int ks = 0; ks < 2; ks++) {
                int ko = ks*8 + tig;
                uint32_t ah[4][4], al[4][4];
                #pragma unroll
                for (int mf = 0; mf < 4; mf++) {
                    int r0 = (mf*16 + g)*36, r1 = (mf*16 + g + 8)*36;
                    ah[mf][0] = Ahs[r0 + ko];      ah[mf][1] = Ahs[r1 + ko];
                    ah[mf][2] = Ahs[r0 + ko + 4];  ah[mf][3] = Ahs[r1 + ko + 4];
                    al[mf][0] = Ahs[r0 + 16 + ko];     al[mf][1] = Ahs[r1 + 16 + ko];
                    al[mf][2] = Ahs[r0 + 16 + ko + 4]; al[mf][3] = Ahs[r1 + 16 + ko + 4];
                }
                #pragma unroll
                for (int nf = 0; nf < 4; nf++) {
                    int rw = (wp*32 + nf*8 + g)*36 + ko;
                    uint32_t bh0 = Whs[rw], bh1 = Whs[rw + 4];
                    uint32_t bl0 = Whs[rw + 16], bl1 = Whs[rw + 20];
                    #pragma unroll
                    for (int mf = 0; mf < 4; mf++) {
                        mma_bf16(acc[mf][nf], ah[mf][0], ah[mf][1], ah[mf][2], ah[mf][3], bh0, bh1);
                        mma_bf16(acc[mf][nf], al[mf][0], al[mf][1], al[mf][2], al[mf][3], bh0, bh1);
                        mma_bf16(acc[mf][nf], ah[mf][0], ah[mf][1], ah[mf][2], ah[mf][3], bl0, bl1);
                    }
                }
            }
            __syncthreads();
        }

        float* gp = d_gates_p + (size_t)ksplit * (BSZ*2048);
        #pragma unroll
        for (int nf = 0; nf < 4; nf++) {
            int n = n0 + wp*32 + nf*8 + 2*tig;
            #pragma unroll
            for (int mf = 0; mf < 4; mf++) {
                int m1 = mf*16 + g;
                float2 o1; o1.x = acc[mf][nf][0]; o1.y = acc[mf][nf][1];
                *(float2*)&gp[m1*2048 + n] = o1;
                int m2 = m1 + 8;
                float2 o2; o2.x = acc[mf][nf][2]; o2.y = acc[mf][nf][3];
                *(float2*)&gp[m2*2048 + n] = o2;
            }
        }
    }
    rec_bar(tid);

    // ---------------- phase C: LSTM apply + bf16 pack (ALL 64 blocks) ---------
    {
        int gid = bid*256 + tid;        // 0..16383 pairs
        int idx0 = gid*2;
        int b = idx0 >> 9;
        int j = idx0 & 511;             // even
        float2 acc[4];
        #pragma unroll
        for (int q = 0; q < 4; q++) { acc[q].x = 0.f; acc[q].y = 0.f; }
        #pragma unroll
        for (int s = 0; s < NSPLIT; s++) {
            const float* gp = d_gates_p + (size_t)s*(BSZ*2048) + b*2048;
            #pragma unroll
            for (int q = 0; q < 4; q++) {
                float2 v = *(const float2*)&gp[q*512 + j];
                acc[q].x += v.x; acc[q].y += v.y;
            }
        }
        #pragma unroll
        for (int q = 0; q < 4; q++) {
            float2 bi = *(const float2*)&bih[q*512 + j];
            float2 bh = *(const float2*)&bhh[q*512 + j];
            acc[q].x += bi.x + bh.x;
            acc[q].y += bi.y + bh.y;
        }
        float2 cold = *(const float2*)&d_c[idx0];
        float hx, hy;
        {
            float ig = sigmoidf_(acc[0].x), fg = sigmoidf_(acc[1].x);
            float gg = tanhf(acc[2].x),     og = sigmoidf_(acc[3].x);
            float c = fg*cold.x + ig*gg; hx = og*tanhf(c); cold.x = c;
        }
        {
            float ig = sigmoidf_(acc[0].y), fg = sigmoidf_(acc[1].y);
            float gg = tanhf(acc[2].y),     og = sigmoidf_(acc[3].y);
            float c = fg*cold.y + ig*gg; hy = og*tanhf(c); cold.y = c;
        }
        *(float2*)&d_c[idx0] = cold;
        uint32_t ph, pl; bfsplit2(hx, hy, ph, pl);
        d_hph[hbw][gid] = ph;
        d_hpl[hbw][gid] = pl;
    }
    rec_bar(tid);

    // ---------------- phase D: dagate via mma (ALL 64 blocks, N=16) -----------
    {
        uint32_t* Asm = smem_u;              // [2][64*68]
        uint32_t* Wsm = smem_u + 2*64*68;    // [2][16*68]
        int n0 = bid * 16;
        int lane = tid & 31, wp = tid >> 5;
        int g = lane >> 2, tig = lane & 3;
        int mf = wp >> 1, nf = wp & 1;       // one fragment per warp

        float acc[4];
        #pragma unroll
        for (int c2 = 0; c2 < 4; c2++) acc[c2] = 0.f;

        dg_issue16(Asm, Wsm, 0, 0, n0, tid, hbw);
        for (int kt = 0; kt < 8; kt++) {
            int stage = kt & 1;
            if (kt < 7) {
                dg_issue16(Asm, Wsm, stage ^ 1, kt + 1, n0, tid, hbw);
                __pipeline_wait_prior(1);
            } else {
                __pipeline_wait_prior(0);
            }
            __syncthreads();
            const uint32_t* Ahs = Asm + stage*(64*68);
            const uint32_t* Whs = Wsm + stage*(16*68);
            #pragma unroll
            for (int ks = 0; ks < 4; ks++) {
                int ko = ks*8 + tig;
                int rw = (nf*8 + g)*68 + ko;
                uint32_t bh0 = Whs[rw], bh1 = Whs[rw + 4];
                uint32_t bl0 = Whs[rw + 32], bl1 = Whs[rw + 36];
                int r0 = (mf*16 + g)*68, r1 = (mf*16 + g + 8)*68;
                uint32_t a0 = Ahs[r0 + ko],      a1 = Ahs[r1 + ko];
                uint32_t a2 = Ahs[r0 + ko + 4],  a3 = Ahs[r1 + ko + 4];
                uint32_t l0 = Ahs[r0 + 32 + ko],     l1 = Ahs[r1 + 32 + ko];
                uint32_t l2 = Ahs[r0 + 32 + ko + 4], l3 = Ahs[r1 + 32 + ko + 4];
                mma_bf16(acc, a0, a1, a2, a3, bh0, bh1);
                mma_bf16(acc, l0, l1, l2, l3, bh0, bh1);
                mma_bf16(acc, a0, a1, a2, a3, bl0, bl1);
            }
            __syncthreads();
        }

        int n = n0 + nf*8 + 2*tig;
        int m1 = mf*16 + g, m2 = m1 + 8;
        if (n < 512) {
            float2 bb = *(const float2*)&bd[n];
            float2 o1; o1.x = acc[0] + bb.x; o1.y = acc[1] + bb.y;
            *(float2*)&d_da[m1*512 + n] = o1;
            float2 o2; o2.x = acc[2] + bb.x; o2.y = acc[3] + bb.y;
            *(float2*)&d_da[m2*512 + n] = o2;
        } else {
            int ng = n - 512;
            float2 bb = *(const float2*)&bg[ng];
            float2 o1; o1.x = sigmoidf_(acc[0] + bb.x); o1.y = sigmoidf_(acc[1] + bb.y);
            *(float2*)&d_gate[m1*512 + ng] = o1;
            float2 o2; o2.x = sigmoidf_(acc[2] + bb.x); o2.y = sigmoidf_(acc[3] + bb.y);
            *(float2*)&d_gate[m2*512 + ng] = o2;
        }
    }
}

// ---------------- launch ------------------------------------------------------
extern "C" void kernel_launch(void* const* d_in, const int* in_sizes, int n_in,
                              void* d_out, int out_size) {
    const float* encoder_out = (const float*)d_in[0];
    const int*   caps        = (const int*)  d_in[1];
    const int*   cap_len     = (const int*)  d_in[2];
    const float* W_enc_attn  = (const float*)d_in[3];
    const float* b_enc_attn  = (const float*)d_in[4];
    const float* W_dec_attn  = (const float*)d_in[5];
    const float* b_dec_attn  = (const float*)d_in[6];
    const float* w_full_attn = (const float*)d_in[7];
    const float* b_full_attn = (const float*)d_in[8];
    const float* emb_table   = (const float*)d_in[9];
    const float* W_ih        = (const float*)d_in[10];
    const float* W_hh        = (const float*)d_in[11];
    const float* b_ih        = (const float*)d_in[12];
    const float* b_hh        = (const float*)d_in[13];
    const float* W_init_h    = (const float*)d_in[14];
    const float* b_init_h    = (const float*)d_in[15];
    const float* W_init_c    = (const float*)d_in[16];
    const float* b_init_c    = (const float*)d_in[17];
    const float* W_f_beta    = (const float*)d_in[18];
    const float* b_f_beta    = (const float*)d_in[19];
    const float* W_fc        = (const float*)d_in[20];
    const float* b_fc        = (const float*)d_in[21];

    float* out = (float*)d_out;
    const size_t OFF_PRED   = 0;
    const size_t OFF_CAPS   = OFF_PRED + (size_t)BSZ*TT*VV;
    const size_t OFF_DECLEN = OFF_CAPS + (size_t)BSZ*ML;
    const size_t OFF_ALPHA  = OFF_DECLEN + BSZ;
    const size_t OFF_ORDER  = OFF_ALPHA + (size_t)BSZ*TT*NPIX;
    float* out_pred   = out + OFF_PRED;
    float* out_caps   = out + OFF_CAPS;
    float* out_declen = out + OFF_DECLEN;
    float* out_alphas = out + OFF_ALPHA;
    float* out_order  = out + OFF_ORDER;

    static cudaStream_t s2 = nullptr;
    static cudaEvent_t evRoot, evCvt;
    static bool inited = false;
    const int FUSED_SMEM = (2*64*36 + 2*256*36) * 4;   // 92160 B (>= D: 2*64*68*4+2*16*68*4)
    const int EA_SMEM = (64*36 + 256*36) * 4;          // 46080 B
    if (!inited) {
        cudaStreamCreateWithFlags(&s2, cudaStreamNonBlocking);
        cudaEventCreateWithFlags(&evRoot, cudaEventDisableTiming);
        cudaEventCreateWithFlags(&evCvt, cudaEventDisableTiming);
        cudaFuncSetAttribute(fused_kernel, cudaFuncAttributeMaxDynamicSharedMemorySize,
                             FUSED_SMEM);
        cudaFuncSetAttribute(ea_mma_kernel, cudaFuncAttributeMaxDynamicSharedMemorySize,
                             EA_SMEM);
        inited = true;
    }

    size_t tail = (size_t)out_size - OFF_CAPS;
    cudaMemsetAsync(out + OFF_CAPS, 0, tail * sizeof(float));

    // weight converts on s2, overlapped with main prologue on stream 0
    cudaEventRecord(evRoot, 0);
    cudaStreamWaitEvent(s2, evRoot, 0);
    convert_wfc_kernel<<<(VV*64)/256, 256, 0, s2>>>((const float4*)W_fc);
    convert_wihh_kernel<<<(2048*768)/256, 256, 0, s2>>>(W_ih, W_hh);
    convert_wdg_kernel<<<(1024*256)/256, 256, 0, s2>>>(W_dec_attn, W_f_beta);
    cudaEventRecord(evCvt, s2);

    sort_kernel<<<1, 64>>>(cap_len, caps, out_caps, out_declen, out_order);
    convert_emb_kernel<<<dim3(BSZ, ML), 256>>>(emb_table);
    reorder_mean_kernel<<<BSZ, 256>>>(encoder_out);
    ea_mma_kernel<<<dim3(2, 196), 256, EA_SMEM>>>(W_enc_attn, b_enc_attn);
    gemm64_kernel<<<dim3(8, 1), 256>>>(1, W_init_h, b_init_h, 512, 512);
    gemm64_kernel<<<dim3(8, 1), 256>>>(2, W_init_c, b_init_c, 512, 512);
    convert_h0_kernel<<<64, 256>>>();
    dagate_kernel<<<16, 256>>>(W_dec_attn, b_dec_attn, W_f_beta, b_f_beta);

    cudaStreamWaitEvent((cudaStream_t)0, evCvt, 0);

    for (int t = 0; t <= TT; t++) {
        fused_kernel<<<GRID, 256, FUSED_SMEM>>>(t, w_full_attn, b_full_attn,
                                                b_ih, b_hh, b_dec_attn, b_f_beta,
                                                b_fc, out_alphas, out_pred);
    }
}